// round 1
// baseline (speedup 1.0000x reference)
#include <cuda_runtime.h>
#include <math.h>

#define MAXN 50000
#define MAXE 800000

// ---- scratch (device globals; no allocation allowed) ----
__device__ float g_deg1[MAXN];
__device__ float g_deg2[MAXN];
__device__ float g_norm1[MAXE];
__device__ float g_norm2[MAXE];
__device__ float g_h1[(size_t)MAXN * 256];
__device__ float g_x1[(size_t)MAXN * 256];
__device__ float g_h2[(size_t)MAXN * 128];
__device__ float g_x2[(size_t)MAXN * 128];
__device__ float g_Adec[(size_t)MAXN * 128];
__device__ float g_Bdec[(size_t)MAXN * 128];

// ---- zeroing ----
__global__ void zero4_kernel(float4* p, int n4) {
    int i = blockIdx.x * blockDim.x + threadIdx.x;
    if (i < n4) p[i] = make_float4(0.f, 0.f, 0.f, 0.f);
}

// ---- degree accumulation (both convs in one pass) ----
__global__ void deg_kernel(const int* __restrict__ col1, const float* __restrict__ w,
                           const int* __restrict__ col2, int E) {
    int e = blockIdx.x * blockDim.x + threadIdx.x;
    if (e < E) {
        atomicAdd(&g_deg1[col1[e]], w[e]);
        atomicAdd(&g_deg2[col2[e]], 1.0f);
    }
}

__global__ void dinv_kernel(int N) {
    int i = blockIdx.x * blockDim.x + threadIdx.x;
    if (i < N) {
        float d1 = g_deg1[i];
        g_deg1[i] = d1 > 0.f ? 1.0f / sqrtf(d1) : 0.f;
        float d2 = g_deg2[i];
        g_deg2[i] = d2 > 0.f ? 1.0f / sqrtf(d2) : 0.f;
    }
}

__global__ void norm_kernel(const int* __restrict__ ei, const int* __restrict__ nei,
                            const float* __restrict__ w, int E) {
    int e = blockIdx.x * blockDim.x + threadIdx.x;
    if (e < E) {
        g_norm1[e] = g_deg1[ei[e]] * w[e] * g_deg1[ei[E + e]];
        g_norm2[e] = g_deg2[nei[e]] * g_deg2[nei[E + e]];
    }
}

// ---- tiled SGEMM with optional row gather on A ----
// C[M,Nc] = gather(A)[M,K] @ B[K,Nc].  BM=BN=64, BK=16, 256 threads, 4x4/thread.
__global__ void sgemm_kernel(const float* __restrict__ A, const float* __restrict__ B,
                             float* __restrict__ C, const int* __restrict__ idx,
                             int M, int K, int Nc) {
    __shared__ float As[16][68];   // padded: STS mostly conflict-free, rows 16B aligned
    __shared__ float Bs[16][64];
    int tid = threadIdx.x;
    int bx = blockIdx.x, by = blockIdx.y;
    int tx = tid & 15, ty = tid >> 4;
    float acc[4][4];
#pragma unroll
    for (int i = 0; i < 4; i++)
#pragma unroll
        for (int j = 0; j < 4; j++) acc[i][j] = 0.f;

    int lrow = tid >> 2;
    int lk4 = (tid & 3) << 2;
    int grow = by * 64 + lrow;
    long arow = -1;
    if (grow < M) arow = idx ? (long)idx[grow] : (long)grow;
    int bk = tid >> 4;
    int bn4 = (tid & 15) << 2;
    int gcol = bx * 64 + bn4;   // Nc is a multiple of 64 here

    for (int kt = 0; kt < K; kt += 16) {
        float4 av = make_float4(0.f, 0.f, 0.f, 0.f);
        if (arow >= 0) av = *(const float4*)(A + arow * (size_t)K + kt + lk4);
        As[lk4 + 0][lrow] = av.x;
        As[lk4 + 1][lrow] = av.y;
        As[lk4 + 2][lrow] = av.z;
        As[lk4 + 3][lrow] = av.w;
        *(float4*)&Bs[bk][bn4] = *(const float4*)(B + (size_t)(kt + bk) * Nc + gcol);
        __syncthreads();
#pragma unroll
        for (int k = 0; k < 16; k++) {
            float4 a = *(const float4*)&As[k][ty << 2];
            float4 b = *(const float4*)&Bs[k][tx << 2];
            float ar[4] = {a.x, a.y, a.z, a.w};
            float br[4] = {b.x, b.y, b.z, b.w};
#pragma unroll
            for (int i = 0; i < 4; i++)
#pragma unroll
                for (int j = 0; j < 4; j++) acc[i][j] = fmaf(ar[i], br[j], acc[i][j]);
        }
        __syncthreads();
    }
    int crow = by * 64 + (ty << 2);
    int ccol = bx * 64 + (tx << 2);
#pragma unroll
    for (int i = 0; i < 4; i++) {
        if (crow + i < M) {
            float4 v = make_float4(acc[i][0], acc[i][1], acc[i][2], acc[i][3]);
            *(float4*)(C + (size_t)(crow + i) * Nc + ccol) = v;
        }
    }
}

// ---- vectorized f32x4 reduction to global (no return) ----
__device__ __forceinline__ void red_add_v4(float* p, float x, float y, float z, float w) {
    asm volatile("red.global.add.v4.f32 [%0], {%1,%2,%3,%4};"
                 :: "l"(p), "f"(x), "f"(y), "f"(z), "f"(w) : "memory");
}

// ---- normalized message scatter: out[col] += h[row] * norm ----
template <int C>
__global__ void scatter_kernel(const float* __restrict__ h, float* __restrict__ out,
                               const int* __restrict__ idx2,  // rows [0,E), cols [E,2E)
                               const float* __restrict__ nrm, int E) {
    const int TPE = C / 4;
    int gid = blockIdx.x * blockDim.x + threadIdx.x;
    int e = gid / TPE;
    int q = gid - e * TPE;
    if (e >= E) return;
    float n = nrm[e];
    if (n == 0.f) return;
    int r = idx2[e];
    int c = idx2[E + e];
    float4 v = *(const float4*)(h + (size_t)r * C + q * 4);
    float* o = out + (size_t)c * C + q * 4;
    red_add_v4(o, v.x * n, v.y * n, v.z * n, v.w * n);
}

// ---- x = elu(x + b) ----
__global__ void bias_elu_kernel(float* __restrict__ x, const float* __restrict__ b,
                                int total, int C) {
    int i = blockIdx.x * blockDim.x + threadIdx.x;
    if (i < total) {
        float v = x[i] + b[i % C];
        x[i] = v > 0.f ? v : (expf(v) - 1.0f);
    }
}

// ---- edge decoder: out[e] = relu(relu(A[src]+B[dst]+b1) @ W2 + b2) @ W3 + b3 ----
// 64 edges/block, 256 threads. t (64x132) + full W2 (128x128) in smem.
#define DEC_TS 132
__global__ void decoder_kernel(const float* __restrict__ Ad, const float* __restrict__ Bd,
                               const int* __restrict__ ei,  // src [0,E), dst [E,2E)
                               const float* __restrict__ b1, const float* __restrict__ W2,
                               const float* __restrict__ b2, const float* __restrict__ W3,
                               const float* __restrict__ b3, float* __restrict__ out, int E) {
    extern __shared__ float smem[];
    float* tS = smem;                  // 64 x DEC_TS
    float* W2s = smem + 64 * DEC_TS;   // 128 x 128
    int tid = threadIdx.x;
    int eBase = blockIdx.x * 64;

    // stage W2 (16384 floats, 64/thread)
    {
        const float4* s4 = (const float4*)W2;
        float4* d4 = (float4*)W2s;
#pragma unroll
        for (int q = 0; q < 16; q++) d4[tid + q * 256] = s4[tid + q * 256];
    }
    // phase 1: t = relu(A[src] + B[dst] + b1), 4 threads per edge
    {
        int eloc = tid >> 2;
        int seg = tid & 3;
        int e = eBase + eloc;
        if (e < E) {
            int s = ei[e], d = ei[E + e];
            const float* ap = Ad + (size_t)s * 128;
            const float* bp = Bd + (size_t)d * 128;
#pragma unroll
            for (int q = 0; q < 8; q++) {
                int k = seg * 32 + q * 4;
                float4 a = *(const float4*)(ap + k);
                float4 b = *(const float4*)(bp + k);
                float4 bb = *(const float4*)(b1 + k);
                float4 t;
                t.x = fmaxf(a.x + b.x + bb.x, 0.f);
                t.y = fmaxf(a.y + b.y + bb.y, 0.f);
                t.z = fmaxf(a.z + b.z + bb.z, 0.f);
                t.w = fmaxf(a.w + b.w + bb.w, 0.f);
                *(float4*)&tS[eloc * DEC_TS + k] = t;
            }
        } else {
#pragma unroll
            for (int q = 0; q < 8; q++) {
                int k = seg * 32 + q * 4;
                *(float4*)&tS[eloc * DEC_TS + k] = make_float4(0.f, 0.f, 0.f, 0.f);
            }
        }
    }
    __syncthreads();

    // phase 2: u = t @ W2; fold relu(u+b2)·W3 on the fly. 4 edges x 8 cols / thread.
    int jg = tid & 15, ig = tid >> 4;
    int i0 = ig * 4, j0 = jg * 8;
    float acc[4][8];
#pragma unroll
    for (int r = 0; r < 4; r++)
#pragma unroll
        for (int c = 0; c < 8; c++) acc[r][c] = 0.f;

    for (int k = 0; k < 128; k += 4) {
        float tr[4][4];
#pragma unroll
        for (int r = 0; r < 4; r++) {
            float4 v = *(const float4*)&tS[(i0 + r) * DEC_TS + k];
            tr[r][0] = v.x; tr[r][1] = v.y; tr[r][2] = v.z; tr[r][3] = v.w;
        }
#pragma unroll
        for (int kk = 0; kk < 4; kk++) {
            float4 w0 = *(const float4*)&W2s[(k + kk) * 128 + j0];
            float4 w1 = *(const float4*)&W2s[(k + kk) * 128 + j0 + 4];
            float wj[8] = {w0.x, w0.y, w0.z, w0.w, w1.x, w1.y, w1.z, w1.w};
#pragma unroll
            for (int r = 0; r < 4; r++) {
                float t = tr[r][kk];
#pragma unroll
                for (int c = 0; c < 8; c++) acc[r][c] = fmaf(t, wj[c], acc[r][c]);
            }
        }
    }

    float esum[4] = {0.f, 0.f, 0.f, 0.f};
#pragma unroll
    for (int c = 0; c < 8; c++) {
        float bb = b2[j0 + c];
        float ww = W3[j0 + c];
#pragma unroll
        for (int r = 0; r < 4; r++) {
            float u = acc[r][c] + bb;
            esum[r] += fmaxf(u, 0.f) * ww;
        }
    }
#pragma unroll
    for (int off = 8; off >= 1; off >>= 1)
#pragma unroll
        for (int r = 0; r < 4; r++)
            esum[r] += __shfl_down_sync(0xffffffffu, esum[r], off, 16);

    if (jg == 0) {
        float b3v = b3[0];
#pragma unroll
        for (int r = 0; r < 4; r++) {
            int e = eBase + i0 + r;
            if (e < E) out[e] = esum[r] + b3v;
        }
    }
}

extern "C" void kernel_launch(void* const* d_in, const int* in_sizes, int n_in,
                              void* d_out, int out_size) {
    const int* node_ids = (const int*)d_in[0];
    const int* ei       = (const int*)d_in[1];   // [2,E]
    const int* nei      = (const int*)d_in[2];   // [2,E]
    const float* eattr  = (const float*)d_in[3]; // [E]
    const float* emb    = (const float*)d_in[4]; // [N,128]
    const float* W_in   = (const float*)d_in[5]; // [128,256]
    const float* b_in   = (const float*)d_in[6]; // [256]
    const float* W_out  = (const float*)d_in[7]; // [256,128]
    const float* b_out  = (const float*)d_in[8]; // [128]
    const float* W1     = (const float*)d_in[9]; // [256,128]
    const float* b1     = (const float*)d_in[10];// [128]
    const float* W2     = (const float*)d_in[11];// [128,128]
    const float* b2     = (const float*)d_in[12];// [128]
    const float* W3     = (const float*)d_in[13];// [128,1]
    const float* b3     = (const float*)d_in[14];// [1]
    int N = in_sizes[0];
    int E = in_sizes[3];
    float* out = (float*)d_out;

    float *deg1, *deg2, *n1, *n2, *h1, *x1, *h2, *x2, *Ad, *Bd;
    cudaGetSymbolAddress((void**)&deg1, g_deg1);
    cudaGetSymbolAddress((void**)&deg2, g_deg2);
    cudaGetSymbolAddress((void**)&n1, g_norm1);
    cudaGetSymbolAddress((void**)&n2, g_norm2);
    cudaGetSymbolAddress((void**)&h1, g_h1);
    cudaGetSymbolAddress((void**)&x1, g_x1);
    cudaGetSymbolAddress((void**)&h2, g_h2);
    cudaGetSymbolAddress((void**)&x2, g_x2);
    cudaGetSymbolAddress((void**)&Ad, g_Adec);
    cudaGetSymbolAddress((void**)&Bd, g_Bdec);

    const int T = 256;
    int nz = (N + 3) / 4;
    zero4_kernel<<<(nz + T - 1) / T, T>>>((float4*)deg1, nz);
    zero4_kernel<<<(nz + T - 1) / T, T>>>((float4*)deg2, nz);
    int nx1 = N * 64;  // N*256/4
    zero4_kernel<<<(nx1 + T - 1) / T, T>>>((float4*)x1, nx1);
    int nx2 = N * 32;  // N*128/4
    zero4_kernel<<<(nx2 + T - 1) / T, T>>>((float4*)x2, nx2);

    deg_kernel<<<(E + T - 1) / T, T>>>(ei + E, eattr, nei + E, E);
    dinv_kernel<<<(N + T - 1) / T, T>>>(N);
    norm_kernel<<<(E + T - 1) / T, T>>>(ei, nei, eattr, E);

    dim3 gH((256 + 63) / 64, (N + 63) / 64);
    dim3 gD((128 + 63) / 64, (N + 63) / 64);

    // conv1: h1 = emb[node_ids] @ W_in ; scatter ; elu(+b_in)
    sgemm_kernel<<<gH, 256>>>(emb, W_in, h1, node_ids, N, 128, 256);
    {
        long tot = (long)E * 64;
        scatter_kernel<256><<<(int)((tot + T - 1) / T), T>>>(h1, x1, ei, n1, E);
    }
    bias_elu_kernel<<<(N * 256 + T - 1) / T, T>>>(x1, b_in, N * 256, 256);

    // conv2: h2 = x1 @ W_out ; scatter ; elu(+b_out)
    sgemm_kernel<<<gD, 256>>>(x1, W_out, h2, nullptr, N, 256, 128);
    {
        long tot = (long)E * 32;
        scatter_kernel<128><<<(int)((tot + T - 1) / T), T>>>(h2, x2, nei, n2, E);
    }
    bias_elu_kernel<<<(N * 128 + T - 1) / T, T>>>(x2, b_out, N * 128, 128);

    // decoder pre-GEMMs: A = x2 @ W1[:128,:], B = x2 @ W1[128:,:]
    sgemm_kernel<<<gD, 256>>>(x2, W1, Ad, nullptr, N, 128, 128);
    sgemm_kernel<<<gD, 256>>>(x2, W1 + 128 * 128, Bd, nullptr, N, 128, 128);

    // edge decoder
    int smem_dec = (64 * DEC_TS + 128 * 128) * 4;
    cudaFuncSetAttribute(decoder_kernel, cudaFuncAttributeMaxDynamicSharedMemorySize, smem_dec);
    decoder_kernel<<<(E + 63) / 64, 256, smem_dec>>>(Ad, Bd, ei, b1, W2, b2, W3, b3, out, E);
}

// round 2
// speedup vs baseline: 1.7826x; 1.7826x over previous
#include <cuda_runtime.h>
#include <math.h>

#define MAXN 50000
#define MAXE 800000

// ---- scratch (device globals; no allocation allowed) ----
__device__ float g_deg1[MAXN];
__device__ float g_deg2[MAXN];
__device__ float g_norm1[MAXE];
__device__ float g_norm2[MAXE];
__device__ float g_agg1[(size_t)MAXN * 128];
__device__ float g_x1[(size_t)MAXN * 256];
__device__ float g_h2[(size_t)MAXN * 128];
__device__ float g_x2[(size_t)MAXN * 128];
__device__ float g_Adec[(size_t)MAXN * 128];
__device__ float g_Bdec[(size_t)MAXN * 128];

// ---- zeroing ----
__global__ void zero4_kernel(float4* p, int n4) {
    int i = blockIdx.x * blockDim.x + threadIdx.x;
    if (i < n4) p[i] = make_float4(0.f, 0.f, 0.f, 0.f);
}

// ---- degree accumulation (both convs in one pass) ----
__global__ void deg_kernel(const int* __restrict__ col1, const float* __restrict__ w,
                           const int* __restrict__ col2, int E) {
    int e = blockIdx.x * blockDim.x + threadIdx.x;
    if (e < E) {
        atomicAdd(&g_deg1[col1[e]], w[e]);
        atomicAdd(&g_deg2[col2[e]], 1.0f);
    }
}

__global__ void dinv_kernel(int N) {
    int i = blockIdx.x * blockDim.x + threadIdx.x;
    if (i < N) {
        float d1 = g_deg1[i];
        g_deg1[i] = d1 > 0.f ? 1.0f / sqrtf(d1) : 0.f;
        float d2 = g_deg2[i];
        g_deg2[i] = d2 > 0.f ? 1.0f / sqrtf(d2) : 0.f;
    }
}

__global__ void norm_kernel(const int* __restrict__ ei, const int* __restrict__ nei,
                            const float* __restrict__ w, int E) {
    int e = blockIdx.x * blockDim.x + threadIdx.x;
    if (e < E) {
        g_norm1[e] = g_deg1[ei[e]] * w[e] * g_deg1[ei[E + e]];
        g_norm2[e] = g_deg2[nei[e]] * g_deg2[nei[E + e]];
    }
}

// ---- tiled SGEMM, optional row gather on A, optional fused bias(+elu) epilogue ----
// C[M,Nc] = act(gather(A)[M,K] @ B[K,Nc] + bias).  BM=BN=64, BK=16, 256 thr, 4x4/thread.
__global__ void sgemm_kernel(const float* __restrict__ A, const float* __restrict__ B,
                             float* __restrict__ C, const int* __restrict__ idx,
                             int M, int K, int Nc,
                             const float* __restrict__ bias, int act) {
    __shared__ float As[16][68];
    __shared__ float Bs[16][64];
    int tid = threadIdx.x;
    int bx = blockIdx.x, by = blockIdx.y;
    int tx = tid & 15, ty = tid >> 4;
    float acc[4][4];
#pragma unroll
    for (int i = 0; i < 4; i++)
#pragma unroll
        for (int j = 0; j < 4; j++) acc[i][j] = 0.f;

    int lrow = tid >> 2;
    int lk4 = (tid & 3) << 2;
    int grow = by * 64 + lrow;
    long arow = -1;
    if (grow < M) arow = idx ? (long)idx[grow] : (long)grow;
    int bk = tid >> 4;
    int bn4 = (tid & 15) << 2;
    int gcol = bx * 64 + bn4;

    for (int kt = 0; kt < K; kt += 16) {
        float4 av = make_float4(0.f, 0.f, 0.f, 0.f);
        if (arow >= 0) av = *(const float4*)(A + arow * (size_t)K + kt + lk4);
        As[lk4 + 0][lrow] = av.x;
        As[lk4 + 1][lrow] = av.y;
        As[lk4 + 2][lrow] = av.z;
        As[lk4 + 3][lrow] = av.w;
        *(float4*)&Bs[bk][bn4] = *(const float4*)(B + (size_t)(kt + bk) * Nc + gcol);
        __syncthreads();
#pragma unroll
        for (int k = 0; k < 16; k++) {
            float4 a = *(const float4*)&As[k][ty << 2];
            float4 b = *(const float4*)&Bs[k][tx << 2];
            float ar[4] = {a.x, a.y, a.z, a.w};
            float br[4] = {b.x, b.y, b.z, b.w};
#pragma unroll
            for (int i = 0; i < 4; i++)
#pragma unroll
                for (int j = 0; j < 4; j++) acc[i][j] = fmaf(ar[i], br[j], acc[i][j]);
        }
        __syncthreads();
    }
    int crow = by * 64 + (ty << 2);
    int ccol = bx * 64 + (tx << 2);
    float bz[4] = {0.f, 0.f, 0.f, 0.f};
    if (bias) { float4 b4 = *(const float4*)(bias + ccol); bz[0]=b4.x; bz[1]=b4.y; bz[2]=b4.z; bz[3]=b4.w; }
#pragma unroll
    for (int i = 0; i < 4; i++) {
        if (crow + i < M) {
            float v[4];
#pragma unroll
            for (int j = 0; j < 4; j++) {
                float u = acc[i][j] + bz[j];
                if (act) u = u > 0.f ? u : expm1f(u);
                v[j] = u;
            }
            *(float4*)(C + (size_t)(crow + i) * Nc + ccol) = make_float4(v[0], v[1], v[2], v[3]);
        }
    }
}

// ---- vectorized f32x4 reduction to global (no return) ----
__device__ __forceinline__ void red_add_v4(float* p, float x, float y, float z, float w) {
    asm volatile("red.global.add.v4.f32 [%0], {%1,%2,%3,%4};"
                 :: "l"(p), "f"(x), "f"(y), "f"(z), "f"(w) : "memory");
}

// ---- normalized message scatter: out[col] += h[remap(row)] * norm (C=128 wide) ----
__global__ void scatter128_kernel(const float* __restrict__ h, float* __restrict__ out,
                                  const int* __restrict__ idx2,  // rows [0,E), cols [E,2E)
                                  const float* __restrict__ nrm,
                                  const int* __restrict__ remap, int E) {
    int gid = blockIdx.x * blockDim.x + threadIdx.x;
    int e = gid >> 5;
    int q = gid & 31;
    if (e >= E) return;
    float n = nrm[e];
    if (n == 0.f) return;
    int r = idx2[e];
    if (remap) r = remap[r];
    int c = idx2[E + e];
    float4 v = *(const float4*)(h + (size_t)r * 128 + q * 4);
    float* o = out + (size_t)c * 128 + q * 4;
    red_add_v4(o, v.x * n, v.y * n, v.z * n, v.w * n);
}

// ---- x = elu(x + b) ----
__global__ void bias_elu_kernel(float* __restrict__ x, const float* __restrict__ b,
                                int total, int Cmask) {
    int i = blockIdx.x * blockDim.x + threadIdx.x;
    if (i < total) {
        float v = x[i] + b[i & Cmask];
        x[i] = v > 0.f ? v : expm1f(v);
    }
}

// ============================================================================
// Edge decoder with tf32 mma.sync:
//   out[e] = relu(relu(A[src]+B[dst]+b1) @ W2 + b2) @ W3 + b3
// 128 edges per block, 256 threads (8 warps). t in smem (tf32), W2 in smem (tf32).
// Each warp owns 16 edge-rows; mma m16n8k8 over K=128 (16 steps), N=128 (16 chunks).
// ============================================================================
#define TS_STRIDE 132
#define W2_STRIDE 136

__device__ __forceinline__ unsigned f2tf32(float x) {
    unsigned u;
    asm("cvt.rna.tf32.f32 %0, %1;" : "=r"(u) : "f"(x));
    return u;
}

__global__ __launch_bounds__(256, 1)
void decoder_mma_kernel(const float* __restrict__ Ad, const float* __restrict__ Bd,
                        const int* __restrict__ ei,  // src [0,E), dst [E,2E)
                        const float* __restrict__ b1, const float* __restrict__ W2,
                        const float* __restrict__ b2, const float* __restrict__ W3,
                        const float* __restrict__ b3, float* __restrict__ out, int E) {
    extern __shared__ unsigned smem[];
    unsigned* tS = smem;                       // 128 x TS_STRIDE (tf32 bits)
    unsigned* W2s = smem + 128 * TS_STRIDE;    // 128 x W2_STRIDE (tf32 bits)
    int tid = threadIdx.x;
    int warp = tid >> 5, lane = tid & 31;
    int qr = lane >> 2, qc = lane & 3;
    int eBase = blockIdx.x * 128;

    // stage W2 -> smem as tf32 (16384 floats, 64 per thread)
    {
#pragma unroll
        for (int i = 0; i < 16; i++) {
            int idx4 = tid + i * 256;          // float4 index, 4096 total
            int row = idx4 >> 5;
            int col = (idx4 & 31) << 2;
            float4 w = *(const float4*)(W2 + (row << 7) + col);
            unsigned* d = W2s + row * W2_STRIDE + col;
            d[0] = f2tf32(w.x); d[1] = f2tf32(w.y); d[2] = f2tf32(w.z); d[3] = f2tf32(w.w);
        }
    }
    // phase 1: t = relu(A[src] + B[dst] + b1) -> tf32 smem. 2 threads per edge.
    {
        int eloc = tid >> 1;
        int half = tid & 1;
        int e = eBase + eloc;
        unsigned* trow = tS + eloc * TS_STRIDE;
        if (e < E) {
            int s = ei[e], d = ei[E + e];
            const float* ap = Ad + (size_t)s * 128;
            const float* bp = Bd + (size_t)d * 128;
#pragma unroll
            for (int q = 0; q < 16; q++) {
                int k = half * 64 + q * 4;
                float4 a = *(const float4*)(ap + k);
                float4 b = *(const float4*)(bp + k);
                float4 bb = *(const float4*)(b1 + k);
                trow[k + 0] = f2tf32(fmaxf(a.x + b.x + bb.x, 0.f));
                trow[k + 1] = f2tf32(fmaxf(a.y + b.y + bb.y, 0.f));
                trow[k + 2] = f2tf32(fmaxf(a.z + b.z + bb.z, 0.f));
                trow[k + 3] = f2tf32(fmaxf(a.w + b.w + bb.w, 0.f));
            }
        } else {
#pragma unroll
            for (int q = 0; q < 16; q++) {
                int k = half * 64 + q * 4;
                trow[k] = 0u; trow[k + 1] = 0u; trow[k + 2] = 0u; trow[k + 3] = 0u;
            }
        }
    }
    __syncthreads();

    // phase 2: u = t @ W2 via mma.sync m16n8k8 tf32; warp owns rows r0..r0+15
    int r0 = warp * 16;
    float acc[16][4];
#pragma unroll
    for (int n = 0; n < 16; n++)
#pragma unroll
        for (int j = 0; j < 4; j++) acc[n][j] = 0.f;

    for (int kc = 0; kc < 16; kc++) {
        int kb = kc * 8;
        unsigned a0 = tS[(r0 + qr) * TS_STRIDE + kb + qc];
        unsigned a1 = tS[(r0 + qr + 8) * TS_STRIDE + kb + qc];
        unsigned a2 = tS[(r0 + qr) * TS_STRIDE + kb + qc + 4];
        unsigned a3 = tS[(r0 + qr + 8) * TS_STRIDE + kb + qc + 4];
#pragma unroll
        for (int nc = 0; nc < 16; nc++) {
            int nb = nc * 8;
            unsigned bf0 = W2s[(kb + qc) * W2_STRIDE + nb + qr];
            unsigned bf1 = W2s[(kb + qc + 4) * W2_STRIDE + nb + qr];
            asm volatile(
                "mma.sync.aligned.m16n8k8.row.col.f32.tf32.tf32.f32 "
                "{%0,%1,%2,%3}, {%4,%5,%6,%7}, {%8,%9}, {%0,%1,%2,%3};"
                : "+f"(acc[nc][0]), "+f"(acc[nc][1]), "+f"(acc[nc][2]), "+f"(acc[nc][3])
                : "r"(a0), "r"(a1), "r"(a2), "r"(a3), "r"(bf0), "r"(bf1));
        }
    }

    // epilogue: esum = relu(u + b2) . W3 ; reduce across quad columns
    float esum0 = 0.f, esum1 = 0.f;
#pragma unroll
    for (int nc = 0; nc < 16; nc++) {
        int c0 = nc * 8 + qc * 2;
        float bb0 = __ldg(b2 + c0), bb1 = __ldg(b2 + c0 + 1);
        float w0 = __ldg(W3 + c0), w1 = __ldg(W3 + c0 + 1);
        esum0 += fmaxf(acc[nc][0] + bb0, 0.f) * w0 + fmaxf(acc[nc][1] + bb1, 0.f) * w1;
        esum1 += fmaxf(acc[nc][2] + bb0, 0.f) * w0 + fmaxf(acc[nc][3] + bb1, 0.f) * w1;
    }
    esum0 += __shfl_xor_sync(0xffffffffu, esum0, 1);
    esum0 += __shfl_xor_sync(0xffffffffu, esum0, 2);
    esum1 += __shfl_xor_sync(0xffffffffu, esum1, 1);
    esum1 += __shfl_xor_sync(0xffffffffu, esum1, 2);

    if (qc == 0) {
        float b3v = __ldg(b3);
        int e0 = eBase + r0 + qr;
        int e1 = e0 + 8;
        if (e0 < E) out[e0] = esum0 + b3v;
        if (e1 < E) out[e1] = esum1 + b3v;
    }
}

extern "C" void kernel_launch(void* const* d_in, const int* in_sizes, int n_in,
                              void* d_out, int out_size) {
    const int* node_ids = (const int*)d_in[0];
    const int* ei       = (const int*)d_in[1];   // [2,E]
    const int* nei      = (const int*)d_in[2];   // [2,E]
    const float* eattr  = (const float*)d_in[3]; // [E]
    const float* emb    = (const float*)d_in[4]; // [N,128]
    const float* W_in   = (const float*)d_in[5]; // [128,256]
    const float* b_in   = (const float*)d_in[6]; // [256]
    const float* W_out  = (const float*)d_in[7]; // [256,128]
    const float* b_out  = (const float*)d_in[8]; // [128]
    const float* W1     = (const float*)d_in[9]; // [256,128]
    const float* b1     = (const float*)d_in[10];// [128]
    const float* W2     = (const float*)d_in[11];// [128,128]
    const float* b2     = (const float*)d_in[12];// [128]
    const float* W3     = (const float*)d_in[13];// [128,1]
    const float* b3     = (const float*)d_in[14];// [1]
    int N = in_sizes[0];
    int E = in_sizes[3];
    float* out = (float*)d_out;

    float *deg1, *deg2, *n1, *n2, *agg1, *x1, *h2, *x2, *Ad, *Bd;
    cudaGetSymbolAddress((void**)&deg1, g_deg1);
    cudaGetSymbolAddress((void**)&deg2, g_deg2);
    cudaGetSymbolAddress((void**)&n1, g_norm1);
    cudaGetSymbolAddress((void**)&n2, g_norm2);
    cudaGetSymbolAddress((void**)&agg1, g_agg1);
    cudaGetSymbolAddress((void**)&x1, g_x1);
    cudaGetSymbolAddress((void**)&h2, g_h2);
    cudaGetSymbolAddress((void**)&x2, g_x2);
    cudaGetSymbolAddress((void**)&Ad, g_Adec);
    cudaGetSymbolAddress((void**)&Bd, g_Bdec);

    const int T = 256;
    int nz = (N + 3) / 4;
    zero4_kernel<<<(nz + T - 1) / T, T>>>((float4*)deg1, nz);
    zero4_kernel<<<(nz + T - 1) / T, T>>>((float4*)deg2, nz);
    int nx = N * 32;  // N*128/4
    zero4_kernel<<<(nx + T - 1) / T, T>>>((float4*)agg1, nx);
    zero4_kernel<<<(nx + T - 1) / T, T>>>((float4*)x2, nx);

    deg_kernel<<<(E + T - 1) / T, T>>>(ei + E, eattr, nei + E, E);
    dinv_kernel<<<(N + T - 1) / T, T>>>(N);
    norm_kernel<<<(E + T - 1) / T, T>>>(ei, nei, eattr, E);

    dim3 gH((256 + 63) / 64, (N + 63) / 64);
    dim3 gD((128 + 63) / 64, (N + 63) / 64);

    // conv1 (linearity: scatter in 128-wide space, THEN GEMM with fused bias+elu)
    {
        long tot = (long)E * 32;
        scatter128_kernel<<<(int)((tot + T - 1) / T), T>>>(emb, agg1, ei, n1, node_ids, E);
    }
    sgemm_kernel<<<gH, 256>>>(agg1, W_in, x1, nullptr, N, 128, 256, b_in, 1);

    // conv2: h2 = x1 @ W_out ; scatter ; elu(+b_out)
    sgemm_kernel<<<gD, 256>>>(x1, W_out, h2, nullptr, N, 256, 128, nullptr, 0);
    {
        long tot = (long)E * 32;
        scatter128_kernel<<<(int)((tot + T - 1) / T), T>>>(h2, x2, nei, n2, nullptr, E);
    }
    bias_elu_kernel<<<(N * 128 + T - 1) / T, T>>>(x2, b_out, N * 128, 127);

    // decoder pre-GEMMs: A = x2 @ W1[:128,:], B = x2 @ W1[128:,:]
    sgemm_kernel<<<gD, 256>>>(x2, W1, Ad, nullptr, N, 128, 128, nullptr, 0);
    sgemm_kernel<<<gD, 256>>>(x2, W1 + 128 * 128, Bd, nullptr, N, 128, 128, nullptr, 0);

    // edge decoder (tf32 tensor cores)
    int smem_dec = (128 * TS_STRIDE + 128 * W2_STRIDE) * 4;
    cudaFuncSetAttribute(decoder_mma_kernel, cudaFuncAttributeMaxDynamicSharedMemorySize, smem_dec);
    decoder_mma_kernel<<<(E + 127) / 128, 256, smem_dec>>>(Ad, Bd, ei, b1, W2, b2, W3, b3, out, E);
}

// round 3
// speedup vs baseline: 1.8148x; 1.0181x over previous
#include <cuda_runtime.h>
#include <math.h>

#define MAXN 50000
#define MAXE 800000

// ---- scratch (device globals; no allocation allowed) ----
__device__ float g_deg1[MAXN];
__device__ float g_deg2[MAXN];
__device__ float g_norm1[MAXE];
__device__ float g_norm2[MAXE];
__device__ float g_agg1[(size_t)MAXN * 128];
__device__ float g_x1[(size_t)MAXN * 256];
__device__ float g_h2[(size_t)MAXN * 128];
__device__ float g_x2[(size_t)MAXN * 128];
__device__ float g_Adec[(size_t)MAXN * 128];
__device__ float g_Bdec[(size_t)MAXN * 128];

__device__ __forceinline__ unsigned f2tf32(float x) {
    unsigned u;
    asm("cvt.rna.tf32.f32 %0, %1;" : "=r"(u) : "f"(x));
    return u;
}

// ---- zeroing ----
__global__ void zero4_kernel(float4* p, int n4) {
    int i = blockIdx.x * blockDim.x + threadIdx.x;
    if (i < n4) p[i] = make_float4(0.f, 0.f, 0.f, 0.f);
}

// ---- degree accumulation (both convs in one pass) ----
__global__ void deg_kernel(const int* __restrict__ col1, const float* __restrict__ w,
                           const int* __restrict__ col2, int E) {
    int e = blockIdx.x * blockDim.x + threadIdx.x;
    if (e < E) {
        atomicAdd(&g_deg1[col1[e]], w[e]);
        atomicAdd(&g_deg2[col2[e]], 1.0f);
    }
}

__global__ void dinv_kernel(int N) {
    int i = blockIdx.x * blockDim.x + threadIdx.x;
    if (i < N) {
        float d1 = g_deg1[i];
        g_deg1[i] = d1 > 0.f ? 1.0f / sqrtf(d1) : 0.f;
        float d2 = g_deg2[i];
        g_deg2[i] = d2 > 0.f ? 1.0f / sqrtf(d2) : 0.f;
    }
}

__global__ void norm_kernel(const int* __restrict__ ei, const int* __restrict__ nei,
                            const float* __restrict__ w, int E) {
    int e = blockIdx.x * blockDim.x + threadIdx.x;
    if (e < E) {
        g_norm1[e] = g_deg1[ei[e]] * w[e] * g_deg1[ei[E + e]];
        g_norm2[e] = g_deg2[nei[e]] * g_deg2[nei[E + e]];
    }
}

// ============================================================================
// tf32 mma.sync node GEMM: C[M,Nc] = act(A[M,K] @ W[K,Nc] + bias)
// Block: 128 rows x 128 cols, 256 threads (8 warps x 16 rows), BK=32.
// SPLIT=1: 3-term hi/lo compensation (AhBh + AhBl + AlBh) ~ fp32 accuracy.
// ============================================================================
#define AS_STRIDE 36
#define WS_STRIDE 132

template <int SPLIT>
__global__ __launch_bounds__(256, 1)
void gemm_tf32_kernel(const float* __restrict__ A, const float* __restrict__ W,
                      float* __restrict__ C, int M, int K, int Nc,
                      const float* __restrict__ bias, int act) {
    extern __shared__ unsigned sm[];
    unsigned* Ah = sm;                                   // 128 x AS_STRIDE
    unsigned* Al = Ah + 128 * AS_STRIDE;                 // (SPLIT only)
    unsigned* Wh = Al + (SPLIT ? 128 * AS_STRIDE : 0);   // 32 x WS_STRIDE
    unsigned* Wl = Wh + 32 * WS_STRIDE;                  // (SPLIT only)

    int tid = threadIdx.x;
    int warp = tid >> 5, lane = tid & 31;
    int qr = lane >> 2, qc = lane & 3;
    int m0 = blockIdx.y * 128;
    int n0 = blockIdx.x * 128;
    int r0 = warp * 16;

    float acc[16][4];
#pragma unroll
    for (int n = 0; n < 16; n++)
#pragma unroll
        for (int j = 0; j < 4; j++) acc[n][j] = 0.f;

    for (int kt = 0; kt < K; kt += 32) {
        // stage A tile: 128 rows x 32 k  (1024 float4, 4 per thread)
#pragma unroll
        for (int i = 0; i < 4; i++) {
            int idx4 = tid + i * 256;
            int row = idx4 >> 3;
            int col = (idx4 & 7) << 2;
            float4 v = make_float4(0.f, 0.f, 0.f, 0.f);
            if (m0 + row < M) v = *(const float4*)(A + (size_t)(m0 + row) * K + kt + col);
            unsigned* dh = Ah + row * AS_STRIDE + col;
            unsigned h0 = f2tf32(v.x), h1 = f2tf32(v.y), h2_ = f2tf32(v.z), h3 = f2tf32(v.w);
            dh[0] = h0; dh[1] = h1; dh[2] = h2_; dh[3] = h3;
            if (SPLIT) {
                unsigned* dl = Al + row * AS_STRIDE + col;
                dl[0] = f2tf32(v.x - __uint_as_float(h0));
                dl[1] = f2tf32(v.y - __uint_as_float(h1));
                dl[2] = f2tf32(v.z - __uint_as_float(h2_));
                dl[3] = f2tf32(v.w - __uint_as_float(h3));
            }
        }
        // stage W tile: 32 k x 128 n  (1024 float4, 4 per thread)
#pragma unroll
        for (int i = 0; i < 4; i++) {
            int idx4 = tid + i * 256;
            int row = idx4 >> 5;
            int col = (idx4 & 31) << 2;
            float4 v = *(const float4*)(W + (size_t)(kt + row) * Nc + n0 + col);
            unsigned* dh = Wh + row * WS_STRIDE + col;
            unsigned h0 = f2tf32(v.x), h1 = f2tf32(v.y), h2_ = f2tf32(v.z), h3 = f2tf32(v.w);
            dh[0] = h0; dh[1] = h1; dh[2] = h2_; dh[3] = h3;
            if (SPLIT) {
                unsigned* dl = Wl + row * WS_STRIDE + col;
                dl[0] = f2tf32(v.x - __uint_as_float(h0));
                dl[1] = f2tf32(v.y - __uint_as_float(h1));
                dl[2] = f2tf32(v.z - __uint_as_float(h2_));
                dl[3] = f2tf32(v.w - __uint_as_float(h3));
            }
        }
        __syncthreads();

#pragma unroll
        for (int kk = 0; kk < 4; kk++) {
            int kb = kk * 8;
            unsigned ah0 = Ah[(r0 + qr) * AS_STRIDE + kb + qc];
            unsigned ah1 = Ah[(r0 + qr + 8) * AS_STRIDE + kb + qc];
            unsigned ah2 = Ah[(r0 + qr) * AS_STRIDE + kb + qc + 4];
            unsigned ah3 = Ah[(r0 + qr + 8) * AS_STRIDE + kb + qc + 4];
            unsigned al0, al1, al2, al3;
            if (SPLIT) {
                al0 = Al[(r0 + qr) * AS_STRIDE + kb + qc];
                al1 = Al[(r0 + qr + 8) * AS_STRIDE + kb + qc];
                al2 = Al[(r0 + qr) * AS_STRIDE + kb + qc + 4];
                al3 = Al[(r0 + qr + 8) * AS_STRIDE + kb + qc + 4];
            }
#pragma unroll
            for (int nc = 0; nc < 16; nc++) {
                int nb = nc * 8;
                unsigned bh0 = Wh[(kb + qc) * WS_STRIDE + nb + qr];
                unsigned bh1 = Wh[(kb + qc + 4) * WS_STRIDE + nb + qr];
                asm volatile(
                    "mma.sync.aligned.m16n8k8.row.col.f32.tf32.tf32.f32 "
                    "{%0,%1,%2,%3}, {%4,%5,%6,%7}, {%8,%9}, {%0,%1,%2,%3};"
                    : "+f"(acc[nc][0]), "+f"(acc[nc][1]), "+f"(acc[nc][2]), "+f"(acc[nc][3])
                    : "r"(ah0), "r"(ah1), "r"(ah2), "r"(ah3), "r"(bh0), "r"(bh1));
                if (SPLIT) {
                    unsigned bl0 = Wl[(kb + qc) * WS_STRIDE + nb + qr];
                    unsigned bl1 = Wl[(kb + qc + 4) * WS_STRIDE + nb + qr];
                    asm volatile(
                        "mma.sync.aligned.m16n8k8.row.col.f32.tf32.tf32.f32 "
                        "{%0,%1,%2,%3}, {%4,%5,%6,%7}, {%8,%9}, {%0,%1,%2,%3};"
                        : "+f"(acc[nc][0]), "+f"(acc[nc][1]), "+f"(acc[nc][2]), "+f"(acc[nc][3])
                        : "r"(ah0), "r"(ah1), "r"(ah2), "r"(ah3), "r"(bl0), "r"(bl1));
                    asm volatile(
                        "mma.sync.aligned.m16n8k8.row.col.f32.tf32.tf32.f32 "
                        "{%0,%1,%2,%3}, {%4,%5,%6,%7}, {%8,%9}, {%0,%1,%2,%3};"
                        : "+f"(acc[nc][0]), "+f"(acc[nc][1]), "+f"(acc[nc][2]), "+f"(acc[nc][3])
                        : "r"(al0), "r"(al1), "r"(al2), "r"(al3), "r"(bh0), "r"(bh1));
                }
            }
        }
        __syncthreads();
    }

    // epilogue: bias + optional elu, float2 stores
    int row0 = m0 + r0 + qr;
    int row1 = row0 + 8;
#pragma unroll
    for (int nc = 0; nc < 16; nc++) {
        int c0 = n0 + nc * 8 + qc * 2;
        float bz0 = 0.f, bz1 = 0.f;
        if (bias) { bz0 = __ldg(bias + c0); bz1 = __ldg(bias + c0 + 1); }
        float u0 = acc[nc][0] + bz0, u1 = acc[nc][1] + bz1;
        float u2 = acc[nc][2] + bz0, u3 = acc[nc][3] + bz1;
        if (act) {
            u0 = u0 > 0.f ? u0 : expm1f(u0);
            u1 = u1 > 0.f ? u1 : expm1f(u1);
            u2 = u2 > 0.f ? u2 : expm1f(u2);
            u3 = u3 > 0.f ? u3 : expm1f(u3);
        }
        if (row0 < M) *(float2*)(C + (size_t)row0 * Nc + c0) = make_float2(u0, u1);
        if (row1 < M) *(float2*)(C + (size_t)row1 * Nc + c0) = make_float2(u2, u3);
    }
}

// ---- vectorized f32x4 reduction to global (no return) ----
__device__ __forceinline__ void red_add_v4(float* p, float x, float y, float z, float w) {
    asm volatile("red.global.add.v4.f32 [%0], {%1,%2,%3,%4};"
                 :: "l"(p), "f"(x), "f"(y), "f"(z), "f"(w) : "memory");
}

// ---- normalized message scatter: out[col] += h[remap(row)] * norm (C=128 wide) ----
__global__ void scatter128_kernel(const float* __restrict__ h, float* __restrict__ out,
                                  const int* __restrict__ idx2,  // rows [0,E), cols [E,2E)
                                  const float* __restrict__ nrm,
                                  const int* __restrict__ remap, int E) {
    int gid = blockIdx.x * blockDim.x + threadIdx.x;
    int e = gid >> 5;
    int q = gid & 31;
    if (e >= E) return;
    float n = nrm[e];
    if (n == 0.f) return;
    int r = idx2[e];
    if (remap) r = remap[r];
    int c = idx2[E + e];
    float4 v = *(const float4*)(h + (size_t)r * 128 + q * 4);
    float* o = out + (size_t)c * 128 + q * 4;
    red_add_v4(o, v.x * n, v.y * n, v.z * n, v.w * n);
}

// ---- x = elu(x + b) ----
__global__ void bias_elu_kernel(float* __restrict__ x, const float* __restrict__ b,
                                int total, int Cmask) {
    int i = blockIdx.x * blockDim.x + threadIdx.x;
    if (i < total) {
        float v = x[i] + b[i & Cmask];
        x[i] = v > 0.f ? v : expm1f(v);
    }
}

// ============================================================================
// Edge decoder with tf32 mma.sync:
//   out[e] = relu(relu(A[src]+B[dst]+b1) @ W2 + b2) @ W3 + b3
// ============================================================================
#define TS_STRIDE 132
#define W2_STRIDE 136

__global__ __launch_bounds__(256, 1)
void decoder_mma_kernel(const float* __restrict__ Ad, const float* __restrict__ Bd,
                        const int* __restrict__ ei,  // src [0,E), dst [E,2E)
                        const float* __restrict__ b1, const float* __restrict__ W2,
                        const float* __restrict__ b2, const float* __restrict__ W3,
                        const float* __restrict__ b3, float* __restrict__ out, int E) {
    extern __shared__ unsigned smem[];
    unsigned* tS = smem;                       // 128 x TS_STRIDE (tf32 bits)
    unsigned* W2s = smem + 128 * TS_STRIDE;    // 128 x W2_STRIDE (tf32 bits)
    int tid = threadIdx.x;
    int warp = tid >> 5, lane = tid & 31;
    int qr = lane >> 2, qc = lane & 3;
    int eBase = blockIdx.x * 128;

    // stage W2 -> smem as tf32
    {
#pragma unroll
        for (int i = 0; i < 16; i++) {
            int idx4 = tid + i * 256;
            int row = idx4 >> 5;
            int col = (idx4 & 31) << 2;
            float4 w = *(const float4*)(W2 + (row << 7) + col);
            unsigned* d = W2s + row * W2_STRIDE + col;
            d[0] = f2tf32(w.x); d[1] = f2tf32(w.y); d[2] = f2tf32(w.z); d[3] = f2tf32(w.w);
        }
    }
    // phase 1: t = relu(A[src] + B[dst] + b1) -> tf32 smem. 2 threads per edge.
    {
        int eloc = tid >> 1;
        int half = tid & 1;
        int e = eBase + eloc;
        unsigned* trow = tS + eloc * TS_STRIDE;
        if (e < E) {
            int s = ei[e], d = ei[E + e];
            const float* ap = Ad + (size_t)s * 128;
            const float* bp = Bd + (size_t)d * 128;
#pragma unroll
            for (int q = 0; q < 16; q++) {
                int k = half * 64 + q * 4;
                float4 a = *(const float4*)(ap + k);
                float4 b = *(const float4*)(bp + k);
                float4 bb = *(const float4*)(b1 + k);
                trow[k + 0] = f2tf32(fmaxf(a.x + b.x + bb.x, 0.f));
                trow[k + 1] = f2tf32(fmaxf(a.y + b.y + bb.y, 0.f));
                trow[k + 2] = f2tf32(fmaxf(a.z + b.z + bb.z, 0.f));
                trow[k + 3] = f2tf32(fmaxf(a.w + b.w + bb.w, 0.f));
            }
        } else {
#pragma unroll
            for (int q = 0; q < 16; q++) {
                int k = half * 64 + q * 4;
                trow[k] = 0u; trow[k + 1] = 0u; trow[k + 2] = 0u; trow[k + 3] = 0u;
            }
        }
    }
    __syncthreads();

    // phase 2: u = t @ W2 via mma.sync m16n8k8 tf32; warp owns rows r0..r0+15
    int r0 = warp * 16;
    float acc[16][4];
#pragma unroll
    for (int n = 0; n < 16; n++)
#pragma unroll
        for (int j = 0; j < 4; j++) acc[n][j] = 0.f;

    for (int kc = 0; kc < 16; kc++) {
        int kb = kc * 8;
        unsigned a0 = tS[(r0 + qr) * TS_STRIDE + kb + qc];
        unsigned a1 = tS[(r0 + qr + 8) * TS_STRIDE + kb + qc];
        unsigned a2 = tS[(r0 + qr) * TS_STRIDE + kb + qc + 4];
        unsigned a3 = tS[(r0 + qr + 8) * TS_STRIDE + kb + qc + 4];
#pragma unroll
        for (int nc = 0; nc < 16; nc++) {
            int nb = nc * 8;
            unsigned bf0 = W2s[(kb + qc) * W2_STRIDE + nb + qr];
            unsigned bf1 = W2s[(kb + qc + 4) * W2_STRIDE + nb + qr];
            asm volatile(
                "mma.sync.aligned.m16n8k8.row.col.f32.tf32.tf32.f32 "
                "{%0,%1,%2,%3}, {%4,%5,%6,%7}, {%8,%9}, {%0,%1,%2,%3};"
                : "+f"(acc[nc][0]), "+f"(acc[nc][1]), "+f"(acc[nc][2]), "+f"(acc[nc][3])
                : "r"(a0), "r"(a1), "r"(a2), "r"(a3), "r"(bf0), "r"(bf1));
        }
    }

    // epilogue: esum = relu(u + b2) . W3 ; reduce across quad columns
    float esum0 = 0.f, esum1 = 0.f;
#pragma unroll
    for (int nc = 0; nc < 16; nc++) {
        int c0 = nc * 8 + qc * 2;
        float bb0 = __ldg(b2 + c0), bb1 = __ldg(b2 + c0 + 1);
        float w0 = __ldg(W3 + c0), w1 = __ldg(W3 + c0 + 1);
        esum0 += fmaxf(acc[nc][0] + bb0, 0.f) * w0 + fmaxf(acc[nc][1] + bb1, 0.f) * w1;
        esum1 += fmaxf(acc[nc][2] + bb0, 0.f) * w0 + fmaxf(acc[nc][3] + bb1, 0.f) * w1;
    }
    esum0 += __shfl_xor_sync(0xffffffffu, esum0, 1);
    esum0 += __shfl_xor_sync(0xffffffffu, esum0, 2);
    esum1 += __shfl_xor_sync(0xffffffffu, esum1, 1);
    esum1 += __shfl_xor_sync(0xffffffffu, esum1, 2);

    if (qc == 0) {
        float b3v = __ldg(b3);
        int e0 = eBase + r0 + qr;
        int e1 = e0 + 8;
        if (e0 < E) out[e0] = esum0 + b3v;
        if (e1 < E) out[e1] = esum1 + b3v;
    }
}

extern "C" void kernel_launch(void* const* d_in, const int* in_sizes, int n_in,
                              void* d_out, int out_size) {
    const int* node_ids = (const int*)d_in[0];
    const int* ei       = (const int*)d_in[1];   // [2,E]
    const int* nei      = (const int*)d_in[2];   // [2,E]
    const float* eattr  = (const float*)d_in[3]; // [E]
    const float* emb    = (const float*)d_in[4]; // [N,128]
    const float* W_in   = (const float*)d_in[5]; // [128,256]
    const float* b_in   = (const float*)d_in[6]; // [256]
    const float* W_out  = (const float*)d_in[7]; // [256,128]
    const float* b_out  = (const float*)d_in[8]; // [128]
    const float* W1     = (const float*)d_in[9]; // [256,128]
    const float* b1     = (const float*)d_in[10];// [128]
    const float* W2     = (const float*)d_in[11];// [128,128]
    const float* b2     = (const float*)d_in[12];// [128]
    const float* W3     = (const float*)d_in[13];// [128,1]
    const float* b3     = (const float*)d_in[14];// [1]
    int N = in_sizes[0];
    int E = in_sizes[3];
    float* out = (float*)d_out;

    float *deg1, *deg2, *n1, *n2, *agg1, *x1, *h2, *x2, *Ad, *Bd;
    cudaGetSymbolAddress((void**)&deg1, g_deg1);
    cudaGetSymbolAddress((void**)&deg2, g_deg2);
    cudaGetSymbolAddress((void**)&n1, g_norm1);
    cudaGetSymbolAddress((void**)&n2, g_norm2);
    cudaGetSymbolAddress((void**)&agg1, g_agg1);
    cudaGetSymbolAddress((void**)&x1, g_x1);
    cudaGetSymbolAddress((void**)&h2, g_h2);
    cudaGetSymbolAddress((void**)&x2, g_x2);
    cudaGetSymbolAddress((void**)&Ad, g_Adec);
    cudaGetSymbolAddress((void**)&Bd, g_Bdec);

    const int T = 256;
    int nz = (N + 3) / 4;
    zero4_kernel<<<(nz + T - 1) / T, T>>>((float4*)deg1, nz);
    zero4_kernel<<<(nz + T - 1) / T, T>>>((float4*)deg2, nz);
    int nx = N * 32;  // N*128/4
    zero4_kernel<<<(nx + T - 1) / T, T>>>((float4*)agg1, nx);
    zero4_kernel<<<(nx + T - 1) / T, T>>>((float4*)x2, nx);

    deg_kernel<<<(E + T - 1) / T, T>>>(ei + E, eattr, nei + E, E);
    dinv_kernel<<<(N + T - 1) / T, T>>>(N);
    norm_kernel<<<(E + T - 1) / T, T>>>(ei, nei, eattr, E);

    int mBlocks = (N + 127) / 128;
    int smem_split = (128 * AS_STRIDE * 2 + 32 * WS_STRIDE * 2) * 4;
    int smem_plain = (128 * AS_STRIDE + 32 * WS_STRIDE) * 4;
    cudaFuncSetAttribute(gemm_tf32_kernel<1>, cudaFuncAttributeMaxDynamicSharedMemorySize, smem_split);
    cudaFuncSetAttribute(gemm_tf32_kernel<0>, cudaFuncAttributeMaxDynamicSharedMemorySize, smem_plain);

    // conv1 (linearity: scatter in 128-wide space, THEN GEMM with fused bias+elu)
    {
        long tot = (long)E * 32;
        scatter128_kernel<<<(int)((tot + T - 1) / T), T>>>(emb, agg1, ei, n1, node_ids, E);
    }
    gemm_tf32_kernel<1><<<dim3(2, mBlocks), 256, smem_split>>>(agg1, W_in, x1, N, 128, 256, b_in, 1);

    // conv2: h2 = x1 @ W_out ; scatter ; elu(+b_out)
    gemm_tf32_kernel<1><<<dim3(1, mBlocks), 256, smem_split>>>(x1, W_out, h2, N, 256, 128, nullptr, 0);
    {
        long tot = (long)E * 32;
        scatter128_kernel<<<(int)((tot + T - 1) / T), T>>>(h2, x2, nei, n2, nullptr, E);
    }
    bias_elu_kernel<<<(N * 128 + T - 1) / T, T>>>(x2, b_out, N * 128, 127);

    // decoder pre-GEMMs: A = x2 @ W1[:128,:], B = x2 @ W1[128:,:] (single-pass tf32)
    gemm_tf32_kernel<0><<<dim3(1, mBlocks), 256, smem_plain>>>(x2, W1, Ad, N, 128, 128, nullptr, 0);
    gemm_tf32_kernel<0><<<dim3(1, mBlocks), 256, smem_plain>>>(x2, W1 + 128 * 128, Bd, N, 128, 128, nullptr, 0);

    // edge decoder (tf32 tensor cores)
    int smem_dec = (128 * TS_STRIDE + 128 * W2_STRIDE) * 4;
    cudaFuncSetAttribute(decoder_mma_kernel, cudaFuncAttributeMaxDynamicSharedMemorySize, smem_dec);
    decoder_mma_kernel<<<(E + 127) / 128, 256, smem_dec>>>(Ad, Bd, ei, b1, W2, b2, W3, b3, out, E);
}

// round 4
// speedup vs baseline: 1.9262x; 1.0614x over previous
#include <cuda_runtime.h>
#include <math.h>

#define MAXN 50000
#define MAXE 800000

// ---- scratch (device globals; no allocation allowed) ----
__device__ float g_deg1[MAXN];
__device__ float g_deg2[MAXN];
__device__ float g_norm1[MAXE];
__device__ float g_norm2[MAXE];
__device__ float g_agg1[(size_t)MAXN * 128];
__device__ float g_x1[(size_t)MAXN * 256];
__device__ float g_h2[(size_t)MAXN * 128];
__device__ float g_x2[(size_t)MAXN * 128];
__device__ float g_Adec[(size_t)MAXN * 128];
__device__ float g_Bdec[(size_t)MAXN * 128];

__device__ __forceinline__ unsigned f2tf32(float x) {
    unsigned u;
    asm("cvt.rna.tf32.f32 %0, %1;" : "=r"(u) : "f"(x));
    return u;
}

// ---- fused zeroing of all accumulation buffers ----
__global__ void zero_all_kernel(float4* deg1, float4* deg2, float4* agg1, float4* x2,
                                int nDeg4, int nX4) {
    int i = blockIdx.x * blockDim.x + threadIdx.x;
    const float4 z = make_float4(0.f, 0.f, 0.f, 0.f);
    if (i < nDeg4) { deg1[i] = z; deg2[i] = z; }
    for (int j = i; j < nX4; j += gridDim.x * blockDim.x) {
        agg1[j] = z;
        x2[j] = z;
    }
}

// ---- degree accumulation (both convs in one pass) ----
__global__ void deg_kernel(const int* __restrict__ col1, const float* __restrict__ w,
                           const int* __restrict__ col2, int E) {
    int e = blockIdx.x * blockDim.x + threadIdx.x;
    if (e < E) {
        atomicAdd(&g_deg1[col1[e]], w[e]);
        atomicAdd(&g_deg2[col2[e]], 1.0f);
    }
}

__global__ void dinv_kernel(int N) {
    int i = blockIdx.x * blockDim.x + threadIdx.x;
    if (i < N) {
        float d1 = g_deg1[i];
        g_deg1[i] = d1 > 0.f ? 1.0f / sqrtf(d1) : 0.f;
        float d2 = g_deg2[i];
        g_deg2[i] = d2 > 0.f ? 1.0f / sqrtf(d2) : 0.f;
    }
}

__global__ void norm_kernel(const int* __restrict__ ei, const int* __restrict__ nei,
                            const float* __restrict__ w, int E) {
    int e = blockIdx.x * blockDim.x + threadIdx.x;
    if (e < E) {
        g_norm1[e] = g_deg1[ei[e]] * w[e] * g_deg1[ei[E + e]];
        g_norm2[e] = g_deg2[nei[e]] * g_deg2[nei[E + e]];
    }
}

// ============================================================================
// tf32 mma.sync node GEMM: C[M,Nc] = act(A[M,K] @ W[K,Nc] + bias)
// Block: 128 rows x 128 cols, 256 threads (8 warps x 16 rows), BK=32.
// SPLIT=1: 3-term hi/lo compensation ~ fp32 accuracy.
// PREACT=1: A is staged as elu(A + abias) (fuses previous layer's epilogue).
// ============================================================================
#define AS_STRIDE 36
#define WS_STRIDE 132

template <int SPLIT, int PREACT>
__global__ __launch_bounds__(256, 1)
void gemm_tf32_kernel(const float* __restrict__ A, const float* __restrict__ W,
                      float* __restrict__ C, int M, int K, int Nc,
                      const float* __restrict__ bias, int act,
                      const float* __restrict__ abias) {
    extern __shared__ unsigned sm[];
    unsigned* Ah = sm;
    unsigned* Al = Ah + 128 * AS_STRIDE;
    unsigned* Wh = Al + (SPLIT ? 128 * AS_STRIDE : 0);
    unsigned* Wl = Wh + 32 * WS_STRIDE;

    int tid = threadIdx.x;
    int warp = tid >> 5, lane = tid & 31;
    int qr = lane >> 2, qc = lane & 3;
    int m0 = blockIdx.y * 128;
    int n0 = blockIdx.x * 128;
    int r0 = warp * 16;

    float acc[16][4];
#pragma unroll
    for (int n = 0; n < 16; n++)
#pragma unroll
        for (int j = 0; j < 4; j++) acc[n][j] = 0.f;

    for (int kt = 0; kt < K; kt += 32) {
#pragma unroll
        for (int i = 0; i < 4; i++) {
            int idx4 = tid + i * 256;
            int row = idx4 >> 3;
            int col = (idx4 & 7) << 2;
            float4 v = make_float4(0.f, 0.f, 0.f, 0.f);
            if (m0 + row < M) v = *(const float4*)(A + (size_t)(m0 + row) * K + kt + col);
            if (PREACT) {
                float4 ab = *(const float4*)(abias + kt + col);
                v.x += ab.x; v.y += ab.y; v.z += ab.z; v.w += ab.w;
                v.x = v.x > 0.f ? v.x : expm1f(v.x);
                v.y = v.y > 0.f ? v.y : expm1f(v.y);
                v.z = v.z > 0.f ? v.z : expm1f(v.z);
                v.w = v.w > 0.f ? v.w : expm1f(v.w);
            }
            unsigned* dh = Ah + row * AS_STRIDE + col;
            unsigned h0 = f2tf32(v.x), h1 = f2tf32(v.y), h2_ = f2tf32(v.z), h3 = f2tf32(v.w);
            dh[0] = h0; dh[1] = h1; dh[2] = h2_; dh[3] = h3;
            if (SPLIT) {
                unsigned* dl = Al + row * AS_STRIDE + col;
                dl[0] = f2tf32(v.x - __uint_as_float(h0));
                dl[1] = f2tf32(v.y - __uint_as_float(h1));
                dl[2] = f2tf32(v.z - __uint_as_float(h2_));
                dl[3] = f2tf32(v.w - __uint_as_float(h3));
            }
        }
#pragma unroll
        for (int i = 0; i < 4; i++) {
            int idx4 = tid + i * 256;
            int row = idx4 >> 5;
            int col = (idx4 & 31) << 2;
            float4 v = *(const float4*)(W + (size_t)(kt + row) * Nc + n0 + col);
            unsigned* dh = Wh + row * WS_STRIDE + col;
            unsigned h0 = f2tf32(v.x), h1 = f2tf32(v.y), h2_ = f2tf32(v.z), h3 = f2tf32(v.w);
            dh[0] = h0; dh[1] = h1; dh[2] = h2_; dh[3] = h3;
            if (SPLIT) {
                unsigned* dl = Wl + row * WS_STRIDE + col;
                dl[0] = f2tf32(v.x - __uint_as_float(h0));
                dl[1] = f2tf32(v.y - __uint_as_float(h1));
                dl[2] = f2tf32(v.z - __uint_as_float(h2_));
                dl[3] = f2tf32(v.w - __uint_as_float(h3));
            }
        }
        __syncthreads();

#pragma unroll
        for (int kk = 0; kk < 4; kk++) {
            int kb = kk * 8;
            unsigned ah0 = Ah[(r0 + qr) * AS_STRIDE + kb + qc];
            unsigned ah1 = Ah[(r0 + qr + 8) * AS_STRIDE + kb + qc];
            unsigned ah2 = Ah[(r0 + qr) * AS_STRIDE + kb + qc + 4];
            unsigned ah3 = Ah[(r0 + qr + 8) * AS_STRIDE + kb + qc + 4];
            unsigned al0, al1, al2, al3;
            if (SPLIT) {
                al0 = Al[(r0 + qr) * AS_STRIDE + kb + qc];
                al1 = Al[(r0 + qr + 8) * AS_STRIDE + kb + qc];
                al2 = Al[(r0 + qr) * AS_STRIDE + kb + qc + 4];
                al3 = Al[(r0 + qr + 8) * AS_STRIDE + kb + qc + 4];
            }
#pragma unroll
            for (int nc = 0; nc < 16; nc++) {
                int nb = nc * 8;
                unsigned bh0 = Wh[(kb + qc) * WS_STRIDE + nb + qr];
                unsigned bh1 = Wh[(kb + qc + 4) * WS_STRIDE + nb + qr];
                asm volatile(
                    "mma.sync.aligned.m16n8k8.row.col.f32.tf32.tf32.f32 "
                    "{%0,%1,%2,%3}, {%4,%5,%6,%7}, {%8,%9}, {%0,%1,%2,%3};"
                    : "+f"(acc[nc][0]), "+f"(acc[nc][1]), "+f"(acc[nc][2]), "+f"(acc[nc][3])
                    : "r"(ah0), "r"(ah1), "r"(ah2), "r"(ah3), "r"(bh0), "r"(bh1));
                if (SPLIT) {
                    unsigned bl0 = Wl[(kb + qc) * WS_STRIDE + nb + qr];
                    unsigned bl1 = Wl[(kb + qc + 4) * WS_STRIDE + nb + qr];
                    asm volatile(
                        "mma.sync.aligned.m16n8k8.row.col.f32.tf32.tf32.f32 "
                        "{%0,%1,%2,%3}, {%4,%5,%6,%7}, {%8,%9}, {%0,%1,%2,%3};"
                        : "+f"(acc[nc][0]), "+f"(acc[nc][1]), "+f"(acc[nc][2]), "+f"(acc[nc][3])
                        : "r"(ah0), "r"(ah1), "r"(ah2), "r"(ah3), "r"(bl0), "r"(bl1));
                    asm volatile(
                        "mma.sync.aligned.m16n8k8.row.col.f32.tf32.tf32.f32 "
                        "{%0,%1,%2,%3}, {%4,%5,%6,%7}, {%8,%9}, {%0,%1,%2,%3};"
                        : "+f"(acc[nc][0]), "+f"(acc[nc][1]), "+f"(acc[nc][2]), "+f"(acc[nc][3])
                        : "r"(al0), "r"(al1), "r"(al2), "r"(al3), "r"(bh0), "r"(bh1));
                }
            }
        }
        __syncthreads();
    }

    int row0 = m0 + r0 + qr;
    int row1 = row0 + 8;
#pragma unroll
    for (int nc = 0; nc < 16; nc++) {
        int c0 = n0 + nc * 8 + qc * 2;
        float bz0 = 0.f, bz1 = 0.f;
        if (bias) { bz0 = __ldg(bias + c0); bz1 = __ldg(bias + c0 + 1); }
        float u0 = acc[nc][0] + bz0, u1 = acc[nc][1] + bz1;
        float u2 = acc[nc][2] + bz0, u3 = acc[nc][3] + bz1;
        if (act) {
            u0 = u0 > 0.f ? u0 : expm1f(u0);
            u1 = u1 > 0.f ? u1 : expm1f(u1);
            u2 = u2 > 0.f ? u2 : expm1f(u2);
            u3 = u3 > 0.f ? u3 : expm1f(u3);
        }
        if (row0 < M) *(float2*)(C + (size_t)row0 * Nc + c0) = make_float2(u0, u1);
        if (row1 < M) *(float2*)(C + (size_t)row1 * Nc + c0) = make_float2(u2, u3);
    }
}

// ---- vectorized f32x4 reduction to global (no return) ----
__device__ __forceinline__ void red_add_v4(float* p, float x, float y, float z, float w) {
    asm volatile("red.global.add.v4.f32 [%0], {%1,%2,%3,%4};"
                 :: "l"(p), "f"(x), "f"(y), "f"(z), "f"(w) : "memory");
}

// ---- normalized message scatter: out[col] += h[remap(row)] * norm (C=128 wide) ----
__global__ void scatter128_kernel(const float* __restrict__ h, float* __restrict__ out,
                                  const int* __restrict__ idx2,
                                  const float* __restrict__ nrm,
                                  const int* __restrict__ remap, int E) {
    int gid = blockIdx.x * blockDim.x + threadIdx.x;
    int e = gid >> 5;
    int q = gid & 31;
    if (e >= E) return;
    float n = nrm[e];
    if (n == 0.f) return;
    int r = idx2[e];
    if (remap) r = remap[r];
    int c = idx2[E + e];
    float4 v = *(const float4*)(h + (size_t)r * 128 + q * 4);
    float* o = out + (size_t)c * 128 + q * 4;
    red_add_v4(o, v.x * n, v.y * n, v.z * n, v.w * n);
}

// ============================================================================
// Persistent edge decoder (tf32 mma):
//   out[e] = relu(relu(A[src]+B[dst]+b1) @ W2 + b2) @ W3 + b3
// Grid = 2*SMs persistent CTAs, 256 threads. W2 fragments live in REGISTERS
// (each warp owns 16 N-cols -> 64 regs). smem: t-tile only (68KB) -> 2 CTA/SM.
// ============================================================================
#define TS_STRIDE 132

__global__ __launch_bounds__(256, 2)
void decoder_persist_kernel(const float* __restrict__ Ad, const float* __restrict__ Bd,
                            const int* __restrict__ ei,
                            const float* __restrict__ b1, const float* __restrict__ W2,
                            const float* __restrict__ b2, const float* __restrict__ W3,
                            const float* __restrict__ b3, float* __restrict__ out,
                            int E, int numTiles) {
    extern __shared__ unsigned smemd[];
    unsigned* tS = smemd;                      // 128 x TS_STRIDE
    float* esum = (float*)(smemd + 128 * TS_STRIDE);  // 128 floats
    int tid = threadIdx.x;
    int warp = tid >> 5, lane = tid & 31;
    int qr = lane >> 2, qc = lane & 3;
    int nBase = warp * 16;

    // one-time: W2 fragments for this warp's 16 columns -> registers
    unsigned bf[16][2][2];
#pragma unroll
    for (int kc = 0; kc < 16; kc++) {
        int kb = kc * 8;
#pragma unroll
        for (int ncl = 0; ncl < 2; ncl++) {
            int nb = nBase + ncl * 8;
            bf[kc][ncl][0] = f2tf32(__ldg(W2 + (kb + qc) * 128 + nb + qr));
            bf[kc][ncl][1] = f2tf32(__ldg(W2 + (kb + qc + 4) * 128 + nb + qr));
        }
    }
    // one-time: epilogue constants for this thread's columns
    float bb0[2], bb1[2], w30[2], w31[2];
#pragma unroll
    for (int ncl = 0; ncl < 2; ncl++) {
        int c0 = nBase + ncl * 8 + qc * 2;
        bb0[ncl] = __ldg(b2 + c0); bb1[ncl] = __ldg(b2 + c0 + 1);
        w30[ncl] = __ldg(W3 + c0); w31[ncl] = __ldg(W3 + c0 + 1);
    }
    float b3v = __ldg(b3);

    for (int tile = blockIdx.x; tile < numTiles; tile += gridDim.x) {
        int eBase = tile * 128;
        __syncthreads();   // previous iteration fully done with tS/esum

        // phase 1: stage t = relu(A[src]+B[dst]+b1) as tf32; zero esum
        {
            int eloc = tid >> 1;
            int half = tid & 1;
            int e = eBase + eloc;
            unsigned* trow = tS + eloc * TS_STRIDE;
            if (e < E) {
                int s = ei[e], d = ei[E + e];
                const float* ap = Ad + (size_t)s * 128;
                const float* bp = Bd + (size_t)d * 128;
#pragma unroll
                for (int q = 0; q < 16; q++) {
                    int k = half * 64 + q * 4;
                    float4 a = *(const float4*)(ap + k);
                    float4 b = *(const float4*)(bp + k);
                    float4 bb = *(const float4*)(b1 + k);
                    trow[k + 0] = f2tf32(fmaxf(a.x + b.x + bb.x, 0.f));
                    trow[k + 1] = f2tf32(fmaxf(a.y + b.y + bb.y, 0.f));
                    trow[k + 2] = f2tf32(fmaxf(a.z + b.z + bb.z, 0.f));
                    trow[k + 3] = f2tf32(fmaxf(a.w + b.w + bb.w, 0.f));
                }
            } else {
#pragma unroll
                for (int q = 0; q < 16; q++) {
                    int k = half * 64 + q * 4;
                    trow[k] = 0u; trow[k + 1] = 0u; trow[k + 2] = 0u; trow[k + 3] = 0u;
                }
            }
            if (tid < 128) esum[tid] = 0.f;
        }
        __syncthreads();

        // phase 2: per m-tile of 16 edges, all 8 warps cover their N-slice
#pragma unroll 1
        for (int m = 0; m < 8; m++) {
            int r0 = m * 16;
            float acc[2][4];
            acc[0][0] = acc[0][1] = acc[0][2] = acc[0][3] = 0.f;
            acc[1][0] = acc[1][1] = acc[1][2] = acc[1][3] = 0.f;
#pragma unroll
            for (int kc = 0; kc < 16; kc++) {
                int kb = kc * 8;
                unsigned a0 = tS[(r0 + qr) * TS_STRIDE + kb + qc];
                unsigned a1 = tS[(r0 + qr + 8) * TS_STRIDE + kb + qc];
                unsigned a2 = tS[(r0 + qr) * TS_STRIDE + kb + qc + 4];
                unsigned a3 = tS[(r0 + qr + 8) * TS_STRIDE + kb + qc + 4];
                asm volatile(
                    "mma.sync.aligned.m16n8k8.row.col.f32.tf32.tf32.f32 "
                    "{%0,%1,%2,%3}, {%4,%5,%6,%7}, {%8,%9}, {%0,%1,%2,%3};"
                    : "+f"(acc[0][0]), "+f"(acc[0][1]), "+f"(acc[0][2]), "+f"(acc[0][3])
                    : "r"(a0), "r"(a1), "r"(a2), "r"(a3), "r"(bf[kc][0][0]), "r"(bf[kc][0][1]));
                asm volatile(
                    "mma.sync.aligned.m16n8k8.row.col.f32.tf32.tf32.f32 "
                    "{%0,%1,%2,%3}, {%4,%5,%6,%7}, {%8,%9}, {%0,%1,%2,%3};"
                    : "+f"(acc[1][0]), "+f"(acc[1][1]), "+f"(acc[1][2]), "+f"(acc[1][3])
                    : "r"(a0), "r"(a1), "r"(a2), "r"(a3), "r"(bf[kc][1][0]), "r"(bf[kc][1][1]));
            }
            float e0 = 0.f, e1 = 0.f;
#pragma unroll
            for (int ncl = 0; ncl < 2; ncl++) {
                e0 += fmaxf(acc[ncl][0] + bb0[ncl], 0.f) * w30[ncl]
                    + fmaxf(acc[ncl][1] + bb1[ncl], 0.f) * w31[ncl];
                e1 += fmaxf(acc[ncl][2] + bb0[ncl], 0.f) * w30[ncl]
                    + fmaxf(acc[ncl][3] + bb1[ncl], 0.f) * w31[ncl];
            }
            e0 += __shfl_xor_sync(0xffffffffu, e0, 1);
            e0 += __shfl_xor_sync(0xffffffffu, e0, 2);
            e1 += __shfl_xor_sync(0xffffffffu, e1, 1);
            e1 += __shfl_xor_sync(0xffffffffu, e1, 2);
            if (qc == 0) {
                atomicAdd(&esum[r0 + qr], e0);
                atomicAdd(&esum[r0 + qr + 8], e1);
            }
        }
        __syncthreads();

        if (tid < 128) {
            int e = eBase + tid;
            if (e < E) out[e] = esum[tid] + b3v;
        }
    }
}

extern "C" void kernel_launch(void* const* d_in, const int* in_sizes, int n_in,
                              void* d_out, int out_size) {
    const int* node_ids = (const int*)d_in[0];
    const int* ei       = (const int*)d_in[1];
    const int* nei      = (const int*)d_in[2];
    const float* eattr  = (const float*)d_in[3];
    const float* emb    = (const float*)d_in[4];
    const float* W_in   = (const float*)d_in[5];
    const float* b_in   = (const float*)d_in[6];
    const float* W_out  = (const float*)d_in[7];
    const float* b_out  = (const float*)d_in[8];
    const float* W1     = (const float*)d_in[9];
    const float* b1     = (const float*)d_in[10];
    const float* W2     = (const float*)d_in[11];
    const float* b2     = (const float*)d_in[12];
    const float* W3     = (const float*)d_in[13];
    const float* b3     = (const float*)d_in[14];
    int N = in_sizes[0];
    int E = in_sizes[3];
    float* out = (float*)d_out;

    float *deg1, *deg2, *n1, *n2, *agg1, *x1, *h2, *x2, *Ad, *Bd;
    cudaGetSymbolAddress((void**)&deg1, g_deg1);
    cudaGetSymbolAddress((void**)&deg2, g_deg2);
    cudaGetSymbolAddress((void**)&n1, g_norm1);
    cudaGetSymbolAddress((void**)&n2, g_norm2);
    cudaGetSymbolAddress((void**)&agg1, g_agg1);
    cudaGetSymbolAddress((void**)&x1, g_x1);
    cudaGetSymbolAddress((void**)&h2, g_h2);
    cudaGetSymbolAddress((void**)&x2, g_x2);
    cudaGetSymbolAddress((void**)&Ad, g_Adec);
    cudaGetSymbolAddress((void**)&Bd, g_Bdec);

    const int T = 256;
    int nDeg4 = (N + 3) / 4;
    int nX4 = N * 32;
    // launch #1: fused zero
    zero_all_kernel<<<6400, T>>>((float4*)deg1, (float4*)deg2, (float4*)agg1, (float4*)x2,
                                 nDeg4, nX4);
    // #2..#4
    deg_kernel<<<(E + T - 1) / T, T>>>(ei + E, eattr, nei + E, E);
    dinv_kernel<<<(N + T - 1) / T, T>>>(N);
    norm_kernel<<<(E + T - 1) / T, T>>>(ei, nei, eattr, E);

    int mBlocks = (N + 127) / 128;
    int smem_split = (128 * AS_STRIDE * 2 + 32 * WS_STRIDE * 2) * 4;
    int smem_plain = (128 * AS_STRIDE + 32 * WS_STRIDE) * 4;
    cudaFuncSetAttribute((const void*)gemm_tf32_kernel<1, 0>, cudaFuncAttributeMaxDynamicSharedMemorySize, smem_split);
    cudaFuncSetAttribute((const void*)gemm_tf32_kernel<0, 1>, cudaFuncAttributeMaxDynamicSharedMemorySize, smem_plain);

    // #5: conv1 scatter (linearity: aggregate in 128-dim emb space first)
    {
        long tot = (long)E * 32;
        scatter128_kernel<<<(int)((tot + T - 1) / T), T>>>(emb, agg1, ei, n1, node_ids, E);
    }
    // #6 (ncu capture target): conv1 GEMM, fused bias+elu
    gemm_tf32_kernel<1, 0><<<dim3(2, mBlocks), 256, smem_split>>>(agg1, W_in, x1, N, 128, 256, b_in, 1, nullptr);

    // conv2
    gemm_tf32_kernel<1, 0><<<dim3(1, mBlocks), 256, smem_split>>>(x1, W_out, h2, N, 256, 128, nullptr, 0, nullptr);
    {
        long tot = (long)E * 32;
        scatter128_kernel<<<(int)((tot + T - 1) / T), T>>>(h2, x2, nei, n2, nullptr, E);
    }

    // decoder pre-GEMMs with fused elu(x2 + b_out) on A staging
    gemm_tf32_kernel<0, 1><<<dim3(1, mBlocks), 256, smem_plain>>>(x2, W1, Ad, N, 128, 128, nullptr, 0, b_out);
    gemm_tf32_kernel<0, 1><<<dim3(1, mBlocks), 256, smem_plain>>>(x2, W1 + 128 * 128, Bd, N, 128, 128, nullptr, 0, b_out);

    // persistent edge decoder
    int numTiles = (E + 127) / 128;
    int smem_dec = 128 * TS_STRIDE * 4 + 128 * 4;
    cudaFuncSetAttribute(decoder_persist_kernel, cudaFuncAttributeMaxDynamicSharedMemorySize, smem_dec);
    int grid_dec = 2 * 148;
    if (grid_dec > numTiles) grid_dec = numTiles;
    decoder_persist_kernel<<<grid_dec, 256, smem_dec>>>(Ad, Bd, ei, b1, W2, b2, W3, b3, out, E, numTiles);
}

// round 5
// speedup vs baseline: 2.0498x; 1.0641x over previous
#include <cuda_runtime.h>
#include <math.h>

#define MAXN 50000
#define MAXE 800000

// ---- scratch (device globals; no allocation allowed) ----
__device__ float g_deg1[MAXN];          // weighted in-degree (conv1)
__device__ int   g_cnt1[MAXN];          // in-count (conv1 CSR)
__device__ int   g_deg2[MAXN];          // in-count (conv2, also its degree)
__device__ int   g_off1[MAXN + 1];
__device__ int   g_off2[MAXN + 1];
__device__ int   g_cur1[MAXN];
__device__ int   g_cur2[MAXN];
__device__ int   g_rowp1[MAXE];
__device__ int   g_rowp2[MAXE];
__device__ float g_nrmp1[MAXE];
__device__ float g_nrmp2[MAXE];
__device__ float g_agg1[(size_t)MAXN * 128];
__device__ float g_x1[(size_t)MAXN * 256];
__device__ float g_h2[(size_t)MAXN * 128];
__device__ float g_x2[(size_t)MAXN * 128];
__device__ float g_Adec[(size_t)MAXN * 128];
__device__ float g_Bdec[(size_t)MAXN * 128];

__device__ __forceinline__ unsigned f2tf32(float x) {
    unsigned u;
    asm("cvt.rna.tf32.f32 %0, %1;" : "=r"(u) : "f"(x));
    return u;
}

// ---- zero small per-node arrays ----
__global__ void zero_init_kernel(int N) {
    int i = blockIdx.x * blockDim.x + threadIdx.x;
    if (i < N) {
        g_deg1[i] = 0.f;
        g_cnt1[i] = 0;
        g_deg2[i] = 0;
        g_cur1[i] = 0;
        g_cur2[i] = 0;
    }
}

// ---- degree + count accumulation ----
__global__ void deg_cnt_kernel(const int* __restrict__ ei, const float* __restrict__ w,
                               const int* __restrict__ nei, int E) {
    int e = blockIdx.x * blockDim.x + threadIdx.x;
    if (e < E) {
        int c1 = ei[E + e];
        atomicAdd(&g_deg1[c1], w[e]);
        atomicAdd(&g_cnt1[c1], 1);
        atomicAdd(&g_deg2[nei[E + e]], 1);
    }
}

// ---- single-block exclusive scan of both count arrays -> offsets ----
__global__ __launch_bounds__(1024, 1)
void scan2_kernel(int N, int E) {
    __shared__ int warpTot[32];
    int tid = threadIdx.x;
    int lane = tid & 31, w = tid >> 5;
    int chunk = (N + 1023) / 1024;
    int beg = tid * chunk;
    int end = beg + chunk; if (end > N) end = N;
#pragma unroll 1
    for (int a = 0; a < 2; a++) {
        const int* c = a ? g_deg2 : g_cnt1;
        int* o = a ? g_off2 : g_off1;
        __syncthreads();
        int t = 0;
        for (int i = beg; i < end; i++) t += c[i];
        int v = t;
#pragma unroll
        for (int d = 1; d < 32; d <<= 1) {
            int u = __shfl_up_sync(0xffffffffu, v, d);
            if (lane >= d) v += u;
        }
        if (lane == 31) warpTot[w] = v;
        __syncthreads();
        if (w == 0) {
            int x = warpTot[lane];
#pragma unroll
            for (int d = 1; d < 32; d <<= 1) {
                int u = __shfl_up_sync(0xffffffffu, x, d);
                if (lane >= d) x += u;
            }
            warpTot[lane] = x;
        }
        __syncthreads();
        int run = v - t + (w > 0 ? warpTot[w - 1] : 0);
        for (int i = beg; i < end; i++) { o[i] = run; run += c[i]; }
    }
    if (tid == 0) { g_off1[N] = E; g_off2[N] = E; }
}

// ---- fill CSR entries with (row, norm) ; norms computed inline ----
__global__ void fill_kernel(const int* __restrict__ ei, const int* __restrict__ nei,
                            const float* __restrict__ w, const int* __restrict__ node_ids,
                            int E) {
    int e = blockIdx.x * blockDim.x + threadIdx.x;
    if (e >= E) return;
    {
        int r = ei[e], c = ei[E + e];
        float dr = g_deg1[r], dc = g_deg1[c];
        float nrm = (dr > 0.f ? rsqrtf(dr) : 0.f) * w[e] * (dc > 0.f ? rsqrtf(dc) : 0.f);
        int p = g_off1[c] + atomicAdd(&g_cur1[c], 1);
        g_rowp1[p] = node_ids[r];
        g_nrmp1[p] = nrm;
    }
    {
        int r = nei[e], c = nei[E + e];
        float dr = (float)g_deg2[r], dc = (float)g_deg2[c];
        float nrm = (dr > 0.f ? rsqrtf(dr) : 0.f) * (dc > 0.f ? rsqrtf(dc) : 0.f);
        int p = g_off2[c] + atomicAdd(&g_cur2[c], 1);
        g_rowp2[p] = r;
        g_nrmp2[p] = nrm;
    }
}

// ---- atomic-free gather-reduce: out[n] = sum_i h[rowp[i]] * nrmp[i] ----
// one warp per node; lane owns 4 contiguous floats (float4).
__global__ void gather_kernel(const float* __restrict__ h, float* __restrict__ out,
                              const int* __restrict__ off, const int* __restrict__ rowp,
                              const float* __restrict__ nrmp, int N) {
    int gw = (blockIdx.x * blockDim.x + threadIdx.x) >> 5;
    if (gw >= N) return;
    int lane = threadIdx.x & 31;
    int s = off[gw], t = off[gw + 1];
    float4 acc0 = make_float4(0.f, 0.f, 0.f, 0.f);
    float4 acc1 = make_float4(0.f, 0.f, 0.f, 0.f);
    int i = s;
    for (; i + 2 <= t; i += 2) {
        int r0 = __ldg(rowp + i), r1 = __ldg(rowp + i + 1);
        float n0 = __ldg(nrmp + i), n1 = __ldg(nrmp + i + 1);
        float4 v0 = *(const float4*)(h + (size_t)r0 * 128 + lane * 4);
        float4 v1 = *(const float4*)(h + (size_t)r1 * 128 + lane * 4);
        acc0.x = fmaf(v0.x, n0, acc0.x); acc0.y = fmaf(v0.y, n0, acc0.y);
        acc0.z = fmaf(v0.z, n0, acc0.z); acc0.w = fmaf(v0.w, n0, acc0.w);
        acc1.x = fmaf(v1.x, n1, acc1.x); acc1.y = fmaf(v1.y, n1, acc1.y);
        acc1.z = fmaf(v1.z, n1, acc1.z); acc1.w = fmaf(v1.w, n1, acc1.w);
    }
    if (i < t) {
        int r0 = __ldg(rowp + i);
        float n0 = __ldg(nrmp + i);
        float4 v0 = *(const float4*)(h + (size_t)r0 * 128 + lane * 4);
        acc0.x = fmaf(v0.x, n0, acc0.x); acc0.y = fmaf(v0.y, n0, acc0.y);
        acc0.z = fmaf(v0.z, n0, acc0.z); acc0.w = fmaf(v0.w, n0, acc0.w);
    }
    acc0.x += acc1.x; acc0.y += acc1.y; acc0.z += acc1.z; acc0.w += acc1.w;
    *(float4*)(out + (size_t)gw * 128 + lane * 4) = acc0;
}

// ============================================================================
// tf32 mma.sync node GEMM (unchanged from R4)
// ============================================================================
#define AS_STRIDE 36
#define WS_STRIDE 132

template <int SPLIT, int PREACT>
__global__ __launch_bounds__(256, 1)
void gemm_tf32_kernel(const float* __restrict__ A, const float* __restrict__ W,
                      float* __restrict__ C, int M, int K, int Nc,
                      const float* __restrict__ bias, int act,
                      const float* __restrict__ abias) {
    extern __shared__ unsigned sm[];
    unsigned* Ah = sm;
    unsigned* Al = Ah + 128 * AS_STRIDE;
    unsigned* Wh = Al + (SPLIT ? 128 * AS_STRIDE : 0);
    unsigned* Wl = Wh + 32 * WS_STRIDE;

    int tid = threadIdx.x;
    int warp = tid >> 5, lane = tid & 31;
    int qr = lane >> 2, qc = lane & 3;
    int m0 = blockIdx.y * 128;
    int n0 = blockIdx.x * 128;
    int r0 = warp * 16;

    float acc[16][4];
#pragma unroll
    for (int n = 0; n < 16; n++)
#pragma unroll
        for (int j = 0; j < 4; j++) acc[n][j] = 0.f;

    for (int kt = 0; kt < K; kt += 32) {
#pragma unroll
        for (int i = 0; i < 4; i++) {
            int idx4 = tid + i * 256;
            int row = idx4 >> 3;
            int col = (idx4 & 7) << 2;
            float4 v = make_float4(0.f, 0.f, 0.f, 0.f);
            if (m0 + row < M) v = *(const float4*)(A + (size_t)(m0 + row) * K + kt + col);
            if (PREACT) {
                float4 ab = *(const float4*)(abias + kt + col);
                v.x += ab.x; v.y += ab.y; v.z += ab.z; v.w += ab.w;
                v.x = v.x > 0.f ? v.x : expm1f(v.x);
                v.y = v.y > 0.f ? v.y : expm1f(v.y);
                v.z = v.z > 0.f ? v.z : expm1f(v.z);
                v.w = v.w > 0.f ? v.w : expm1f(v.w);
            }
            unsigned* dh = Ah + row * AS_STRIDE + col;
            unsigned h0 = f2tf32(v.x), h1 = f2tf32(v.y), h2_ = f2tf32(v.z), h3 = f2tf32(v.w);
            dh[0] = h0; dh[1] = h1; dh[2] = h2_; dh[3] = h3;
            if (SPLIT) {
                unsigned* dl = Al + row * AS_STRIDE + col;
                dl[0] = f2tf32(v.x - __uint_as_float(h0));
                dl[1] = f2tf32(v.y - __uint_as_float(h1));
                dl[2] = f2tf32(v.z - __uint_as_float(h2_));
                dl[3] = f2tf32(v.w - __uint_as_float(h3));
            }
        }
#pragma unroll
        for (int i = 0; i < 4; i++) {
            int idx4 = tid + i * 256;
            int row = idx4 >> 5;
            int col = (idx4 & 31) << 2;
            float4 v = *(const float4*)(W + (size_t)(kt + row) * Nc + n0 + col);
            unsigned* dh = Wh + row * WS_STRIDE + col;
            unsigned h0 = f2tf32(v.x), h1 = f2tf32(v.y), h2_ = f2tf32(v.z), h3 = f2tf32(v.w);
            dh[0] = h0; dh[1] = h1; dh[2] = h2_; dh[3] = h3;
            if (SPLIT) {
                unsigned* dl = Wl + row * WS_STRIDE + col;
                dl[0] = f2tf32(v.x - __uint_as_float(h0));
                dl[1] = f2tf32(v.y - __uint_as_float(h1));
                dl[2] = f2tf32(v.z - __uint_as_float(h2_));
                dl[3] = f2tf32(v.w - __uint_as_float(h3));
            }
        }
        __syncthreads();

#pragma unroll
        for (int kk = 0; kk < 4; kk++) {
            int kb = kk * 8;
            unsigned ah0 = Ah[(r0 + qr) * AS_STRIDE + kb + qc];
            unsigned ah1 = Ah[(r0 + qr + 8) * AS_STRIDE + kb + qc];
            unsigned ah2 = Ah[(r0 + qr) * AS_STRIDE + kb + qc + 4];
            unsigned ah3 = Ah[(r0 + qr + 8) * AS_STRIDE + kb + qc + 4];
            unsigned al0, al1, al2, al3;
            if (SPLIT) {
                al0 = Al[(r0 + qr) * AS_STRIDE + kb + qc];
                al1 = Al[(r0 + qr + 8) * AS_STRIDE + kb + qc];
                al2 = Al[(r0 + qr) * AS_STRIDE + kb + qc + 4];
                al3 = Al[(r0 + qr + 8) * AS_STRIDE + kb + qc + 4];
            }
#pragma unroll
            for (int nc = 0; nc < 16; nc++) {
                int nb = nc * 8;
                unsigned bh0 = Wh[(kb + qc) * WS_STRIDE + nb + qr];
                unsigned bh1 = Wh[(kb + qc + 4) * WS_STRIDE + nb + qr];
                asm volatile(
                    "mma.sync.aligned.m16n8k8.row.col.f32.tf32.tf32.f32 "
                    "{%0,%1,%2,%3}, {%4,%5,%6,%7}, {%8,%9}, {%0,%1,%2,%3};"
                    : "+f"(acc[nc][0]), "+f"(acc[nc][1]), "+f"(acc[nc][2]), "+f"(acc[nc][3])
                    : "r"(ah0), "r"(ah1), "r"(ah2), "r"(ah3), "r"(bh0), "r"(bh1));
                if (SPLIT) {
                    unsigned bl0 = Wl[(kb + qc) * WS_STRIDE + nb + qr];
                    unsigned bl1 = Wl[(kb + qc + 4) * WS_STRIDE + nb + qr];
                    asm volatile(
                        "mma.sync.aligned.m16n8k8.row.col.f32.tf32.tf32.f32 "
                        "{%0,%1,%2,%3}, {%4,%5,%6,%7}, {%8,%9}, {%0,%1,%2,%3};"
                        : "+f"(acc[nc][0]), "+f"(acc[nc][1]), "+f"(acc[nc][2]), "+f"(acc[nc][3])
                        : "r"(ah0), "r"(ah1), "r"(ah2), "r"(ah3), "r"(bl0), "r"(bl1));
                    asm volatile(
                        "mma.sync.aligned.m16n8k8.row.col.f32.tf32.tf32.f32 "
                        "{%0,%1,%2,%3}, {%4,%5,%6,%7}, {%8,%9}, {%0,%1,%2,%3};"
                        : "+f"(acc[nc][0]), "+f"(acc[nc][1]), "+f"(acc[nc][2]), "+f"(acc[nc][3])
                        : "r"(al0), "r"(al1), "r"(al2), "r"(al3), "r"(bh0), "r"(bh1));
                }
            }
        }
        __syncthreads();
    }

    int row0 = m0 + r0 + qr;
    int row1 = row0 + 8;
#pragma unroll
    for (int nc = 0; nc < 16; nc++) {
        int c0 = n0 + nc * 8 + qc * 2;
        float bz0 = 0.f, bz1 = 0.f;
        if (bias) { bz0 = __ldg(bias + c0); bz1 = __ldg(bias + c0 + 1); }
        float u0 = acc[nc][0] + bz0, u1 = acc[nc][1] + bz1;
        float u2 = acc[nc][2] + bz0, u3 = acc[nc][3] + bz1;
        if (act) {
            u0 = u0 > 0.f ? u0 : expm1f(u0);
            u1 = u1 > 0.f ? u1 : expm1f(u1);
            u2 = u2 > 0.f ? u2 : expm1f(u2);
            u3 = u3 > 0.f ? u3 : expm1f(u3);
        }
        if (row0 < M) *(float2*)(C + (size_t)row0 * Nc + c0) = make_float2(u0, u1);
        if (row1 < M) *(float2*)(C + (size_t)row1 * Nc + c0) = make_float2(u2, u3);
    }
}

// ============================================================================
// Persistent edge decoder (tf32 mma, W2 fragments in registers) — from R4
// ============================================================================
#define TS_STRIDE 132

__global__ __launch_bounds__(256, 2)
void decoder_persist_kernel(const float* __restrict__ Ad, const float* __restrict__ Bd,
                            const int* __restrict__ ei,
                            const float* __restrict__ b1, const float* __restrict__ W2,
                            const float* __restrict__ b2, const float* __restrict__ W3,
                            const float* __restrict__ b3, float* __restrict__ out,
                            int E, int numTiles) {
    extern __shared__ unsigned smemd[];
    unsigned* tS = smemd;
    float* esum = (float*)(smemd + 128 * TS_STRIDE);
    int tid = threadIdx.x;
    int warp = tid >> 5, lane = tid & 31;
    int qr = lane >> 2, qc = lane & 3;
    int nBase = warp * 16;

    unsigned bf[16][2][2];
#pragma unroll
    for (int kc = 0; kc < 16; kc++) {
        int kb = kc * 8;
#pragma unroll
        for (int ncl = 0; ncl < 2; ncl++) {
            int nb = nBase + ncl * 8;
            bf[kc][ncl][0] = f2tf32(__ldg(W2 + (kb + qc) * 128 + nb + qr));
            bf[kc][ncl][1] = f2tf32(__ldg(W2 + (kb + qc + 4) * 128 + nb + qr));
        }
    }
    float bb0[2], bb1[2], w30[2], w31[2];
#pragma unroll
    for (int ncl = 0; ncl < 2; ncl++) {
        int c0 = nBase + ncl * 8 + qc * 2;
        bb0[ncl] = __ldg(b2 + c0); bb1[ncl] = __ldg(b2 + c0 + 1);
        w30[ncl] = __ldg(W3 + c0); w31[ncl] = __ldg(W3 + c0 + 1);
    }
    float b3v = __ldg(b3);

    for (int tile = blockIdx.x; tile < numTiles; tile += gridDim.x) {
        int eBase = tile * 128;
        __syncthreads();

        {
            int eloc = tid >> 1;
            int half = tid & 1;
            int e = eBase + eloc;
            unsigned* trow = tS + eloc * TS_STRIDE;
            if (e < E) {
                int s = ei[e], d = ei[E + e];
                const float* ap = Ad + (size_t)s * 128;
                const float* bp = Bd + (size_t)d * 128;
#pragma unroll
                for (int q = 0; q < 16; q++) {
                    int k = half * 64 + q * 4;
                    float4 a = *(const float4*)(ap + k);
                    float4 b = *(const float4*)(bp + k);
                    float4 bb = *(const float4*)(b1 + k);
                    trow[k + 0] = f2tf32(fmaxf(a.x + b.x + bb.x, 0.f));
                    trow[k + 1] = f2tf32(fmaxf(a.y + b.y + bb.y, 0.f));
                    trow[k + 2] = f2tf32(fmaxf(a.z + b.z + bb.z, 0.f));
                    trow[k + 3] = f2tf32(fmaxf(a.w + b.w + bb.w, 0.f));
                }
            } else {
#pragma unroll
                for (int q = 0; q < 16; q++) {
                    int k = half * 64 + q * 4;
                    trow[k] = 0u; trow[k + 1] = 0u; trow[k + 2] = 0u; trow[k + 3] = 0u;
                }
            }
            if (tid < 128) esum[tid] = 0.f;
        }
        __syncthreads();

#pragma unroll 1
        for (int m = 0; m < 8; m++) {
            int r0 = m * 16;
            float acc[2][4];
            acc[0][0] = acc[0][1] = acc[0][2] = acc[0][3] = 0.f;
            acc[1][0] = acc[1][1] = acc[1][2] = acc[1][3] = 0.f;
#pragma unroll
            for (int kc = 0; kc < 16; kc++) {
                int kb = kc * 8;
                unsigned a0 = tS[(r0 + qr) * TS_STRIDE + kb + qc];
                unsigned a1 = tS[(r0 + qr + 8) * TS_STRIDE + kb + qc];
                unsigned a2 = tS[(r0 + qr) * TS_STRIDE + kb + qc + 4];
                unsigned a3 = tS[(r0 + qr + 8) * TS_STRIDE + kb + qc + 4];
                asm volatile(
                    "mma.sync.aligned.m16n8k8.row.col.f32.tf32.tf32.f32 "
                    "{%0,%1,%2,%3}, {%4,%5,%6,%7}, {%8,%9}, {%0,%1,%2,%3};"
                    : "+f"(acc[0][0]), "+f"(acc[0][1]), "+f"(acc[0][2]), "+f"(acc[0][3])
                    : "r"(a0), "r"(a1), "r"(a2), "r"(a3), "r"(bf[kc][0][0]), "r"(bf[kc][0][1]));
                asm volatile(
                    "mma.sync.aligned.m16n8k8.row.col.f32.tf32.tf32.f32 "
                    "{%0,%1,%2,%3}, {%4,%5,%6,%7}, {%8,%9}, {%0,%1,%2,%3};"
                    : "+f"(acc[1][0]), "+f"(acc[1][1]), "+f"(acc[1][2]), "+f"(acc[1][3])
                    : "r"(a0), "r"(a1), "r"(a2), "r"(a3), "r"(bf[kc][1][0]), "r"(bf[kc][1][1]));
            }
            float e0 = 0.f, e1 = 0.f;
#pragma unroll
            for (int ncl = 0; ncl < 2; ncl++) {
                e0 += fmaxf(acc[ncl][0] + bb0[ncl], 0.f) * w30[ncl]
                    + fmaxf(acc[ncl][1] + bb1[ncl], 0.f) * w31[ncl];
                e1 += fmaxf(acc[ncl][2] + bb0[ncl], 0.f) * w30[ncl]
                    + fmaxf(acc[ncl][3] + bb1[ncl], 0.f) * w31[ncl];
            }
            e0 += __shfl_xor_sync(0xffffffffu, e0, 1);
            e0 += __shfl_xor_sync(0xffffffffu, e0, 2);
            e1 += __shfl_xor_sync(0xffffffffu, e1, 1);
            e1 += __shfl_xor_sync(0xffffffffu, e1, 2);
            if (qc == 0) {
                atomicAdd(&esum[r0 + qr], e0);
                atomicAdd(&esum[r0 + qr + 8], e1);
            }
        }
        __syncthreads();

        if (tid < 128) {
            int e = eBase + tid;
            if (e < E) out[e] = esum[tid] + b3v;
        }
    }
}

extern "C" void kernel_launch(void* const* d_in, const int* in_sizes, int n_in,
                              void* d_out, int out_size) {
    const int* node_ids = (const int*)d_in[0];
    const int* ei       = (const int*)d_in[1];
    const int* nei      = (const int*)d_in[2];
    const float* eattr  = (const float*)d_in[3];
    const float* emb    = (const float*)d_in[4];
    const float* W_in   = (const float*)d_in[5];
    const float* b_in   = (const float*)d_in[6];
    const float* W_out  = (const float*)d_in[7];
    const float* b_out  = (const float*)d_in[8];
    const float* W1     = (const float*)d_in[9];
    const float* b1     = (const float*)d_in[10];
    const float* W2     = (const float*)d_in[11];
    const float* b2     = (const float*)d_in[12];
    const float* W3     = (const float*)d_in[13];
    const float* b3     = (const float*)d_in[14];
    int N = in_sizes[0];
    int E = in_sizes[3];
    float* out = (float*)d_out;

    float *agg1, *x1, *h2, *x2, *Ad, *Bd;
    int *off1, *off2, *rowp1, *rowp2;
    float *nrmp1, *nrmp2;
    cudaGetSymbolAddress((void**)&agg1, g_agg1);
    cudaGetSymbolAddress((void**)&x1, g_x1);
    cudaGetSymbolAddress((void**)&h2, g_h2);
    cudaGetSymbolAddress((void**)&x2, g_x2);
    cudaGetSymbolAddress((void**)&Ad, g_Adec);
    cudaGetSymbolAddress((void**)&Bd, g_Bdec);
    cudaGetSymbolAddress((void**)&off1, g_off1);
    cudaGetSymbolAddress((void**)&off2, g_off2);
    cudaGetSymbolAddress((void**)&rowp1, g_rowp1);
    cudaGetSymbolAddress((void**)&rowp2, g_rowp2);
    cudaGetSymbolAddress((void**)&nrmp1, g_nrmp1);
    cudaGetSymbolAddress((void**)&nrmp2, g_nrmp2);

    const int T = 256;
    // CSR build
    zero_init_kernel<<<(N + T - 1) / T, T>>>(N);
    deg_cnt_kernel<<<(E + T - 1) / T, T>>>(ei, eattr, nei, E);
    scan2_kernel<<<1, 1024>>>(N, E);
    fill_kernel<<<(E + T - 1) / T, T>>>(ei, nei, eattr, node_ids, E);

    int mBlocks = (N + 127) / 128;
    int smem_split = (128 * AS_STRIDE * 2 + 32 * WS_STRIDE * 2) * 4;
    int smem_plain = (128 * AS_STRIDE + 32 * WS_STRIDE) * 4;
    cudaFuncSetAttribute((const void*)gemm_tf32_kernel<1, 0>, cudaFuncAttributeMaxDynamicSharedMemorySize, smem_split);
    cudaFuncSetAttribute((const void*)gemm_tf32_kernel<0, 1>, cudaFuncAttributeMaxDynamicSharedMemorySize, smem_plain);

    int gatherBlocks = (N * 32 + T - 1) / T;

    // conv1: gather-aggregate emb (with node_ids remap baked into CSR), then GEMM
    gather_kernel<<<gatherBlocks, T>>>(emb, agg1, off1, rowp1, nrmp1, N);
    gemm_tf32_kernel<1, 0><<<dim3(2, mBlocks), 256, smem_split>>>(agg1, W_in, x1, N, 128, 256, b_in, 1, nullptr);

    // conv2: GEMM then gather-aggregate
    gemm_tf32_kernel<1, 0><<<dim3(1, mBlocks), 256, smem_split>>>(x1, W_out, h2, N, 256, 128, nullptr, 0, nullptr);
    gather_kernel<<<gatherBlocks, T>>>(h2, x2, off2, rowp2, nrmp2, N);

    // decoder pre-GEMMs with fused elu(x2 + b_out) on A staging
    gemm_tf32_kernel<0, 1><<<dim3(1, mBlocks), 256, smem_plain>>>(x2, W1, Ad, N, 128, 128, nullptr, 0, b_out);
    gemm_tf32_kernel<0, 1><<<dim3(1, mBlocks), 256, smem_plain>>>(x2, W1 + 128 * 128, Bd, N, 128, 128, nullptr, 0, b_out);

    // persistent edge decoder
    int numTiles = (E + 127) / 128;
    int smem_dec = 128 * TS_STRIDE * 4 + 128 * 4;
    cudaFuncSetAttribute(decoder_persist_kernel, cudaFuncAttributeMaxDynamicSharedMemorySize, smem_dec);
    int grid_dec = 2 * 148;
    if (grid_dec > numTiles) grid_dec = numTiles;
    decoder_persist_kernel<<<grid_dec, 256, smem_dec>>>(Ad, Bd, ei, b1, W2, b2, W3, b3, out, E, numTiles);
}

// round 9
// speedup vs baseline: 2.3874x; 1.1647x over previous
#include <cuda_runtime.h>
#include <cuda_fp16.h>
#include <math.h>
#include <stdint.h>

#define MAXN 50000
#define MAXE 800000

// ---- scratch (device globals; no allocation allowed) ----
__device__ float g_deg1[MAXN];
__device__ int   g_cnt1[MAXN];
__device__ int   g_deg2[MAXN];
__device__ int   g_off1[MAXN + 1];
__device__ int   g_off2[MAXN + 1];
__device__ int   g_cur1[MAXN];
__device__ int   g_cur2[MAXN];
__device__ int   g_rowp1[MAXE];
__device__ int   g_rowp2[MAXE];
__device__ float g_nrmp1[MAXE];
__device__ float g_nrmp2[MAXE];
__device__ float g_agg1[(size_t)MAXN * 128];
__device__ float g_x1[(size_t)MAXN * 256];
__device__ float g_h2[(size_t)MAXN * 128];
__device__ float g_x2[(size_t)MAXN * 128];
__device__ __half g_Adec[(size_t)MAXN * 128];
__device__ __half g_Bdec[(size_t)MAXN * 128];

__device__ __forceinline__ unsigned f2tf32(float x) {
    unsigned u;
    asm("cvt.rna.tf32.f32 %0, %1;" : "=r"(u) : "f"(x));
    return u;
}
__device__ __forceinline__ unsigned h2_bits(__half2 h) {
    unsigned u;
    *(__half2*)&u = h;
    return u;
}
__device__ __forceinline__ __half2 bits_h2(unsigned u) {
    return *(__half2*)&u;
}

// ================= CSR build =================
__global__ void zero_init_kernel(int N) {
    int i = blockIdx.x * blockDim.x + threadIdx.x;
    if (i < N) {
        g_deg1[i] = 0.f; g_cnt1[i] = 0; g_deg2[i] = 0;
        g_cur1[i] = 0; g_cur2[i] = 0;
    }
}

__global__ void deg_cnt_kernel(const int* __restrict__ ei, const float* __restrict__ w,
                               const int* __restrict__ nei, int E) {
    int e = blockIdx.x * blockDim.x + threadIdx.x;
    if (e < E) {
        int c1 = ei[E + e];
        atomicAdd(&g_deg1[c1], w[e]);
        atomicAdd(&g_cnt1[c1], 1);
        atomicAdd(&g_deg2[nei[E + e]], 1);
    }
}

__global__ __launch_bounds__(1024, 1)
void scan2_kernel(int N, int E) {
    __shared__ int warpTot[32];
    int tid = threadIdx.x;
    int lane = tid & 31, w = tid >> 5;
    int chunk = (N + 1023) / 1024;
    int beg = tid * chunk;
    int end = beg + chunk; if (end > N) end = N;
#pragma unroll 1
    for (int a = 0; a < 2; a++) {
        const int* c = a ? g_deg2 : g_cnt1;
        int* o = a ? g_off2 : g_off1;
        __syncthreads();
        int t = 0;
        for (int i = beg; i < end; i++) t += c[i];
        int v = t;
#pragma unroll
        for (int d = 1; d < 32; d <<= 1) {
            int u = __shfl_up_sync(0xffffffffu, v, d);
            if (lane >= d) v += u;
        }
        if (lane == 31) warpTot[w] = v;
        __syncthreads();
        if (w == 0) {
            int x = warpTot[lane];
#pragma unroll
            for (int d = 1; d < 32; d <<= 1) {
                int u = __shfl_up_sync(0xffffffffu, x, d);
                if (lane >= d) x += u;
            }
            warpTot[lane] = x;
        }
        __syncthreads();
        int run = v - t + (w > 0 ? warpTot[w - 1] : 0);
        for (int i = beg; i < end; i++) { o[i] = run; run += c[i]; }
    }
    if (tid == 0) { g_off1[N] = E; g_off2[N] = E; }
}

__global__ void fill_kernel(const int* __restrict__ ei, const int* __restrict__ nei,
                            const float* __restrict__ w, const int* __restrict__ node_ids,
                            int E) {
    int e = blockIdx.x * blockDim.x + threadIdx.x;
    if (e >= E) return;
    {
        int r = ei[e], c = ei[E + e];
        float dr = g_deg1[r], dc = g_deg1[c];
        float nrm = (dr > 0.f ? rsqrtf(dr) : 0.f) * w[e] * (dc > 0.f ? rsqrtf(dc) : 0.f);
        int p = g_off1[c] + atomicAdd(&g_cur1[c], 1);
        g_rowp1[p] = node_ids[r];
        g_nrmp1[p] = nrm;
    }
    {
        int r = nei[e], c = nei[E + e];
        float dr = (float)g_deg2[r], dc = (float)g_deg2[c];
        float nrm = (dr > 0.f ? rsqrtf(dr) : 0.f) * (dc > 0.f ? rsqrtf(dc) : 0.f);
        int p = g_off2[c] + atomicAdd(&g_cur2[c], 1);
        g_rowp2[p] = r;
        g_nrmp2[p] = nrm;
    }
}

__global__ void gather_kernel(const float* __restrict__ h, float* __restrict__ out,
                              const int* __restrict__ off, const int* __restrict__ rowp,
                              const float* __restrict__ nrmp, int N) {
    int gw = (blockIdx.x * blockDim.x + threadIdx.x) >> 5;
    if (gw >= N) return;
    int lane = threadIdx.x & 31;
    int s = off[gw], t = off[gw + 1];
    float4 acc0 = make_float4(0.f, 0.f, 0.f, 0.f);
    float4 acc1 = make_float4(0.f, 0.f, 0.f, 0.f);
    int i = s;
    for (; i + 2 <= t; i += 2) {
        int r0 = __ldg(rowp + i), r1 = __ldg(rowp + i + 1);
        float n0 = __ldg(nrmp + i), n1 = __ldg(nrmp + i + 1);
        float4 v0 = *(const float4*)(h + (size_t)r0 * 128 + lane * 4);
        float4 v1 = *(const float4*)(h + (size_t)r1 * 128 + lane * 4);
        acc0.x = fmaf(v0.x, n0, acc0.x); acc0.y = fmaf(v0.y, n0, acc0.y);
        acc0.z = fmaf(v0.z, n0, acc0.z); acc0.w = fmaf(v0.w, n0, acc0.w);
        acc1.x = fmaf(v1.x, n1, acc1.x); acc1.y = fmaf(v1.y, n1, acc1.y);
        acc1.z = fmaf(v1.z, n1, acc1.z); acc1.w = fmaf(v1.w, n1, acc1.w);
    }
    if (i < t) {
        int r0 = __ldg(rowp + i);
        float n0 = __ldg(nrmp + i);
        float4 v0 = *(const float4*)(h + (size_t)r0 * 128 + lane * 4);
        acc0.x = fmaf(v0.x, n0, acc0.x); acc0.y = fmaf(v0.y, n0, acc0.y);
        acc0.z = fmaf(v0.z, n0, acc0.z); acc0.w = fmaf(v0.w, n0, acc0.w);
    }
    acc0.x += acc1.x; acc0.y += acc1.y; acc0.z += acc1.z; acc0.w += acc1.w;
    *(float4*)(out + (size_t)gw * 128 + lane * 4) = acc0;
}

// ================= tf32 mma.sync node GEMM =================
#define AS_STRIDE 36
#define WS_STRIDE 132

template <int SPLIT, int PREACT, int DUAL, int OUTH>
__global__ __launch_bounds__(256, 1)
void gemm_tf32_kernel(const float* __restrict__ A, const float* __restrict__ W,
                      void* __restrict__ C, int M, int K, int Nc,
                      const float* __restrict__ bias, int act,
                      const float* __restrict__ abias,
                      const float* __restrict__ Wb, void* __restrict__ Cb) {
    extern __shared__ unsigned sm[];
    unsigned* Ah = sm;
    unsigned* Al = Ah + 128 * AS_STRIDE;
    unsigned* Wh = Al + (SPLIT ? 128 * AS_STRIDE : 0);
    unsigned* Wl = Wh + 32 * WS_STRIDE;

    int tid = threadIdx.x;
    int warp = tid >> 5, lane = tid & 31;
    int qr = lane >> 2, qc = lane & 3;
    int m0 = blockIdx.y * 128;
    const float* Wp = W;
    void* Cp = C;
    int n0 = blockIdx.x * 128;
    if (DUAL) {
        if (blockIdx.x) { Wp = Wb; Cp = Cb; }
        n0 = 0;
    }
    int r0 = warp * 16;

    float acc[16][4];
#pragma unroll
    for (int n = 0; n < 16; n++)
#pragma unroll
        for (int j = 0; j < 4; j++) acc[n][j] = 0.f;

    for (int kt = 0; kt < K; kt += 32) {
#pragma unroll
        for (int i = 0; i < 4; i++) {
            int idx4 = tid + i * 256;
            int row = idx4 >> 3;
            int col = (idx4 & 7) << 2;
            float4 v = make_float4(0.f, 0.f, 0.f, 0.f);
            if (m0 + row < M) v = *(const float4*)(A + (size_t)(m0 + row) * K + kt + col);
            if (PREACT) {
                float4 ab = *(const float4*)(abias + kt + col);
                v.x += ab.x; v.y += ab.y; v.z += ab.z; v.w += ab.w;
                v.x = v.x > 0.f ? v.x : expm1f(v.x);
                v.y = v.y > 0.f ? v.y : expm1f(v.y);
                v.z = v.z > 0.f ? v.z : expm1f(v.z);
                v.w = v.w > 0.f ? v.w : expm1f(v.w);
            }
            unsigned* dh = Ah + row * AS_STRIDE + col;
            unsigned h0 = f2tf32(v.x), h1 = f2tf32(v.y), h2_ = f2tf32(v.z), h3 = f2tf32(v.w);
            dh[0] = h0; dh[1] = h1; dh[2] = h2_; dh[3] = h3;
            if (SPLIT) {
                unsigned* dl = Al + row * AS_STRIDE + col;
                dl[0] = f2tf32(v.x - __uint_as_float(h0));
                dl[1] = f2tf32(v.y - __uint_as_float(h1));
                dl[2] = f2tf32(v.z - __uint_as_float(h2_));
                dl[3] = f2tf32(v.w - __uint_as_float(h3));
            }
        }
#pragma unroll
        for (int i = 0; i < 4; i++) {
            int idx4 = tid + i * 256;
            int row = idx4 >> 5;
            int col = (idx4 & 31) << 2;
            float4 v = *(const float4*)(Wp + (size_t)(kt + row) * Nc + n0 + col);
            unsigned* dh = Wh + row * WS_STRIDE + col;
            unsigned h0 = f2tf32(v.x), h1 = f2tf32(v.y), h2_ = f2tf32(v.z), h3 = f2tf32(v.w);
            dh[0] = h0; dh[1] = h1; dh[2] = h2_; dh[3] = h3;
            if (SPLIT) {
                unsigned* dl = Wl + row * WS_STRIDE + col;
                dl[0] = f2tf32(v.x - __uint_as_float(h0));
                dl[1] = f2tf32(v.y - __uint_as_float(h1));
                dl[2] = f2tf32(v.z - __uint_as_float(h2_));
                dl[3] = f2tf32(v.w - __uint_as_float(h3));
            }
        }
        __syncthreads();

#pragma unroll
        for (int kk = 0; kk < 4; kk++) {
            int kb = kk * 8;
            unsigned ah0 = Ah[(r0 + qr) * AS_STRIDE + kb + qc];
            unsigned ah1 = Ah[(r0 + qr + 8) * AS_STRIDE + kb + qc];
            unsigned ah2 = Ah[(r0 + qr) * AS_STRIDE + kb + qc + 4];
            unsigned ah3 = Ah[(r0 + qr + 8) * AS_STRIDE + kb + qc + 4];
            unsigned al0, al1, al2, al3;
            if (SPLIT) {
                al0 = Al[(r0 + qr) * AS_STRIDE + kb + qc];
                al1 = Al[(r0 + qr + 8) * AS_STRIDE + kb + qc];
                al2 = Al[(r0 + qr) * AS_STRIDE + kb + qc + 4];
                al3 = Al[(r0 + qr + 8) * AS_STRIDE + kb + qc + 4];
            }
#pragma unroll
            for (int nc = 0; nc < 16; nc++) {
                int nb = nc * 8;
                unsigned bh0 = Wh[(kb + qc) * WS_STRIDE + nb + qr];
                unsigned bh1 = Wh[(kb + qc + 4) * WS_STRIDE + nb + qr];
                asm volatile(
                    "mma.sync.aligned.m16n8k8.row.col.f32.tf32.tf32.f32 "
                    "{%0,%1,%2,%3}, {%4,%5,%6,%7}, {%8,%9}, {%0,%1,%2,%3};"
                    : "+f"(acc[nc][0]), "+f"(acc[nc][1]), "+f"(acc[nc][2]), "+f"(acc[nc][3])
                    : "r"(ah0), "r"(ah1), "r"(ah2), "r"(ah3), "r"(bh0), "r"(bh1));
                if (SPLIT) {
                    unsigned bl0 = Wl[(kb + qc) * WS_STRIDE + nb + qr];
                    unsigned bl1 = Wl[(kb + qc + 4) * WS_STRIDE + nb + qr];
                    asm volatile(
                        "mma.sync.aligned.m16n8k8.row.col.f32.tf32.tf32.f32 "
                        "{%0,%1,%2,%3}, {%4,%5,%6,%7}, {%8,%9}, {%0,%1,%2,%3};"
                        : "+f"(acc[nc][0]), "+f"(acc[nc][1]), "+f"(acc[nc][2]), "+f"(acc[nc][3])
                        : "r"(ah0), "r"(ah1), "r"(ah2), "r"(ah3), "r"(bl0), "r"(bl1));
                    asm volatile(
                        "mma.sync.aligned.m16n8k8.row.col.f32.tf32.tf32.f32 "
                        "{%0,%1,%2,%3}, {%4,%5,%6,%7}, {%8,%9}, {%0,%1,%2,%3};"
                        : "+f"(acc[nc][0]), "+f"(acc[nc][1]), "+f"(acc[nc][2]), "+f"(acc[nc][3])
                        : "r"(al0), "r"(al1), "r"(al2), "r"(al3), "r"(bh0), "r"(bh1));
                }
            }
        }
        __syncthreads();
    }

    int row0 = m0 + r0 + qr;
    int row1 = row0 + 8;
#pragma unroll
    for (int nc = 0; nc < 16; nc++) {
        int c0 = n0 + nc * 8 + qc * 2;
        float bz0 = 0.f, bz1 = 0.f;
        if (bias) { bz0 = __ldg(bias + c0); bz1 = __ldg(bias + c0 + 1); }
        float u0 = acc[nc][0] + bz0, u1 = acc[nc][1] + bz1;
        float u2 = acc[nc][2] + bz0, u3 = acc[nc][3] + bz1;
        if (act) {
            u0 = u0 > 0.f ? u0 : expm1f(u0);
            u1 = u1 > 0.f ? u1 : expm1f(u1);
            u2 = u2 > 0.f ? u2 : expm1f(u2);
            u3 = u3 > 0.f ? u3 : expm1f(u3);
        }
        if (OUTH) {
            if (row0 < M) *(__half2*)((__half*)Cp + (size_t)row0 * Nc + c0) = __floats2half2_rn(u0, u1);
            if (row1 < M) *(__half2*)((__half*)Cp + (size_t)row1 * Nc + c0) = __floats2half2_rn(u2, u3);
        } else {
            if (row0 < M) *(float2*)((float*)Cp + (size_t)row0 * Nc + c0) = make_float2(u0, u1);
            if (row1 < M) *(float2*)((float*)Cp + (size_t)row1 * Nc + c0) = make_float2(u2, u3);
        }
    }
}

// ============================================================================
// Persistent fp16 edge decoder (mma.sync m16n8k16.f16, fp32 accum)
// ============================================================================
#define TS_HW 68   // u32 words per t row (136 halves incl. padding)

__global__ __launch_bounds__(256, 3)
void decoder_fp16_kernel(const __half* __restrict__ Ad, const __half* __restrict__ Bd,
                         const int* __restrict__ ei,
                         const float* __restrict__ b1, const float* __restrict__ W2,
                         const float* __restrict__ b2, const float* __restrict__ W3,
                         const float* __restrict__ b3, float* __restrict__ out,
                         int E, int numTiles) {
    extern __shared__ unsigned smemd[];
    unsigned* tS = smemd;                           // 128 x TS_HW u32
    float* b1s = (float*)(smemd + 128 * TS_HW);     // 128 floats
    float* esum = b1s + 128;                        // 128 floats
    int tid = threadIdx.x;
    int warp = tid >> 5, lane = tid & 31;
    int qr = lane >> 2, qc = lane & 3;
    int nBase = warp * 16;

    // one-time: W2 fragments (fp16) for this warp's 16 N-cols, all K
    unsigned bf[8][2][2];
#pragma unroll
    for (int c = 0; c < 8; c++) {
        int kb = c * 16;
#pragma unroll
        for (int ncl = 0; ncl < 2; ncl++) {
            int n = nBase + ncl * 8 + qr;
            bf[c][ncl][0] = h2_bits(__floats2half2_rn(
                __ldg(W2 + (kb + 2 * qc) * 128 + n), __ldg(W2 + (kb + 2 * qc + 1) * 128 + n)));
            bf[c][ncl][1] = h2_bits(__floats2half2_rn(
                __ldg(W2 + (kb + 2 * qc + 8) * 128 + n), __ldg(W2 + (kb + 2 * qc + 9) * 128 + n)));
        }
    }
    float bb0[2], bb1[2], w30[2], w31[2];
#pragma unroll
    for (int ncl = 0; ncl < 2; ncl++) {
        int c0 = nBase + ncl * 8 + qc * 2;
        bb0[ncl] = __ldg(b2 + c0); bb1[ncl] = __ldg(b2 + c0 + 1);
        w30[ncl] = __ldg(W3 + c0); w31[ncl] = __ldg(W3 + c0 + 1);
    }
    float b3v = __ldg(b3);
    if (tid < 128) b1s[tid] = __ldg(b1 + tid);
    __syncthreads();

    for (int tile = blockIdx.x; tile < numTiles; tile += gridDim.x) {
        int eBase = tile * 128;
        __syncthreads();   // previous iteration done with tS/esum

        // phase 1: t = relu(A[src]+B[dst]+b1) -> fp16 smem. 2 threads/edge,
        // each thread stages 64 halves (8 x uint4 from Ad and Bd).
        {
            int eloc = tid >> 1;
            int half_ = tid & 1;
            int e = eBase + eloc;
            unsigned* trow = tS + eloc * TS_HW + half_ * 32;
            if (e < E) {
                int s = ei[e], d = ei[E + e];
                const uint4* ap = (const uint4*)(Ad + (size_t)s * 128) + half_ * 8;
                const uint4* bp = (const uint4*)(Bd + (size_t)d * 128) + half_ * 8;
#pragma unroll
                for (int j = 0; j < 8; j++) {
                    uint4 av = __ldg(ap + j);
                    uint4 bv = __ldg(bp + j);
                    const float* bb = b1s + half_ * 64 + j * 8;
                    unsigned aw[4] = {av.x, av.y, av.z, av.w};
                    unsigned bw[4] = {bv.x, bv.y, bv.z, bv.w};
#pragma unroll
                    for (int w = 0; w < 4; w++) {
                        float2 af = __half22float2(bits_h2(aw[w]));
                        float2 bf2 = __half22float2(bits_h2(bw[w]));
                        float v0 = fmaxf(af.x + bf2.x + bb[2 * w], 0.f);
                        float v1 = fmaxf(af.y + bf2.y + bb[2 * w + 1], 0.f);
                        trow[j * 4 + w] = h2_bits(__floats2half2_rn(v0, v1));
                    }
                }
            } else {
#pragma unroll
                for (int j = 0; j < 32; j++) trow[j] = 0u;
            }
            if (tid < 128) esum[tid] = 0.f;
        }
        __syncthreads();

        // phase 2: per m-tile of 16 edges; warp covers its 16 N-cols; K=128 in 8 chunks
#pragma unroll 1
        for (int m = 0; m < 8; m++) {
            int r0 = m * 16;
            float acc[2][4];
            acc[0][0] = acc[0][1] = acc[0][2] = acc[0][3] = 0.f;
            acc[1][0] = acc[1][1] = acc[1][2] = acc[1][3] = 0.f;
#pragma unroll
            for (int c = 0; c < 8; c++) {
                int wb = c * 8;
                unsigned a0 = tS[(r0 + qr) * TS_HW + wb + qc];
                unsigned a1 = tS[(r0 + qr + 8) * TS_HW + wb + qc];
                unsigned a2 = tS[(r0 + qr) * TS_HW + wb + 4 + qc];
                unsigned a3 = tS[(r0 + qr + 8) * TS_HW + wb + 4 + qc];
                asm volatile(
                    "mma.sync.aligned.m16n8k16.row.col.f32.f16.f16.f32 "
                    "{%0,%1,%2,%3}, {%4,%5,%6,%7}, {%8,%9}, {%0,%1,%2,%3};"
                    : "+f"(acc[0][0]), "+f"(acc[0][1]), "+f"(acc[0][2]), "+f"(acc[0][3])
                    : "r"(a0), "r"(a1), "r"(a2), "r"(a3), "r"(bf[c][0][0]), "r"(bf[c][0][1]));
                asm volatile(
                    "mma.sync.aligned.m16n8k16.row.col.f32.f16.f16.f32 "
                    "{%0,%1,%2,%3}, {%4,%5,%6,%7}, {%8,%9}, {%0,%1,%2,%3};"
                    : "+f"(acc[1][0]), "+f"(acc[1][1]), "+f"(acc[1][2]), "+f"(acc[1][3])
                    : "r"(a0), "r"(a1), "r"(a2), "r"(a3), "r"(bf[c][1][0]), "r"(bf[c][1][1]));
            }
            float e0 = 0.f, e1 = 0.f;
#pragma unroll
            for (int ncl = 0; ncl < 2; ncl++) {
                e0 += fmaxf(acc[ncl][0] + bb0[ncl], 0.f) * w30[ncl]
                    + fmaxf(acc[ncl][1] + bb1[ncl], 0.f) * w31[ncl];
                e1 += fmaxf(acc[ncl][2] + bb0[ncl], 0.f) * w30[ncl]
                    + fmaxf(acc[ncl][3] + bb1[ncl], 0.f) * w31[ncl];
            }
            e0 += __shfl_xor_sync(0xffffffffu, e0, 1);
            e0 += __shfl_xor_sync(0xffffffffu, e0, 2);
            e1 += __shfl_xor_sync(0xffffffffu, e1, 1);
            e1 += __shfl_xor_sync(0xffffffffu, e1, 2);
            if (qc == 0) {
                atomicAdd(&esum[r0 + qr], e0);
                atomicAdd(&esum[r0 + qr + 8], e1);
            }
        }
        __syncthreads();

        if (tid < 128) {
            int e = eBase + tid;
            if (e < E) out[e] = esum[tid] + b3v;
        }
    }
}

extern "C" void kernel_launch(void* const* d_in, const int* in_sizes, int n_in,
                              void* d_out, int out_size) {
    const int* node_ids = (const int*)d_in[0];
    const int* ei       = (const int*)d_in[1];
    const int* nei      = (const int*)d_in[2];
    const float* eattr  = (const float*)d_in[3];
    const float* emb    = (const float*)d_in[4];
    const float* W_in   = (const float*)d_in[5];
    const float* b_in   = (const float*)d_in[6];
    const float* W_out  = (const float*)d_in[7];
    const float* b_out  = (const float*)d_in[8];
    const float* W1     = (const float*)d_in[9];
    const float* b1     = (const float*)d_in[10];
    const float* W2     = (const float*)d_in[11];
    const float* b2     = (const float*)d_in[12];
    const float* W3     = (const float*)d_in[13];
    const float* b3     = (const float*)d_in[14];
    int N = in_sizes[0];
    int E = in_sizes[3];
    float* out = (float*)d_out;

    float *agg1, *x1, *h2, *x2;
    __half *Ad, *Bd;
    int *off1, *off2, *rowp1, *rowp2;
    float *nrmp1, *nrmp2;
    cudaGetSymbolAddress((void**)&agg1, g_agg1);
    cudaGetSymbolAddress((void**)&x1, g_x1);
    cudaGetSymbolAddress((void**)&h2, g_h2);
    cudaGetSymbolAddress((void**)&x2, g_x2);
    cudaGetSymbolAddress((void**)&Ad, g_Adec);
    cudaGetSymbolAddress((void**)&Bd, g_Bdec);
    cudaGetSymbolAddress((void**)&off1, g_off1);
    cudaGetSymbolAddress((void**)&off2, g_off2);
    cudaGetSymbolAddress((void**)&rowp1, g_rowp1);
    cudaGetSymbolAddress((void**)&rowp2, g_rowp2);
    cudaGetSymbolAddress((void**)&nrmp1, g_nrmp1);
    cudaGetSymbolAddress((void**)&nrmp2, g_nrmp2);

    const int T = 256;
    zero_init_kernel<<<(N + T - 1) / T, T>>>(N);
    deg_cnt_kernel<<<(E + T - 1) / T, T>>>(ei, eattr, nei, E);
    scan2_kernel<<<1, 1024>>>(N, E);
    fill_kernel<<<(E + T - 1) / T, T>>>(ei, nei, eattr, node_ids, E);

    int mBlocks = (N + 127) / 128;
    int smem_split = (128 * AS_STRIDE * 2 + 32 * WS_STRIDE * 2) * 4;
    cudaFuncSetAttribute((const void*)gemm_tf32_kernel<1, 0, 0, 0>,
                         cudaFuncAttributeMaxDynamicSharedMemorySize, smem_split);
    cudaFuncSetAttribute((const void*)gemm_tf32_kernel<1, 1, 1, 1>,
                         cudaFuncAttributeMaxDynamicSharedMemorySize, smem_split);

    int gatherBlocks = (N * 32 + T - 1) / T;

    // conv1: gather-aggregate emb, then GEMM with fused bias+elu
    gather_kernel<<<gatherBlocks, T>>>(emb, agg1, off1, rowp1, nrmp1, N);
    gemm_tf32_kernel<1, 0, 0, 0><<<dim3(2, mBlocks), 256, smem_split>>>(
        agg1, W_in, x1, N, 128, 256, b_in, 1, nullptr, nullptr, nullptr);

    // conv2: GEMM then gather-aggregate
    gemm_tf32_kernel<1, 0, 0, 0><<<dim3(1, mBlocks), 256, smem_split>>>(
        x1, W_out, h2, N, 256, 128, nullptr, 0, nullptr, nullptr, nullptr);
    gather_kernel<<<gatherBlocks, T>>>(h2, x2, off2, rowp2, nrmp2, N);

    // merged dual pre-GEMMs (hi/lo split, elu(x2+b_out) fused on A, fp16 outputs)
    gemm_tf32_kernel<1, 1, 1, 1><<<dim3(2, mBlocks), 256, smem_split>>>(
        x2, W1, Ad, N, 128, 128, nullptr, 0, b_out, W1 + 128 * 128, Bd);

    // persistent fp16 tensor-core edge decoder
    int numTiles = (E + 127) / 128;
    int smem_dec = (128 * TS_HW + 256) * 4;
    cudaFuncSetAttribute(decoder_fp16_kernel, cudaFuncAttributeMaxDynamicSharedMemorySize, smem_dec);
    int grid_dec = 3 * 148;
    if (grid_dec > numTiles) grid_dec = numTiles;
    decoder_fp16_kernel<<<grid_dec, 256, smem_dec>>>(Ad, Bd, ei, b1, W2, b2, W3, b3, out, E, numTiles);
}

// round 10
// speedup vs baseline: 2.4503x; 1.0264x over previous
#include <cuda_runtime.h>
#include <cuda_fp16.h>
#include <math.h>
#include <stdint.h>

#define MAXN 50000
#define MAXE 800000

// ---- scratch (device globals; no allocation allowed) ----
__device__ float g_deg1[MAXN];
__device__ int   g_cnt1[MAXN];
__device__ int   g_deg2[MAXN];
__device__ int   g_off1[MAXN + 1];
__device__ int   g_off2[MAXN + 1];
__device__ int   g_cur1[MAXN];
__device__ int   g_cur2[MAXN];
__device__ int2  g_pair1[MAXE];
__device__ int2  g_pair2[MAXE];
__device__ float g_agg1[(size_t)MAXN * 128];
__device__ float g_x1[(size_t)MAXN * 256];
__device__ __half g_h2h[(size_t)MAXN * 128];
__device__ float g_x2[(size_t)MAXN * 128];
__device__ __half g_Adec[(size_t)MAXN * 128];
__device__ __half g_Bdec[(size_t)MAXN * 128];

__device__ __forceinline__ unsigned f2tf32(float x) {
    unsigned u;
    asm("cvt.rna.tf32.f32 %0, %1;" : "=r"(u) : "f"(x));
    return u;
}
__device__ __forceinline__ unsigned h2_bits(__half2 h) {
    unsigned u;
    *(__half2*)&u = h;
    return u;
}
__device__ __forceinline__ __half2 bits_h2(unsigned u) {
    return *(__half2*)&u;
}
__device__ __forceinline__ uint32_t smem_u32(const void* p) {
    uint32_t a;
    asm("{ .reg .u64 t; cvta.to.shared.u64 t, %1; cvt.u32.u64 %0, t; }" : "=r"(a) : "l"(p));
    return a;
}

// ================= CSR build =================
__global__ void zero_init_kernel(int N) {
    int i = blockIdx.x * blockDim.x + threadIdx.x;
    if (i < N) {
        g_deg1[i] = 0.f; g_cnt1[i] = 0; g_deg2[i] = 0;
        g_cur1[i] = 0; g_cur2[i] = 0;
    }
}

__global__ void deg_cnt_kernel(const int* __restrict__ ei, const float* __restrict__ w,
                               const int* __restrict__ nei, int E) {
    int e = blockIdx.x * blockDim.x + threadIdx.x;
    if (e < E) {
        int c1 = ei[E + e];
        atomicAdd(&g_deg1[c1], w[e]);
        atomicAdd(&g_cnt1[c1], 1);
        atomicAdd(&g_deg2[nei[E + e]], 1);
    }
}

__global__ __launch_bounds__(1024, 1)
void scan2_kernel(int N, int E) {
    __shared__ int warpTot[32];
    int tid = threadIdx.x;
    int lane = tid & 31, w = tid >> 5;
    int chunk = (N + 1023) / 1024;
    int beg = tid * chunk;
    int end = beg + chunk; if (end > N) end = N;
#pragma unroll 1
    for (int a = 0; a < 2; a++) {
        const int* c = a ? g_deg2 : g_cnt1;
        int* o = a ? g_off2 : g_off1;
        __syncthreads();
        int t = 0;
        for (int i = beg; i < end; i++) t += c[i];
        int v = t;
#pragma unroll
        for (int d = 1; d < 32; d <<= 1) {
            int u = __shfl_up_sync(0xffffffffu, v, d);
            if (lane >= d) v += u;
        }
        if (lane == 31) warpTot[w] = v;
        __syncthreads();
        if (w == 0) {
            int x = warpTot[lane];
#pragma unroll
            for (int d = 1; d < 32; d <<= 1) {
                int u = __shfl_up_sync(0xffffffffu, x, d);
                if (lane >= d) x += u;
            }
            warpTot[lane] = x;
        }
        __syncthreads();
        int run = v - t + (w > 0 ? warpTot[w - 1] : 0);
        for (int i = beg; i < end; i++) { o[i] = run; run += c[i]; }
    }
    if (tid == 0) { g_off1[N] = E; g_off2[N] = E; }
}

__global__ void fill_kernel(const int* __restrict__ ei, const int* __restrict__ nei,
                            const float* __restrict__ w, const int* __restrict__ node_ids,
                            int E) {
    int e = blockIdx.x * blockDim.x + threadIdx.x;
    if (e >= E) return;
    {
        int r = ei[e], c = ei[E + e];
        float dr = g_deg1[r], dc = g_deg1[c];
        float nrm = (dr > 0.f ? rsqrtf(dr) : 0.f) * w[e] * (dc > 0.f ? rsqrtf(dc) : 0.f);
        int p = g_off1[c] + atomicAdd(&g_cur1[c], 1);
        g_pair1[p] = make_int2(node_ids[r], __float_as_int(nrm));
    }
    {
        int r = nei[e], c = nei[E + e];
        float dr = (float)g_deg2[r], dc = (float)g_deg2[c];
        float nrm = (dr > 0.f ? rsqrtf(dr) : 0.f) * (dc > 0.f ? rsqrtf(dc) : 0.f);
        int p = g_off2[c] + atomicAdd(&g_cur2[c], 1);
        g_pair2[p] = make_int2(r, __float_as_int(nrm));
    }
}

// ---- gather-reduce from fp32 rows: out[n] = sum_i h[pair.x] * pair.y ----
__global__ void gather_f32_kernel(const float* __restrict__ h, float* __restrict__ out,
                                  const int* __restrict__ off, const int2* __restrict__ pair,
                                  int N) {
    int gw = (blockIdx.x * blockDim.x + threadIdx.x) >> 5;
    if (gw >= N) return;
    int lane = threadIdx.x & 31;
    int s = off[gw], t = off[gw + 1];
    float4 acc0 = make_float4(0.f, 0.f, 0.f, 0.f);
    float4 acc1 = make_float4(0.f, 0.f, 0.f, 0.f);
    int i = s;
    for (; i + 2 <= t; i += 2) {
        int2 p0 = __ldg(pair + i), p1 = __ldg(pair + i + 1);
        float n0 = __int_as_float(p0.y), n1 = __int_as_float(p1.y);
        float4 v0 = *(const float4*)(h + (size_t)p0.x * 128 + lane * 4);
        float4 v1 = *(const float4*)(h + (size_t)p1.x * 128 + lane * 4);
        acc0.x = fmaf(v0.x, n0, acc0.x); acc0.y = fmaf(v0.y, n0, acc0.y);
        acc0.z = fmaf(v0.z, n0, acc0.z); acc0.w = fmaf(v0.w, n0, acc0.w);
        acc1.x = fmaf(v1.x, n1, acc1.x); acc1.y = fmaf(v1.y, n1, acc1.y);
        acc1.z = fmaf(v1.z, n1, acc1.z); acc1.w = fmaf(v1.w, n1, acc1.w);
    }
    if (i < t) {
        int2 p0 = __ldg(pair + i);
        float n0 = __int_as_float(p0.y);
        float4 v0 = *(const float4*)(h + (size_t)p0.x * 128 + lane * 4);
        acc0.x = fmaf(v0.x, n0, acc0.x); acc0.y = fmaf(v0.y, n0, acc0.y);
        acc0.z = fmaf(v0.z, n0, acc0.z); acc0.w = fmaf(v0.w, n0, acc0.w);
    }
    acc0.x += acc1.x; acc0.y += acc1.y; acc0.z += acc1.z; acc0.w += acc1.w;
    *(float4*)(out + (size_t)gw * 128 + lane * 4) = acc0;
}

// ---- gather-reduce from fp16 rows (half the read traffic) ----
__global__ void gather_f16_kernel(const __half* __restrict__ h, float* __restrict__ out,
                                  const int* __restrict__ off, const int2* __restrict__ pair,
                                  int N) {
    int gw = (blockIdx.x * blockDim.x + threadIdx.x) >> 5;
    if (gw >= N) return;
    int lane = threadIdx.x & 31;
    int s = off[gw], t = off[gw + 1];
    float4 acc0 = make_float4(0.f, 0.f, 0.f, 0.f);
    float4 acc1 = make_float4(0.f, 0.f, 0.f, 0.f);
    int i = s;
    for (; i + 2 <= t; i += 2) {
        int2 p0 = __ldg(pair + i), p1 = __ldg(pair + i + 1);
        float n0 = __int_as_float(p0.y), n1 = __int_as_float(p1.y);
        uint2 w0 = *(const uint2*)(h + (size_t)p0.x * 128 + lane * 4);
        uint2 w1 = *(const uint2*)(h + (size_t)p1.x * 128 + lane * 4);
        float2 v0a = __half22float2(bits_h2(w0.x)), v0b = __half22float2(bits_h2(w0.y));
        float2 v1a = __half22float2(bits_h2(w1.x)), v1b = __half22float2(bits_h2(w1.y));
        acc0.x = fmaf(v0a.x, n0, acc0.x); acc0.y = fmaf(v0a.y, n0, acc0.y);
        acc0.z = fmaf(v0b.x, n0, acc0.z); acc0.w = fmaf(v0b.y, n0, acc0.w);
        acc1.x = fmaf(v1a.x, n1, acc1.x); acc1.y = fmaf(v1a.y, n1, acc1.y);
        acc1.z = fmaf(v1b.x, n1, acc1.z); acc1.w = fmaf(v1b.y, n1, acc1.w);
    }
    if (i < t) {
        int2 p0 = __ldg(pair + i);
        float n0 = __int_as_float(p0.y);
        uint2 w0 = *(const uint2*)(h + (size_t)p0.x * 128 + lane * 4);
        float2 v0a = __half22float2(bits_h2(w0.x)), v0b = __half22float2(bits_h2(w0.y));
        acc0.x = fmaf(v0a.x, n0, acc0.x); acc0.y = fmaf(v0a.y, n0, acc0.y);
        acc0.z = fmaf(v0b.x, n0, acc0.z); acc0.w = fmaf(v0b.y, n0, acc0.w);
    }
    acc0.x += acc1.x; acc0.y += acc1.y; acc0.z += acc1.z; acc0.w += acc1.w;
    *(float4*)(out + (size_t)gw * 128 + lane * 4) = acc0;
}

// ================= tf32 mma.sync node GEMM =================
#define AS_STRIDE 36
#define WS_STRIDE 132

template <int SPLIT, int PREACT, int DUAL, int OUTH>
__global__ __launch_bounds__(256, 1)
void gemm_tf32_kernel(const float* __restrict__ A, const float* __restrict__ W,
                      void* __restrict__ C, int M, int K, int Nc,
                      const float* __restrict__ bias, int act,
                      const float* __restrict__ abias,
                      const float* __restrict__ Wb, void* __restrict__ Cb) {
    extern __shared__ unsigned sm[];
    unsigned* Ah = sm;
    unsigned* Al = Ah + 128 * AS_STRIDE;
    unsigned* Wh = Al + (SPLIT ? 128 * AS_STRIDE : 0);
    unsigned* Wl = Wh + 32 * WS_STRIDE;

    int tid = threadIdx.x;
    int warp = tid >> 5, lane = tid & 31;
    int qr = lane >> 2, qc = lane & 3;
    int m0 = blockIdx.y * 128;
    const float* Wp = W;
    void* Cp = C;
    int n0 = blockIdx.x * 128;
    if (DUAL) {
        if (blockIdx.x) { Wp = Wb; Cp = Cb; }
        n0 = 0;
    }
    int r0 = warp * 16;

    float acc[16][4];
#pragma unroll
    for (int n = 0; n < 16; n++)
#pragma unroll
        for (int j = 0; j < 4; j++) acc[n][j] = 0.f;

    for (int kt = 0; kt < K; kt += 32) {
#pragma unroll
        for (int i = 0; i < 4; i++) {
            int idx4 = tid + i * 256;
            int row = idx4 >> 3;
            int col = (idx4 & 7) << 2;
            float4 v = make_float4(0.f, 0.f, 0.f, 0.f);
            if (m0 + row < M) v = *(const float4*)(A + (size_t)(m0 + row) * K + kt + col);
            if (PREACT) {
                float4 ab = *(const float4*)(abias + kt + col);
                v.x += ab.x; v.y += ab.y; v.z += ab.z; v.w += ab.w;
                v.x = v.x > 0.f ? v.x : expm1f(v.x);
                v.y = v.y > 0.f ? v.y : expm1f(v.y);
                v.z = v.z > 0.f ? v.z : expm1f(v.z);
                v.w = v.w > 0.f ? v.w : expm1f(v.w);
            }
            unsigned* dh = Ah + row * AS_STRIDE + col;
            unsigned h0 = f2tf32(v.x), h1 = f2tf32(v.y), h2_ = f2tf32(v.z), h3 = f2tf32(v.w);
            dh[0] = h0; dh[1] = h1; dh[2] = h2_; dh[3] = h3;
            if (SPLIT) {
                unsigned* dl = Al + row * AS_STRIDE + col;
                dl[0] = f2tf32(v.x - __uint_as_float(h0));
                dl[1] = f2tf32(v.y - __uint_as_float(h1));
                dl[2] = f2tf32(v.z - __uint_as_float(h2_));
                dl[3] = f2tf32(v.w - __uint_as_float(h3));
            }
        }
#pragma unroll
        for (int i = 0; i < 4; i++) {
            int idx4 = tid + i * 256;
            int row = idx4 >> 5;
            int col = (idx4 & 31) << 2;
            float4 v = *(const float4*)(Wp + (size_t)(kt + row) * Nc + n0 + col);
            unsigned* dh = Wh + row * WS_STRIDE + col;
            unsigned h0 = f2tf32(v.x), h1 = f2tf32(v.y), h2_ = f2tf32(v.z), h3 = f2tf32(v.w);
            dh[0] = h0; dh[1] = h1; dh[2] = h2_; dh[3] = h3;
            if (SPLIT) {
                unsigned* dl = Wl + row * WS_STRIDE + col;
                dl[0] = f2tf32(v.x - __uint_as_float(h0));
                dl[1] = f2tf32(v.y - __uint_as_float(h1));
                dl[2] = f2tf32(v.z - __uint_as_float(h2_));
                dl[3] = f2tf32(v.w - __uint_as_float(h3));
            }
        }
        __syncthreads();

#pragma unroll
        for (int kk = 0; kk < 4; kk++) {
            int kb = kk * 8;
            unsigned ah0 = Ah[(r0 + qr) * AS_STRIDE + kb + qc];
            unsigned ah1 = Ah[(r0 + qr + 8) * AS_STRIDE + kb + qc];
            unsigned ah2 = Ah[(r0 + qr) * AS_STRIDE + kb + qc + 4];
            unsigned ah3 = Ah[(r0 + qr + 8) * AS_STRIDE + kb + qc + 4];
            unsigned al0, al1, al2, al3;
            if (SPLIT) {
                al0 = Al[(r0 + qr) * AS_STRIDE + kb + qc];
                al1 = Al[(r0 + qr + 8) * AS_STRIDE + kb + qc];
                al2 = Al[(r0 + qr) * AS_STRIDE + kb + qc + 4];
                al3 = Al[(r0 + qr + 8) * AS_STRIDE + kb + qc + 4];
            }
#pragma unroll
            for (int nc = 0; nc < 16; nc++) {
                int nb = nc * 8;
                unsigned bh0 = Wh[(kb + qc) * WS_STRIDE + nb + qr];
                unsigned bh1 = Wh[(kb + qc + 4) * WS_STRIDE + nb + qr];
                asm volatile(
                    "mma.sync.aligned.m16n8k8.row.col.f32.tf32.tf32.f32 "
                    "{%0,%1,%2,%3}, {%4,%5,%6,%7}, {%8,%9}, {%0,%1,%2,%3};"
                    : "+f"(acc[nc][0]), "+f"(acc[nc][1]), "+f"(acc[nc][2]), "+f"(acc[nc][3])
                    : "r"(ah0), "r"(ah1), "r"(ah2), "r"(ah3), "r"(bh0), "r"(bh1));
                if (SPLIT) {
                    unsigned bl0 = Wl[(kb + qc) * WS_STRIDE + nb + qr];
                    unsigned bl1 = Wl[(kb + qc + 4) * WS_STRIDE + nb + qr];
                    asm volatile(
                        "mma.sync.aligned.m16n8k8.row.col.f32.tf32.tf32.f32 "
                        "{%0,%1,%2,%3}, {%4,%5,%6,%7}, {%8,%9}, {%0,%1,%2,%3};"
                        : "+f"(acc[nc][0]), "+f"(acc[nc][1]), "+f"(acc[nc][2]), "+f"(acc[nc][3])
                        : "r"(ah0), "r"(ah1), "r"(ah2), "r"(ah3), "r"(bl0), "r"(bl1));
                    asm volatile(
                        "mma.sync.aligned.m16n8k8.row.col.f32.tf32.tf32.f32 "
                        "{%0,%1,%2,%3}, {%4,%5,%6,%7}, {%8,%9}, {%0,%1,%2,%3};"
                        : "+f"(acc[nc][0]), "+f"(acc[nc][1]), "+f"(acc[nc][2]), "+f"(acc[nc][3])
                        : "r"(al0), "r"(al1), "r"(al2), "r"(al3), "r"(bh0), "r"(bh1));
                }
            }
        }
        __syncthreads();
    }

    int row0 = m0 + r0 + qr;
    int row1 = row0 + 8;
#pragma unroll
    for (int nc = 0; nc < 16; nc++) {
        int c0 = n0 + nc * 8 + qc * 2;
        float bz0 = 0.f, bz1 = 0.f;
        if (bias) { bz0 = __ldg(bias + c0); bz1 = __ldg(bias + c0 + 1); }
        float u0 = acc[nc][0] + bz0, u1 = acc[nc][1] + bz1;
        float u2 = acc[nc][2] + bz0, u3 = acc[nc][3] + bz1;
        if (act) {
            u0 = u0 > 0.f ? u0 : expm1f(u0);
            u1 = u1 > 0.f ? u1 : expm1f(u1);
            u2 = u2 > 0.f ? u2 : expm1f(u2);
            u3 = u3 > 0.f ? u3 : expm1f(u3);
        }
        if (OUTH) {
            if (row0 < M) *(__half2*)((__half*)Cp + (size_t)row0 * Nc + c0) = __floats2half2_rn(u0, u1);
            if (row1 < M) *(__half2*)((__half*)Cp + (size_t)row1 * Nc + c0) = __floats2half2_rn(u2, u3);
        } else {
            if (row0 < M) *(float2*)((float*)Cp + (size_t)row0 * Nc + c0) = make_float2(u0, u1);
            if (row1 < M) *(float2*)((float*)Cp + (size_t)row1 * Nc + c0) = make_float2(u2, u3);
        }
    }
}

// ============================================================================
// Persistent fp16 edge decoder (mma.sync m16n8k16.f16, ldmatrix A-fragments)
// ============================================================================
#define TS_HW 68   // u32 words per t row (136 halves; row stride 272 bytes)

__global__ __launch_bounds__(256, 3)
void decoder_fp16_kernel(const __half* __restrict__ Ad, const __half* __restrict__ Bd,
                         const int* __restrict__ ei,
                         const float* __restrict__ b1, const float* __restrict__ W2,
                         const float* __restrict__ b2, const float* __restrict__ W3,
                         const float* __restrict__ b3, float* __restrict__ out,
                         int E, int numTiles) {
    extern __shared__ unsigned smemd[];
    unsigned* tS = smemd;                           // 128 x TS_HW u32
    float* b1s = (float*)(smemd + 128 * TS_HW);     // 128 floats
    float* esum = b1s + 128;                        // 128 floats
    int tid = threadIdx.x;
    int warp = tid >> 5, lane = tid & 31;
    int qr = lane >> 2, qc = lane & 3;
    int nBase = warp * 16;
    uint32_t tS_s = smem_u32(tS);
    // ldmatrix per-lane address components
    int laneRow = (lane & 7) + (lane & 8);
    int laneColB = ((lane >> 4) & 1) * 16;          // byte offset for k+8 half-group
    uint32_t lmBase = tS_s + (uint32_t)laneRow * 272 + (uint32_t)laneColB;

    // one-time: W2 fragments (fp16) for this warp's 16 N-cols, all K
    unsigned bf[8][2][2];
#pragma unroll
    for (int c = 0; c < 8; c++) {
        int kb = c * 16;
#pragma unroll
        for (int ncl = 0; ncl < 2; ncl++) {
            int n = nBase + ncl * 8 + qr;
            bf[c][ncl][0] = h2_bits(__floats2half2_rn(
                __ldg(W2 + (kb + 2 * qc) * 128 + n), __ldg(W2 + (kb + 2 * qc + 1) * 128 + n)));
            bf[c][ncl][1] = h2_bits(__floats2half2_rn(
                __ldg(W2 + (kb + 2 * qc + 8) * 128 + n), __ldg(W2 + (kb + 2 * qc + 9) * 128 + n)));
        }
    }
    float bb0[2], bb1[2], w30[2], w31[2];
#pragma unroll
    for (int ncl = 0; ncl < 2; ncl++) {
        int c0 = nBase + ncl * 8 + qc * 2;
        bb0[ncl] = __ldg(b2 + c0); bb1[ncl] = __ldg(b2 + c0 + 1);
        w30[ncl] = __ldg(W3 + c0); w31[ncl] = __ldg(W3 + c0 + 1);
    }
    float b3v = __ldg(b3);
    if (tid < 128) b1s[tid] = __ldg(b1 + tid);
    __syncthreads();

    for (int tile = blockIdx.x; tile < numTiles; tile += gridDim.x) {
        int eBase = tile * 128;
        __syncthreads();   // previous iteration done with tS/esum

        // phase 1: t = relu(A[src]+B[dst]+b1) -> fp16 smem. 2 threads/edge.
        {
            int eloc = tid >> 1;
            int half_ = tid & 1;
            int e = eBase + eloc;
            unsigned* trow = tS + eloc * TS_HW + half_ * 32;
            if (e < E) {
                int s = ei[e], d = ei[E + e];
                const uint4* ap = (const uint4*)(Ad + (size_t)s * 128) + half_ * 8;
                const uint4* bp = (const uint4*)(Bd + (size_t)d * 128) + half_ * 8;
#pragma unroll
                for (int j = 0; j < 8; j++) {
                    uint4 av = __ldg(ap + j);
                    uint4 bv = __ldg(bp + j);
                    const float* bb = b1s + half_ * 64 + j * 8;
                    unsigned aw[4] = {av.x, av.y, av.z, av.w};
                    unsigned bw[4] = {bv.x, bv.y, bv.z, bv.w};
#pragma unroll
                    for (int w = 0; w < 4; w++) {
                        float2 af = __half22float2(bits_h2(aw[w]));
                        float2 bf2 = __half22float2(bits_h2(bw[w]));
                        float v0 = fmaxf(af.x + bf2.x + bb[2 * w], 0.f);
                        float v1 = fmaxf(af.y + bf2.y + bb[2 * w + 1], 0.f);
                        trow[j * 4 + w] = h2_bits(__floats2half2_rn(v0, v1));
                    }
                }
            } else {
#pragma unroll
                for (int j = 0; j < 32; j++) trow[j] = 0u;
            }
            if (tid < 128) esum[tid] = 0.f;
        }
        __syncthreads();

        // phase 2: per m-tile of 16 edges; ldmatrix.x4 A-fragments; K=128 in 8 chunks
#pragma unroll 1
        for (int m = 0; m < 8; m++) {
            int r0 = m * 16;
            uint32_t rowAddr = lmBase + (uint32_t)r0 * 272;
            float acc[2][4];
            acc[0][0] = acc[0][1] = acc[0][2] = acc[0][3] = 0.f;
            acc[1][0] = acc[1][1] = acc[1][2] = acc[1][3] = 0.f;
#pragma unroll
            for (int c = 0; c < 8; c++) {
                unsigned a0, a1, a2, a3;
                asm volatile(
                    "ldmatrix.sync.aligned.m8n8.x4.shared.b16 {%0,%1,%2,%3}, [%4];"
                    : "=r"(a0), "=r"(a1), "=r"(a2), "=r"(a3)
                    : "r"(rowAddr + (uint32_t)c * 32));
                asm volatile(
                    "mma.sync.aligned.m16n8k16.row.col.f32.f16.f16.f32 "
                    "{%0,%1,%2,%3}, {%4,%5,%6,%7}, {%8,%9}, {%0,%1,%2,%3};"
                    : "+f"(acc[0][0]), "+f"(acc[0][1]), "+f"(acc[0][2]), "+f"(acc[0][3])
                    : "r"(a0), "r"(a1), "r"(a2), "r"(a3), "r"(bf[c][0][0]), "r"(bf[c][0][1]));
                asm volatile(
                    "mma.sync.aligned.m16n8k16.row.col.f32.f16.f16.f32 "
                    "{%0,%1,%2,%3}, {%4,%5,%6,%7}, {%8,%9}, {%0,%1,%2,%3};"
                    : "+f"(acc[1][0]), "+f"(acc[1][1]), "+f"(acc[1][2]), "+f"(acc[1][3])
                    : "r"(a0), "r"(a1), "r"(a2), "r"(a3), "r"(bf[c][1][0]), "r"(bf[c][1][1]));
            }
            float e0 = 0.f, e1 = 0.f;
#pragma unroll
            for (int ncl = 0; ncl < 2; ncl++) {
                e0 += fmaxf(acc[ncl][0] + bb0[ncl], 0.f) * w30[ncl]
                    + fmaxf(acc[ncl][1] + bb1[ncl], 0.f) * w31[ncl];
                e1 += fmaxf(acc[ncl][2] + bb0[ncl], 0.f) * w30[ncl]
                    + fmaxf(acc[ncl][3] + bb1[ncl], 0.f) * w31[ncl];
            }
            e0 += __shfl_xor_sync(0xffffffffu, e0, 1);
            e0 += __shfl_xor_sync(0xffffffffu, e0, 2);
            e1 += __shfl_xor_sync(0xffffffffu, e1, 1);
            e1 += __shfl_xor_sync(0xffffffffu, e1, 2);
            if (qc == 0) {
                atomicAdd(&esum[r0 + qr], e0);
                atomicAdd(&esum[r0 + qr + 8], e1);
            }
        }
        __syncthreads();

        if (tid < 128) {
            int e = eBase + tid;
            if (e < E) out[e] = esum[tid] + b3v;
        }
    }
}

extern "C" void kernel_launch(void* const* d_in, const int* in_sizes, int n_in,
                              void* d_out, int out_size) {
    const int* node_ids = (const int*)d_in[0];
    const int* ei       = (const int*)d_in[1];
    const int* nei      = (const int*)d_in[2];
    const float* eattr  = (const float*)d_in[3];
    const float* emb    = (const float*)d_in[4];
    const float* W_in   = (const float*)d_in[5];
    const float* b_in   = (const float*)d_in[6];
    const float* W_out  = (const float*)d_in[7];
    const float* b_out  = (const float*)d_in[8];
    const float* W1     = (const float*)d_in[9];
    const float* b1     = (const float*)d_in[10];
    const float* W2     = (const float*)d_in[11];
    const float* b2     = (const float*)d_in[12];
    const float* W3     = (const float*)d_in[13];
    const float* b3     = (const float*)d_in[14];
    int N = in_sizes[0];
    int E = in_sizes[3];
    float* out = (float*)d_out;

    float *agg1, *x1, *x2;
    __half *h2h, *Ad, *Bd;
    int *off1, *off2;
    int2 *pair1, *pair2;
    cudaGetSymbolAddress((void**)&agg1, g_agg1);
    cudaGetSymbolAddress((void**)&x1, g_x1);
    cudaGetSymbolAddress((void**)&h2h, g_h2h);
    cudaGetSymbolAddress((void**)&x2, g_x2);
    cudaGetSymbolAddress((void**)&Ad, g_Adec);
    cudaGetSymbolAddress((void**)&Bd, g_Bdec);
    cudaGetSymbolAddress((void**)&off1, g_off1);
    cudaGetSymbolAddress((void**)&off2, g_off2);
    cudaGetSymbolAddress((void**)&pair1, g_pair1);
    cudaGetSymbolAddress((void**)&pair2, g_pair2);

    const int T = 256;
    zero_init_kernel<<<(N + T - 1) / T, T>>>(N);
    deg_cnt_kernel<<<(E + T - 1) / T, T>>>(ei, eattr, nei, E);
    scan2_kernel<<<1, 1024>>>(N, E);
    fill_kernel<<<(E + T - 1) / T, T>>>(ei, nei, eattr, node_ids, E);

    int mBlocks = (N + 127) / 128;
    int smem_split = (128 * AS_STRIDE * 2 + 32 * WS_STRIDE * 2) * 4;
    cudaFuncSetAttribute((const void*)gemm_tf32_kernel<1, 0, 0, 0>,
                         cudaFuncAttributeMaxDynamicSharedMemorySize, smem_split);
    cudaFuncSetAttribute((const void*)gemm_tf32_kernel<1, 0, 0, 1>,
                         cudaFuncAttributeMaxDynamicSharedMemorySize, smem_split);
    cudaFuncSetAttribute((const void*)gemm_tf32_kernel<1, 1, 1, 1>,
                         cudaFuncAttributeMaxDynamicSharedMemorySize, smem_split);

    int gatherBlocks = (N * 32 + T - 1) / T;

    // conv1: gather-aggregate emb (fp32), then GEMM with fused bias+elu
    gather_f32_kernel<<<gatherBlocks, T>>>(emb, agg1, off1, pair1, N);
    gemm_tf32_kernel<1, 0, 0, 0><<<dim3(2, mBlocks), 256, smem_split>>>(
        agg1, W_in, x1, N, 128, 256, b_in, 1, nullptr, nullptr, nullptr);

    // conv2: GEMM (fp16 out) then fp16 gather-aggregate
    gemm_tf32_kernel<1, 0, 0, 1><<<dim3(1, mBlocks), 256, smem_split>>>(
        x1, W_out, h2h, N, 256, 128, nullptr, 0, nullptr, nullptr, nullptr);
    gather_f16_kernel<<<gatherBlocks, T>>>(h2h, x2, off2, pair2, N);

    // merged dual pre-GEMMs (hi/lo split, elu(x2+b_out) fused on A, fp16 outputs)
    gemm_tf32_kernel<1, 1, 1, 1><<<dim3(2, mBlocks), 256, smem_split>>>(
        x2, W1, Ad, N, 128, 128, nullptr, 0, b_out, W1 + 128 * 128, Bd);

    // persistent fp16 tensor-core edge decoder
    int numTiles = (E + 127) / 128;
    int smem_dec = (128 * TS_HW + 256) * 4;
    cudaFuncSetAttribute(decoder_fp16_kernel, cudaFuncAttributeMaxDynamicSharedMemorySize, smem_dec);
    int grid_dec = 3 * 148;
    if (grid_dec > numTiles) grid_dec = numTiles;
    decoder_fp16_kernel<<<grid_dec, 256, smem_dec>>>(Ad, Bd, ei, b1, W2, b2, W3, b3, out, E, numTiles);
}

// round 11
// speedup vs baseline: 2.5765x; 1.0515x over previous
#include <cuda_runtime.h>
#include <cuda_fp16.h>
#include <math.h>
#include <stdint.h>

#define MAXN 50000
#define MAXE 800000

// ---- scratch (device globals; no allocation allowed) ----
__device__ float g_deg1[MAXN];
__device__ int   g_cnt1[MAXN];
__device__ int   g_deg2[MAXN];
__device__ int   g_off1[MAXN + 1];
__device__ int   g_off2[MAXN + 1];
__device__ int   g_cur1[MAXN];
__device__ int   g_cur2[MAXN];
__device__ int2  g_pair1[MAXE];
__device__ int2  g_pair2[MAXE];
__device__ __half g_embh[(size_t)MAXN * 128];
__device__ float g_agg1[(size_t)MAXN * 128];
__device__ float g_x1[(size_t)MAXN * 256];
__device__ __half g_h2h[(size_t)MAXN * 128];
__device__ float g_x2[(size_t)MAXN * 128];
__device__ __half g_Adec[(size_t)MAXN * 128];
__device__ __half g_Bdec[(size_t)MAXN * 128];

__device__ __forceinline__ unsigned f2tf32(float x) {
    unsigned u;
    asm("cvt.rna.tf32.f32 %0, %1;" : "=r"(u) : "f"(x));
    return u;
}
__device__ __forceinline__ unsigned h2_bits(__half2 h) {
    unsigned u;
    *(__half2*)&u = h;
    return u;
}
__device__ __forceinline__ __half2 bits_h2(unsigned u) {
    return *(__half2*)&u;
}
__device__ __forceinline__ uint32_t smem_u32(const void* p) {
    uint32_t a;
    asm("{ .reg .u64 t; cvta.to.shared.u64 t, %1; cvt.u32.u64 %0, t; }" : "=r"(a) : "l"(p));
    return a;
}

// ================= misc =================
__global__ void f2h_kernel(const float* __restrict__ in, __half* __restrict__ out, int n4) {
    int i = blockIdx.x * blockDim.x + threadIdx.x;
    if (i < n4) {
        float4 v = ((const float4*)in)[i];
        uint2 o;
        o.x = h2_bits(__floats2half2_rn(v.x, v.y));
        o.y = h2_bits(__floats2half2_rn(v.z, v.w));
        ((uint2*)out)[i] = o;
    }
}

// ================= CSR build =================
__global__ void zero_init_kernel(int N) {
    int i = blockIdx.x * blockDim.x + threadIdx.x;
    if (i < N) {
        g_deg1[i] = 0.f; g_cnt1[i] = 0; g_deg2[i] = 0;
        g_cur1[i] = 0; g_cur2[i] = 0;
    }
}

__global__ void deg_cnt_kernel(const int* __restrict__ ei, const float* __restrict__ w,
                               const int* __restrict__ nei, int E) {
    int e = blockIdx.x * blockDim.x + threadIdx.x;
    if (e < E) {
        int c1 = ei[E + e];
        atomicAdd(&g_deg1[c1], w[e]);
        atomicAdd(&g_cnt1[c1], 1);
        atomicAdd(&g_deg2[nei[E + e]], 1);
    }
}

__global__ __launch_bounds__(1024, 1)
void scan2_kernel(int N, int E) {
    __shared__ int warpTot[32];
    int tid = threadIdx.x;
    int lane = tid & 31, w = tid >> 5;
    int chunk = (N + 1023) / 1024;
    int beg = tid * chunk;
    int end = beg + chunk; if (end > N) end = N;
#pragma unroll 1
    for (int a = 0; a < 2; a++) {
        const int* c = a ? g_deg2 : g_cnt1;
        int* o = a ? g_off2 : g_off1;
        __syncthreads();
        int t = 0;
        for (int i = beg; i < end; i++) t += c[i];
        int v = t;
#pragma unroll
        for (int d = 1; d < 32; d <<= 1) {
            int u = __shfl_up_sync(0xffffffffu, v, d);
            if (lane >= d) v += u;
        }
        if (lane == 31) warpTot[w] = v;
        __syncthreads();
        if (w == 0) {
            int x = warpTot[lane];
#pragma unroll
            for (int d = 1; d < 32; d <<= 1) {
                int u = __shfl_up_sync(0xffffffffu, x, d);
                if (lane >= d) x += u;
            }
            warpTot[lane] = x;
        }
        __syncthreads();
        int run = v - t + (w > 0 ? warpTot[w - 1] : 0);
        for (int i = beg; i < end; i++) { o[i] = run; run += c[i]; }
    }
    if (tid == 0) { g_off1[N] = E; g_off2[N] = E; }
}

__global__ void fill_kernel(const int* __restrict__ ei, const int* __restrict__ nei,
                            const float* __restrict__ w, const int* __restrict__ node_ids,
                            int E) {
    int e = blockIdx.x * blockDim.x + threadIdx.x;
    if (e >= E) return;
    {
        int r = ei[e], c = ei[E + e];
        float dr = g_deg1[r], dc = g_deg1[c];
        float nrm = (dr > 0.f ? rsqrtf(dr) : 0.f) * w[e] * (dc > 0.f ? rsqrtf(dc) : 0.f);
        int p = g_off1[c] + atomicAdd(&g_cur1[c], 1);
        g_pair1[p] = make_int2(node_ids[r], __float_as_int(nrm));
    }
    {
        int r = nei[e], c = nei[E + e];
        float dr = (float)g_deg2[r], dc = (float)g_deg2[c];
        float nrm = (dr > 0.f ? rsqrtf(dr) : 0.f) * (dc > 0.f ? rsqrtf(dc) : 0.f);
        int p = g_off2[c] + atomicAdd(&g_cur2[c], 1);
        g_pair2[p] = make_int2(r, __float_as_int(nrm));
    }
}

// ---- gather-reduce from fp16 rows (half the read traffic) ----
__global__ void gather_f16_kernel(const __half* __restrict__ h, float* __restrict__ out,
                                  const int* __restrict__ off, const int2* __restrict__ pair,
                                  int N) {
    int gw = (blockIdx.x * blockDim.x + threadIdx.x) >> 5;
    if (gw >= N) return;
    int lane = threadIdx.x & 31;
    int s = off[gw], t = off[gw + 1];
    float4 acc0 = make_float4(0.f, 0.f, 0.f, 0.f);
    float4 acc1 = make_float4(0.f, 0.f, 0.f, 0.f);
    int i = s;
    for (; i + 2 <= t; i += 2) {
        int2 p0 = __ldg(pair + i), p1 = __ldg(pair + i + 1);
        float n0 = __int_as_float(p0.y), n1 = __int_as_float(p1.y);
        uint2 w0 = *(const uint2*)(h + (size_t)p0.x * 128 + lane * 4);
        uint2 w1 = *(const uint2*)(h + (size_t)p1.x * 128 + lane * 4);
        float2 v0a = __half22float2(bits_h2(w0.x)), v0b = __half22float2(bits_h2(w0.y));
        float2 v1a = __half22float2(bits_h2(w1.x)), v1b = __half22float2(bits_h2(w1.y));
        acc0.x = fmaf(v0a.x, n0, acc0.x); acc0.y = fmaf(v0a.y, n0, acc0.y);
        acc0.z = fmaf(v0b.x, n0, acc0.z); acc0.w = fmaf(v0b.y, n0, acc0.w);
        acc1.x = fmaf(v1a.x, n1, acc1.x); acc1.y = fmaf(v1a.y, n1, acc1.y);
        acc1.z = fmaf(v1b.x, n1, acc1.z); acc1.w = fmaf(v1b.y, n1, acc1.w);
    }
    if (i < t) {
        int2 p0 = __ldg(pair + i);
        float n0 = __int_as_float(p0.y);
        uint2 w0 = *(const uint2*)(h + (size_t)p0.x * 128 + lane * 4);
        float2 v0a = __half22float2(bits_h2(w0.x)), v0b = __half22float2(bits_h2(w0.y));
        acc0.x = fmaf(v0a.x, n0, acc0.x); acc0.y = fmaf(v0a.y, n0, acc0.y);
        acc0.z = fmaf(v0b.x, n0, acc0.z); acc0.w = fmaf(v0b.y, n0, acc0.w);
    }
    acc0.x += acc1.x; acc0.y += acc1.y; acc0.z += acc1.z; acc0.w += acc1.w;
    *(float4*)(out + (size_t)gw * 128 + lane * 4) = acc0;
}

// ================= tf32 mma.sync node GEMM =================
#define AS_STRIDE 36
#define WS_STRIDE 132

template <int SPLIT, int PREACT, int DUAL, int OUTH>
__global__ __launch_bounds__(256, 1)
void gemm_tf32_kernel(const float* __restrict__ A, const float* __restrict__ W,
                      void* __restrict__ C, int M, int K, int Nc,
                      const float* __restrict__ bias, int act,
                      const float* __restrict__ abias,
                      const float* __restrict__ Wb, void* __restrict__ Cb) {
    extern __shared__ unsigned sm[];
    unsigned* Ah = sm;
    unsigned* Al = Ah + 128 * AS_STRIDE;
    unsigned* Wh = Al + (SPLIT ? 128 * AS_STRIDE : 0);
    unsigned* Wl = Wh + 32 * WS_STRIDE;

    int tid = threadIdx.x;
    int warp = tid >> 5, lane = tid & 31;
    int qr = lane >> 2, qc = lane & 3;
    int m0 = blockIdx.y * 128;
    const float* Wp = W;
    void* Cp = C;
    int n0 = blockIdx.x * 128;
    if (DUAL) {
        if (blockIdx.x) { Wp = Wb; Cp = Cb; }
        n0 = 0;
    }
    int r0 = warp * 16;

    float acc[16][4];
#pragma unroll
    for (int n = 0; n < 16; n++)
#pragma unroll
        for (int j = 0; j < 4; j++) acc[n][j] = 0.f;

    for (int kt = 0; kt < K; kt += 32) {
#pragma unroll
        for (int i = 0; i < 4; i++) {
            int idx4 = tid + i * 256;
            int row = idx4 >> 3;
            int col = (idx4 & 7) << 2;
            float4 v = make_float4(0.f, 0.f, 0.f, 0.f);
            if (m0 + row < M) v = *(const float4*)(A + (size_t)(m0 + row) * K + kt + col);
            if (PREACT) {
                float4 ab = *(const float4*)(abias + kt + col);
                v.x += ab.x; v.y += ab.y; v.z += ab.z; v.w += ab.w;
                v.x = v.x > 0.f ? v.x : expm1f(v.x);
                v.y = v.y > 0.f ? v.y : expm1f(v.y);
                v.z = v.z > 0.f ? v.z : expm1f(v.z);
                v.w = v.w > 0.f ? v.w : expm1f(v.w);
            }
            unsigned* dh = Ah + row * AS_STRIDE + col;
            unsigned h0 = f2tf32(v.x), h1 = f2tf32(v.y), h2_ = f2tf32(v.z), h3 = f2tf32(v.w);
            dh[0] = h0; dh[1] = h1; dh[2] = h2_; dh[3] = h3;
            if (SPLIT) {
                unsigned* dl = Al + row * AS_STRIDE + col;
                dl[0] = f2tf32(v.x - __uint_as_float(h0));
                dl[1] = f2tf32(v.y - __uint_as_float(h1));
                dl[2] = f2tf32(v.z - __uint_as_float(h2_));
                dl[3] = f2tf32(v.w - __uint_as_float(h3));
            }
        }
#pragma unroll
        for (int i = 0; i < 4; i++) {
            int idx4 = tid + i * 256;
            int row = idx4 >> 5;
            int col = (idx4 & 31) << 2;
            float4 v = *(const float4*)(Wp + (size_t)(kt + row) * Nc + n0 + col);
            unsigned* dh = Wh + row * WS_STRIDE + col;
            unsigned h0 = f2tf32(v.x), h1 = f2tf32(v.y), h2_ = f2tf32(v.z), h3 = f2tf32(v.w);
            dh[0] = h0; dh[1] = h1; dh[2] = h2_; dh[3] = h3;
            if (SPLIT) {
                unsigned* dl = Wl + row * WS_STRIDE + col;
                dl[0] = f2tf32(v.x - __uint_as_float(h0));
                dl[1] = f2tf32(v.y - __uint_as_float(h1));
                dl[2] = f2tf32(v.z - __uint_as_float(h2_));
                dl[3] = f2tf32(v.w - __uint_as_float(h3));
            }
        }
        __syncthreads();

#pragma unroll
        for (int kk = 0; kk < 4; kk++) {
            int kb = kk * 8;
            unsigned ah0 = Ah[(r0 + qr) * AS_STRIDE + kb + qc];
            unsigned ah1 = Ah[(r0 + qr + 8) * AS_STRIDE + kb + qc];
            unsigned ah2 = Ah[(r0 + qr) * AS_STRIDE + kb + qc + 4];
            unsigned ah3 = Ah[(r0 + qr + 8) * AS_STRIDE + kb + qc + 4];
            unsigned al0, al1, al2, al3;
            if (SPLIT) {
                al0 = Al[(r0 + qr) * AS_STRIDE + kb + qc];
                al1 = Al[(r0 + qr + 8) * AS_STRIDE + kb + qc];
                al2 = Al[(r0 + qr) * AS_STRIDE + kb + qc + 4];
                al3 = Al[(r0 + qr + 8) * AS_STRIDE + kb + qc + 4];
            }
#pragma unroll
            for (int nc = 0; nc < 16; nc++) {
                int nb = nc * 8;
                unsigned bh0 = Wh[(kb + qc) * WS_STRIDE + nb + qr];
                unsigned bh1 = Wh[(kb + qc + 4) * WS_STRIDE + nb + qr];
                asm volatile(
                    "mma.sync.aligned.m16n8k8.row.col.f32.tf32.tf32.f32 "
                    "{%0,%1,%2,%3}, {%4,%5,%6,%7}, {%8,%9}, {%0,%1,%2,%3};"
                    : "+f"(acc[nc][0]), "+f"(acc[nc][1]), "+f"(acc[nc][2]), "+f"(acc[nc][3])
                    : "r"(ah0), "r"(ah1), "r"(ah2), "r"(ah3), "r"(bh0), "r"(bh1));
                if (SPLIT) {
                    unsigned bl0 = Wl[(kb + qc) * WS_STRIDE + nb + qr];
                    unsigned bl1 = Wl[(kb + qc + 4) * WS_STRIDE + nb + qr];
                    asm volatile(
                        "mma.sync.aligned.m16n8k8.row.col.f32.tf32.tf32.f32 "
                        "{%0,%1,%2,%3}, {%4,%5,%6,%7}, {%8,%9}, {%0,%1,%2,%3};"
                        : "+f"(acc[nc][0]), "+f"(acc[nc][1]), "+f"(acc[nc][2]), "+f"(acc[nc][3])
                        : "r"(ah0), "r"(ah1), "r"(ah2), "r"(ah3), "r"(bl0), "r"(bl1));
                    asm volatile(
                        "mma.sync.aligned.m16n8k8.row.col.f32.tf32.tf32.f32 "
                        "{%0,%1,%2,%3}, {%4,%5,%6,%7}, {%8,%9}, {%0,%1,%2,%3};"
                        : "+f"(acc[nc][0]), "+f"(acc[nc][1]), "+f"(acc[nc][2]), "+f"(acc[nc][3])
                        : "r"(al0), "r"(al1), "r"(al2), "r"(al3), "r"(bh0), "r"(bh1));
                }
            }
        }
        __syncthreads();
    }

    int row0 = m0 + r0 + qr;
    int row1 = row0 + 8;
#pragma unroll
    for (int nc = 0; nc < 16; nc++) {
        int c0 = n0 + nc * 8 + qc * 2;
        float bz0 = 0.f, bz1 = 0.f;
        if (bias) { bz0 = __ldg(bias + c0); bz1 = __ldg(bias + c0 + 1); }
        float u0 = acc[nc][0] + bz0, u1 = acc[nc][1] + bz1;
        float u2 = acc[nc][2] + bz0, u3 = acc[nc][3] + bz1;
        if (act) {
            u0 = u0 > 0.f ? u0 : expm1f(u0);
            u1 = u1 > 0.f ? u1 : expm1f(u1);
            u2 = u2 > 0.f ? u2 : expm1f(u2);
            u3 = u3 > 0.f ? u3 : expm1f(u3);
        }
        if (OUTH) {
            if (row0 < M) *(__half2*)((__half*)Cp + (size_t)row0 * Nc + c0) = __floats2half2_rn(u0, u1);
            if (row1 < M) *(__half2*)((__half*)Cp + (size_t)row1 * Nc + c0) = __floats2half2_rn(u2, u3);
        } else {
            if (row0 < M) *(float2*)((float*)Cp + (size_t)row0 * Nc + c0) = make_float2(u0, u1);
            if (row1 < M) *(float2*)((float*)Cp + (size_t)row1 * Nc + c0) = make_float2(u2, u3);
        }
    }
}

// ============================================================================
// Persistent fp16 edge decoder (mma.sync m16n8k16.f16, ldmatrix A-fragments)
// ============================================================================
#define TS_HW 68   // u32 words per t row (136 halves; row stride 272 bytes)

__global__ __launch_bounds__(256, 3)
void decoder_fp16_kernel(const __half* __restrict__ Ad, const __half* __restrict__ Bd,
                         const int* __restrict__ ei,
                         const float* __restrict__ b1, const float* __restrict__ W2,
                         const float* __restrict__ b2, const float* __restrict__ W3,
                         const float* __restrict__ b3, float* __restrict__ out,
                         int E, int numTiles) {
    extern __shared__ unsigned smemd[];
    unsigned* tS = smemd;                           // 128 x TS_HW u32
    float* b1s = (float*)(smemd + 128 * TS_HW);     // 128 floats
    float* esum = b1s + 128;                        // 128 floats
    int tid = threadIdx.x;
    int warp = tid >> 5, lane = tid & 31;
    int qr = lane >> 2, qc = lane & 3;
    int nBase = warp * 16;
    uint32_t tS_s = smem_u32(tS);
    int laneRow = (lane & 7) + (lane & 8);
    int laneColB = ((lane >> 4) & 1) * 16;
    uint32_t lmBase = tS_s + (uint32_t)laneRow * 272 + (uint32_t)laneColB;

    unsigned bf[8][2][2];
#pragma unroll
    for (int c = 0; c < 8; c++) {
        int kb = c * 16;
#pragma unroll
        for (int ncl = 0; ncl < 2; ncl++) {
            int n = nBase + ncl * 8 + qr;
            bf[c][ncl][0] = h2_bits(__floats2half2_rn(
                __ldg(W2 + (kb + 2 * qc) * 128 + n), __ldg(W2 + (kb + 2 * qc + 1) * 128 + n)));
            bf[c][ncl][1] = h2_bits(__floats2half2_rn(
                __ldg(W2 + (kb + 2 * qc + 8) * 128 + n), __ldg(W2 + (kb + 2 * qc + 9) * 128 + n)));
        }
    }
    float bb0[2], bb1[2], w30[2], w31[2];
#pragma unroll
    for (int ncl = 0; ncl < 2; ncl++) {
        int c0 = nBase + ncl * 8 + qc * 2;
        bb0[ncl] = __ldg(b2 + c0); bb1[ncl] = __ldg(b2 + c0 + 1);
        w30[ncl] = __ldg(W3 + c0); w31[ncl] = __ldg(W3 + c0 + 1);
    }
    float b3v = __ldg(b3);
    if (tid < 128) b1s[tid] = __ldg(b1 + tid);
    __syncthreads();

    for (int tile = blockIdx.x; tile < numTiles; tile += gridDim.x) {
        int eBase = tile * 128;
        __syncthreads();

        {
            int eloc = tid >> 1;
            int half_ = tid & 1;
            int e = eBase + eloc;
            unsigned* trow = tS + eloc * TS_HW + half_ * 32;
            if (e < E) {
                int s = ei[e], d = ei[E + e];
                const uint4* ap = (const uint4*)(Ad + (size_t)s * 128) + half_ * 8;
                const uint4* bp = (const uint4*)(Bd + (size_t)d * 128) + half_ * 8;
#pragma unroll
                for (int j = 0; j < 8; j++) {
                    uint4 av = __ldg(ap + j);
                    uint4 bv = __ldg(bp + j);
                    const float* bb = b1s + half_ * 64 + j * 8;
                    unsigned aw[4] = {av.x, av.y, av.z, av.w};
                    unsigned bw[4] = {bv.x, bv.y, bv.z, bv.w};
#pragma unroll
                    for (int w = 0; w < 4; w++) {
                        float2 af = __half22float2(bits_h2(aw[w]));
                        float2 bf2 = __half22float2(bits_h2(bw[w]));
                        float v0 = fmaxf(af.x + bf2.x + bb[2 * w], 0.f);
                        float v1 = fmaxf(af.y + bf2.y + bb[2 * w + 1], 0.f);
                        trow[j * 4 + w] = h2_bits(__floats2half2_rn(v0, v1));
                    }
                }
            } else {
#pragma unroll
                for (int j = 0; j < 32; j++) trow[j] = 0u;
            }
            if (tid < 128) esum[tid] = 0.f;
        }
        __syncthreads();

#pragma unroll 1
        for (int m = 0; m < 8; m++) {
            int r0 = m * 16;
            uint32_t rowAddr = lmBase + (uint32_t)r0 * 272;
            float acc[2][4];
            acc[0][0] = acc[0][1] = acc[0][2] = acc[0][3] = 0.f;
            acc[1][0] = acc[1][1] = acc[1][2] = acc[1][3] = 0.f;
#pragma unroll
            for (int c = 0; c < 8; c++) {
                unsigned a0, a1, a2, a3;
                asm volatile(
                    "ldmatrix.sync.aligned.m8n8.x4.shared.b16 {%0,%1,%2,%3}, [%4];"
                    : "=r"(a0), "=r"(a1), "=r"(a2), "=r"(a3)
                    : "r"(rowAddr + (uint32_t)c * 32));
                asm volatile(
                    "mma.sync.aligned.m16n8k16.row.col.f32.f16.f16.f32 "
                    "{%0,%1,%2,%3}, {%4,%5,%6,%7}, {%8,%9}, {%0,%1,%2,%3};"
                    : "+f"(acc[0][0]), "+f"(acc[0][1]), "+f"(acc[0][2]), "+f"(acc[0][3])
                    : "r"(a0), "r"(a1), "r"(a2), "r"(a3), "r"(bf[c][0][0]), "r"(bf[c][0][1]));
                asm volatile(
                    "mma.sync.aligned.m16n8k16.row.col.f32.f16.f16.f32 "
                    "{%0,%1,%2,%3}, {%4,%5,%6,%7}, {%8,%9}, {%0,%1,%2,%3};"
                    : "+f"(acc[1][0]), "+f"(acc[1][1]), "+f"(acc[1][2]), "+f"(acc[1][3])
                    : "r"(a0), "r"(a1), "r"(a2), "r"(a3), "r"(bf[c][1][0]), "r"(bf[c][1][1]));
            }
            float e0 = 0.f, e1 = 0.f;
#pragma unroll
            for (int ncl = 0; ncl < 2; ncl++) {
                e0 += fmaxf(acc[ncl][0] + bb0[ncl], 0.f) * w30[ncl]
                    + fmaxf(acc[ncl][1] + bb1[ncl], 0.f) * w31[ncl];
                e1 += fmaxf(acc[ncl][2] + bb0[ncl], 0.f) * w30[ncl]
                    + fmaxf(acc[ncl][3] + bb1[ncl], 0.f) * w31[ncl];
            }
            e0 += __shfl_xor_sync(0xffffffffu, e0, 1);
            e0 += __shfl_xor_sync(0xffffffffu, e0, 2);
            e1 += __shfl_xor_sync(0xffffffffu, e1, 1);
            e1 += __shfl_xor_sync(0xffffffffu, e1, 2);
            if (qc == 0) {
                atomicAdd(&esum[r0 + qr], e0);
                atomicAdd(&esum[r0 + qr + 8], e1);
            }
        }
        __syncthreads();

        if (tid < 128) {
            int e = eBase + tid;
            if (e < E) out[e] = esum[tid] + b3v;
        }
    }
}

extern "C" void kernel_launch(void* const* d_in, const int* in_sizes, int n_in,
                              void* d_out, int out_size) {
    const int* node_ids = (const int*)d_in[0];
    const int* ei       = (const int*)d_in[1];
    const int* nei      = (const int*)d_in[2];
    const float* eattr  = (const float*)d_in[3];
    const float* emb    = (const float*)d_in[4];
    const float* W_in   = (const float*)d_in[5];
    const float* b_in   = (const float*)d_in[6];
    const float* W_out  = (const float*)d_in[7];
    const float* b_out  = (const float*)d_in[8];
    const float* W1     = (const float*)d_in[9];
    const float* b1     = (const float*)d_in[10];
    const float* W2     = (const float*)d_in[11];
    const float* b2     = (const float*)d_in[12];
    const float* W3     = (const float*)d_in[13];
    const float* b3     = (const float*)d_in[14];
    int N = in_sizes[0];
    int E = in_sizes[3];
    float* out = (float*)d_out;

    float *agg1, *x1, *x2;
    __half *embh, *h2h, *Ad, *Bd;
    int *off1, *off2;
    int2 *pair1, *pair2;
    cudaGetSymbolAddress((void**)&embh, g_embh);
    cudaGetSymbolAddress((void**)&agg1, g_agg1);
    cudaGetSymbolAddress((void**)&x1, g_x1);
    cudaGetSymbolAddress((void**)&h2h, g_h2h);
    cudaGetSymbolAddress((void**)&x2, g_x2);
    cudaGetSymbolAddress((void**)&Ad, g_Adec);
    cudaGetSymbolAddress((void**)&Bd, g_Bdec);
    cudaGetSymbolAddress((void**)&off1, g_off1);
    cudaGetSymbolAddress((void**)&off2, g_off2);
    cudaGetSymbolAddress((void**)&pair1, g_pair1);
    cudaGetSymbolAddress((void**)&pair2, g_pair2);

    const int T = 256;
    zero_init_kernel<<<(N + T - 1) / T, T>>>(N);
    deg_cnt_kernel<<<(E + T - 1) / T, T>>>(ei, eattr, nei, E);
    scan2_kernel<<<1, 1024>>>(N, E);
    fill_kernel<<<(E + T - 1) / T, T>>>(ei, nei, eattr, node_ids, E);
    // convert emb table to fp16 (halves conv1 gather traffic)
    f2h_kernel<<<(N * 32 + T - 1) / T, T>>>(emb, embh, N * 32);

    int mBlocks = (N + 127) / 128;
    int smem_split = (128 * AS_STRIDE * 2 + 32 * WS_STRIDE * 2) * 4;
    int smem_plain = (128 * AS_STRIDE + 32 * WS_STRIDE) * 4;
    cudaFuncSetAttribute((const void*)gemm_tf32_kernel<1, 0, 0, 0>,
                         cudaFuncAttributeMaxDynamicSharedMemorySize, smem_split);
    cudaFuncSetAttribute((const void*)gemm_tf32_kernel<1, 0, 0, 1>,
                         cudaFuncAttributeMaxDynamicSharedMemorySize, smem_split);
    cudaFuncSetAttribute((const void*)gemm_tf32_kernel<0, 1, 1, 1>,
                         cudaFuncAttributeMaxDynamicSharedMemorySize, smem_plain);

    int gatherBlocks = (N * 32 + T - 1) / T;

    // conv1: fp16 gather-aggregate emb, then GEMM with fused bias+elu
    gather_f16_kernel<<<gatherBlocks, T>>>(embh, agg1, off1, pair1, N);
    gemm_tf32_kernel<1, 0, 0, 0><<<dim3(2, mBlocks), 256, smem_split>>>(
        agg1, W_in, x1, N, 128, 256, b_in, 1, nullptr, nullptr, nullptr);

    // conv2: GEMM (fp16 out) then fp16 gather-aggregate
    gemm_tf32_kernel<1, 0, 0, 1><<<dim3(1, mBlocks), 256, smem_split>>>(
        x1, W_out, h2h, N, 256, 128, nullptr, 0, nullptr, nullptr, nullptr);
    gather_f16_kernel<<<gatherBlocks, T>>>(h2h, x2, off2, pair2, N);

    // merged dual pre-GEMMs (single-pass tf32; elu(x2+b_out) fused on A, fp16 outputs)
    gemm_tf32_kernel<0, 1, 1, 1><<<dim3(2, mBlocks), 256, smem_plain>>>(
        x2, W1, Ad, N, 128, 128, nullptr, 0, b_out, W1 + 128 * 128, Bd);

    // persistent fp16 tensor-core edge decoder
    int numTiles = (E + 127) / 128;
    int smem_dec = (128 * TS_HW + 256) * 4;
    cudaFuncSetAttribute(decoder_fp16_kernel, cudaFuncAttributeMaxDynamicSharedMemorySize, smem_dec);
    int grid_dec = 3 * 148;
    if (grid_dec > numTiles) grid_dec = numTiles;
    decoder_fp16_kernel<<<grid_dec, 256, smem_dec>>>(Ad, Bd, ei, b1, W2, b2, W3, b3, out, E, numTiles);
}

// round 12
// speedup vs baseline: 2.6368x; 1.0234x over previous
#include <cuda_runtime.h>
#include <cuda_fp16.h>
#include <math.h>
#include <stdint.h>

#define MAXN 50000
#define MAXE 800000

// ---- scratch (device globals; no allocation allowed) ----
__device__ float g_deg1[MAXN];
__device__ int   g_cnt1[MAXN];
__device__ int   g_deg2[MAXN];
__device__ int   g_off1[MAXN + 1];
__device__ int   g_off2[MAXN + 1];
__device__ int   g_cur1[MAXN];
__device__ int   g_cur2[MAXN];
__device__ int2  g_pair1[MAXE];
__device__ int2  g_pair2[MAXE];
__device__ __half g_embh[(size_t)MAXN * 128];
__device__ float g_agg1[(size_t)MAXN * 128];
__device__ float g_x1[(size_t)MAXN * 256];
__device__ __half g_h2h[(size_t)MAXN * 128];
__device__ float g_x2[(size_t)MAXN * 128];
__device__ __half g_Adec[(size_t)MAXN * 128];
__device__ __half g_Bdec[(size_t)MAXN * 128];

__device__ __forceinline__ unsigned h2_bits(__half2 h) {
    unsigned u;
    *(__half2*)&u = h;
    return u;
}
__device__ __forceinline__ __half2 bits_h2(unsigned u) {
    return *(__half2*)&u;
}
__device__ __forceinline__ uint32_t smem_u32(const void* p) {
    uint32_t a;
    asm("{ .reg .u64 t; cvta.to.shared.u64 t, %1; cvt.u32.u64 %0, t; }" : "=r"(a) : "l"(p));
    return a;
}

// ================= misc =================
__global__ void f2h_kernel(const float* __restrict__ in, __half* __restrict__ out, int n4) {
    int i = blockIdx.x * blockDim.x + threadIdx.x;
    if (i < n4) {
        float4 v = ((const float4*)in)[i];
        uint2 o;
        o.x = h2_bits(__floats2half2_rn(v.x, v.y));
        o.y = h2_bits(__floats2half2_rn(v.z, v.w));
        ((uint2*)out)[i] = o;
    }
}

// ================= CSR build =================
__global__ void zero_init_kernel(int N) {
    int i = blockIdx.x * blockDim.x + threadIdx.x;
    if (i < N) {
        g_deg1[i] = 0.f; g_cnt1[i] = 0; g_deg2[i] = 0;
        g_cur1[i] = 0; g_cur2[i] = 0;
    }
}

__global__ void deg_cnt_kernel(const int* __restrict__ ei, const float* __restrict__ w,
                               const int* __restrict__ nei, int E) {
    int e = blockIdx.x * blockDim.x + threadIdx.x;
    if (e < E) {
        int c1 = ei[E + e];
        atomicAdd(&g_deg1[c1], w[e]);
        atomicAdd(&g_cnt1[c1], 1);
        atomicAdd(&g_deg2[nei[E + e]], 1);
    }
}

__global__ __launch_bounds__(1024, 1)
void scan2_kernel(int N, int E) {
    __shared__ int warpTot[32];
    int tid = threadIdx.x;
    int lane = tid & 31, w = tid >> 5;
    int chunk = (N + 1023) / 1024;
    int beg = tid * chunk;
    int end = beg + chunk; if (end > N) end = N;
#pragma unroll 1
    for (int a = 0; a < 2; a++) {
        const int* c = a ? g_deg2 : g_cnt1;
        int* o = a ? g_off2 : g_off1;
        __syncthreads();
        int t = 0;
        for (int i = beg; i < end; i++) t += c[i];
        int v = t;
#pragma unroll
        for (int d = 1; d < 32; d <<= 1) {
            int u = __shfl_up_sync(0xffffffffu, v, d);
            if (lane >= d) v += u;
        }
        if (lane == 31) warpTot[w] = v;
        __syncthreads();
        if (w == 0) {
            int x = warpTot[lane];
#pragma unroll
            for (int d = 1; d < 32; d <<= 1) {
                int u = __shfl_up_sync(0xffffffffu, x, d);
                if (lane >= d) x += u;
            }
            warpTot[lane] = x;
        }
        __syncthreads();
        int run = v - t + (w > 0 ? warpTot[w - 1] : 0);
        for (int i = beg; i < end; i++) { o[i] = run; run += c[i]; }
    }
    if (tid == 0) { g_off1[N] = E; g_off2[N] = E; }
}

__global__ void fill_kernel(const int* __restrict__ ei, const int* __restrict__ nei,
                            const float* __restrict__ w, const int* __restrict__ node_ids,
                            int E) {
    int e = blockIdx.x * blockDim.x + threadIdx.x;
    if (e >= E) return;
    {
        int r = ei[e], c = ei[E + e];
        float dr = g_deg1[r], dc = g_deg1[c];
        float nrm = (dr > 0.f ? rsqrtf(dr) : 0.f) * w[e] * (dc > 0.f ? rsqrtf(dc) : 0.f);
        int p = g_off1[c] + atomicAdd(&g_cur1[c], 1);
        g_pair1[p] = make_int2(node_ids[r], __float_as_int(nrm));
    }
    {
        int r = nei[e], c = nei[E + e];
        float dr = (float)g_deg2[r], dc = (float)g_deg2[c];
        float nrm = (dr > 0.f ? rsqrtf(dr) : 0.f) * (dc > 0.f ? rsqrtf(dc) : 0.f);
        int p = g_off2[c] + atomicAdd(&g_cur2[c], 1);
        g_pair2[p] = make_int2(r, __float_as_int(nrm));
    }
}

// ---- gather-reduce from fp16 rows ----
__global__ void gather_f16_kernel(const __half* __restrict__ h, float* __restrict__ out,
                                  const int* __restrict__ off, const int2* __restrict__ pair,
                                  int N) {
    int gw = (blockIdx.x * blockDim.x + threadIdx.x) >> 5;
    if (gw >= N) return;
    int lane = threadIdx.x & 31;
    int s = off[gw], t = off[gw + 1];
    float4 acc0 = make_float4(0.f, 0.f, 0.f, 0.f);
    float4 acc1 = make_float4(0.f, 0.f, 0.f, 0.f);
    int i = s;
    for (; i + 2 <= t; i += 2) {
        int2 p0 = __ldg(pair + i), p1 = __ldg(pair + i + 1);
        float n0 = __int_as_float(p0.y), n1 = __int_as_float(p1.y);
        uint2 w0 = *(const uint2*)(h + (size_t)p0.x * 128 + lane * 4);
        uint2 w1 = *(const uint2*)(h + (size_t)p1.x * 128 + lane * 4);
        float2 v0a = __half22float2(bits_h2(w0.x)), v0b = __half22float2(bits_h2(w0.y));
        float2 v1a = __half22float2(bits_h2(w1.x)), v1b = __half22float2(bits_h2(w1.y));
        acc0.x = fmaf(v0a.x, n0, acc0.x); acc0.y = fmaf(v0a.y, n0, acc0.y);
        acc0.z = fmaf(v0b.x, n0, acc0.z); acc0.w = fmaf(v0b.y, n0, acc0.w);
        acc1.x = fmaf(v1a.x, n1, acc1.x); acc1.y = fmaf(v1a.y, n1, acc1.y);
        acc1.z = fmaf(v1b.x, n1, acc1.z); acc1.w = fmaf(v1b.y, n1, acc1.w);
    }
    if (i < t) {
        int2 p0 = __ldg(pair + i);
        float n0 = __int_as_float(p0.y);
        uint2 w0 = *(const uint2*)(h + (size_t)p0.x * 128 + lane * 4);
        float2 v0a = __half22float2(bits_h2(w0.x)), v0b = __half22float2(bits_h2(w0.y));
        acc0.x = fmaf(v0a.x, n0, acc0.x); acc0.y = fmaf(v0a.y, n0, acc0.y);
        acc0.z = fmaf(v0b.x, n0, acc0.z); acc0.w = fmaf(v0b.y, n0, acc0.w);
    }
    acc0.x += acc1.x; acc0.y += acc1.y; acc0.z += acc1.z; acc0.w += acc1.w;
    *(float4*)(out + (size_t)gw * 128 + lane * 4) = acc0;
}

// ================= fp16 mma.sync node GEMM (m16n8k16, hi/lo split) =================
// Block tile 128x128, 256 threads, BK=32. A staged [row][k] fp16 (80B stride,
// ldmatrix); W staged transposed [n][k] fp16 (84B stride, conflict-free LDS.32).
// SPLIT: 3-term hi/lo (AhWh + AhWl + AlWh) ~22-bit products.
#define A_STU 20   // u32 per A row (40 halves, 80 bytes)
#define W_STU 21   // u32 per W^T row (42 halves, 84 bytes)

template <int SPLIT, int PREACT, int DUAL, int OUTH>
__global__ __launch_bounds__(256, 1)
void gemm_fp16_kernel(const float* __restrict__ A, const float* __restrict__ W,
                      void* __restrict__ C, int M, int K, int Nc,
                      const float* __restrict__ bias, int act,
                      const float* __restrict__ abias,
                      const float* __restrict__ Wb, void* __restrict__ Cb) {
    extern __shared__ unsigned smg[];
    unsigned* Ahu = smg;                                   // 128*A_STU
    unsigned* Alu = Ahu + 128 * A_STU;                     // (SPLIT)
    unsigned* Whu = Alu + (SPLIT ? 128 * A_STU : 0);       // 128*W_STU
    unsigned* Wlu = Whu + 128 * W_STU;                     // (SPLIT)

    int tid = threadIdx.x;
    int warp = tid >> 5, lane = tid & 31;
    int qr = lane >> 2, qc = lane & 3;
    int m0 = blockIdx.y * 128;
    const float* Wp = W;
    void* Cp = C;
    int n0 = blockIdx.x * 128;
    if (DUAL) {
        if (blockIdx.x) { Wp = Wb; Cp = Cb; }
        n0 = 0;
    }
    int r0 = warp * 16;

    uint32_t Ah_s = smem_u32(Ahu);
    uint32_t Al_s = smem_u32(Alu);
    int laneRow = (lane & 7) + (lane & 8);
    int laneColB = ((lane >> 4) & 1) * 16;
    uint32_t lmH = Ah_s + (uint32_t)(r0 + laneRow) * 80 + (uint32_t)laneColB;
    uint32_t lmL = Al_s + (uint32_t)(r0 + laneRow) * 80 + (uint32_t)laneColB;

    float acc[16][4];
#pragma unroll
    for (int n = 0; n < 16; n++)
#pragma unroll
        for (int j = 0; j < 4; j++) acc[n][j] = 0.f;

    for (int kt = 0; kt < K; kt += 32) {
        // stage A tile: 128 rows x 32 k
#pragma unroll
        for (int i = 0; i < 4; i++) {
            int idx4 = tid + i * 256;
            int row = idx4 >> 3;
            int col = (idx4 & 7) << 2;
            float4 v = make_float4(0.f, 0.f, 0.f, 0.f);
            if (m0 + row < M) v = *(const float4*)(A + (size_t)(m0 + row) * K + kt + col);
            if (PREACT) {
                float4 ab = *(const float4*)(abias + kt + col);
                v.x += ab.x; v.y += ab.y; v.z += ab.z; v.w += ab.w;
                v.x = v.x > 0.f ? v.x : expm1f(v.x);
                v.y = v.y > 0.f ? v.y : expm1f(v.y);
                v.z = v.z > 0.f ? v.z : expm1f(v.z);
                v.w = v.w > 0.f ? v.w : expm1f(v.w);
            }
            __half h0 = __float2half_rn(v.x), h1 = __float2half_rn(v.y);
            __half h2_ = __float2half_rn(v.z), h3 = __float2half_rn(v.w);
            Ahu[row * A_STU + (col >> 1)] = h2_bits(__halves2half2(h0, h1));
            Ahu[row * A_STU + (col >> 1) + 1] = h2_bits(__halves2half2(h2_, h3));
            if (SPLIT) {
                __half l0 = __float2half_rn(v.x - __half2float(h0));
                __half l1 = __float2half_rn(v.y - __half2float(h1));
                __half l2 = __float2half_rn(v.z - __half2float(h2_));
                __half l3 = __float2half_rn(v.w - __half2float(h3));
                Alu[row * A_STU + (col >> 1)] = h2_bits(__halves2half2(l0, l1));
                Alu[row * A_STU + (col >> 1) + 1] = h2_bits(__halves2half2(l2, l3));
            }
        }
        // stage W^T tile: [n][k] halves; each thread handles 4 n x 2 k
#pragma unroll
        for (int i = 0; i < 2; i++) {
            int idx4 = tid + i * 256;
            int k2 = idx4 >> 5;                 // 0..15 -> k = 2*k2
            int ncol = (idx4 & 31) << 2;        // 0..124
            const float* wp0 = Wp + (size_t)(kt + 2 * k2) * Nc + n0 + ncol;
            const float* wp1 = wp0 + Nc;
            float4 va = *(const float4*)wp0;
            float4 vb = *(const float4*)wp1;
            float fa[4] = {va.x, va.y, va.z, va.w};
            float fb[4] = {vb.x, vb.y, vb.z, vb.w};
#pragma unroll
            for (int j = 0; j < 4; j++) {
                __half ha = __float2half_rn(fa[j]), hb = __float2half_rn(fb[j]);
                Whu[(ncol + j) * W_STU + k2] = h2_bits(__halves2half2(ha, hb));
                if (SPLIT) {
                    __half la = __float2half_rn(fa[j] - __half2float(ha));
                    __half lb = __float2half_rn(fb[j] - __half2float(hb));
                    Wlu[(ncol + j) * W_STU + k2] = h2_bits(__halves2half2(la, lb));
                }
            }
        }
        __syncthreads();

#pragma unroll
        for (int kk = 0; kk < 2; kk++) {
            unsigned ah0, ah1, ah2, ah3, al0, al1, al2, al3;
            asm volatile(
                "ldmatrix.sync.aligned.m8n8.x4.shared.b16 {%0,%1,%2,%3}, [%4];"
                : "=r"(ah0), "=r"(ah1), "=r"(ah2), "=r"(ah3)
                : "r"(lmH + (uint32_t)kk * 32));
            if (SPLIT) {
                asm volatile(
                    "ldmatrix.sync.aligned.m8n8.x4.shared.b16 {%0,%1,%2,%3}, [%4];"
                    : "=r"(al0), "=r"(al1), "=r"(al2), "=r"(al3)
                    : "r"(lmL + (uint32_t)kk * 32));
            }
#pragma unroll
            for (int nc = 0; nc < 16; nc++) {
                int widx = (nc * 8 + qr) * W_STU + kk * 8 + qc;
                unsigned bh0 = Whu[widx];
                unsigned bh1 = Whu[widx + 4];
                asm volatile(
                    "mma.sync.aligned.m16n8k16.row.col.f32.f16.f16.f32 "
                    "{%0,%1,%2,%3}, {%4,%5,%6,%7}, {%8,%9}, {%0,%1,%2,%3};"
                    : "+f"(acc[nc][0]), "+f"(acc[nc][1]), "+f"(acc[nc][2]), "+f"(acc[nc][3])
                    : "r"(ah0), "r"(ah1), "r"(ah2), "r"(ah3), "r"(bh0), "r"(bh1));
                if (SPLIT) {
                    unsigned bl0 = Wlu[widx];
                    unsigned bl1 = Wlu[widx + 4];
                    asm volatile(
                        "mma.sync.aligned.m16n8k16.row.col.f32.f16.f16.f32 "
                        "{%0,%1,%2,%3}, {%4,%5,%6,%7}, {%8,%9}, {%0,%1,%2,%3};"
                        : "+f"(acc[nc][0]), "+f"(acc[nc][1]), "+f"(acc[nc][2]), "+f"(acc[nc][3])
                        : "r"(ah0), "r"(ah1), "r"(ah2), "r"(ah3), "r"(bl0), "r"(bl1));
                    asm volatile(
                        "mma.sync.aligned.m16n8k16.row.col.f32.f16.f16.f32 "
                        "{%0,%1,%2,%3}, {%4,%5,%6,%7}, {%8,%9}, {%0,%1,%2,%3};"
                        : "+f"(acc[nc][0]), "+f"(acc[nc][1]), "+f"(acc[nc][2]), "+f"(acc[nc][3])
                        : "r"(al0), "r"(al1), "r"(al2), "r"(al3), "r"(bh0), "r"(bh1));
                }
            }
        }
        __syncthreads();
    }

    int row0 = m0 + r0 + qr;
    int row1 = row0 + 8;
#pragma unroll
    for (int nc = 0; nc < 16; nc++) {
        int c0 = n0 + nc * 8 + qc * 2;
        float bz0 = 0.f, bz1 = 0.f;
        if (bias) { bz0 = __ldg(bias + c0); bz1 = __ldg(bias + c0 + 1); }
        float u0 = acc[nc][0] + bz0, u1 = acc[nc][1] + bz1;
        float u2 = acc[nc][2] + bz0, u3 = acc[nc][3] + bz1;
        if (act) {
            u0 = u0 > 0.f ? u0 : expm1f(u0);
            u1 = u1 > 0.f ? u1 : expm1f(u1);
            u2 = u2 > 0.f ? u2 : expm1f(u2);
            u3 = u3 > 0.f ? u3 : expm1f(u3);
        }
        if (OUTH) {
            if (row0 < M) *(__half2*)((__half*)Cp + (size_t)row0 * Nc + c0) = __floats2half2_rn(u0, u1);
            if (row1 < M) *(__half2*)((__half*)Cp + (size_t)row1 * Nc + c0) = __floats2half2_rn(u2, u3);
        } else {
            if (row0 < M) *(float2*)((float*)Cp + (size_t)row0 * Nc + c0) = make_float2(u0, u1);
            if (row1 < M) *(float2*)((float*)Cp + (size_t)row1 * Nc + c0) = make_float2(u2, u3);
        }
    }
}

// ============================================================================
// Persistent fp16 edge decoder (mma.sync m16n8k16.f16, ldmatrix A-fragments)
// ============================================================================
#define TS_HW 68   // u32 words per t row (136 halves; row stride 272 bytes)

__global__ __launch_bounds__(256, 3)
void decoder_fp16_kernel(const __half* __restrict__ Ad, const __half* __restrict__ Bd,
                         const int* __restrict__ ei,
                         const float* __restrict__ b1, const float* __restrict__ W2,
                         const float* __restrict__ b2, const float* __restrict__ W3,
                         const float* __restrict__ b3, float* __restrict__ out,
                         int E, int numTiles) {
    extern __shared__ unsigned smemd[];
    unsigned* tS = smemd;
    float* b1s = (float*)(smemd + 128 * TS_HW);
    float* esum = b1s + 128;
    int tid = threadIdx.x;
    int warp = tid >> 5, lane = tid & 31;
    int qr = lane >> 2, qc = lane & 3;
    int nBase = warp * 16;
    uint32_t tS_s = smem_u32(tS);
    int laneRow = (lane & 7) + (lane & 8);
    int laneColB = ((lane >> 4) & 1) * 16;
    uint32_t lmBase = tS_s + (uint32_t)laneRow * 272 + (uint32_t)laneColB;

    unsigned bf[8][2][2];
#pragma unroll
    for (int c = 0; c < 8; c++) {
        int kb = c * 16;
#pragma unroll
        for (int ncl = 0; ncl < 2; ncl++) {
            int n = nBase + ncl * 8 + qr;
            bf[c][ncl][0] = h2_bits(__floats2half2_rn(
                __ldg(W2 + (kb + 2 * qc) * 128 + n), __ldg(W2 + (kb + 2 * qc + 1) * 128 + n)));
            bf[c][ncl][1] = h2_bits(__floats2half2_rn(
                __ldg(W2 + (kb + 2 * qc + 8) * 128 + n), __ldg(W2 + (kb + 2 * qc + 9) * 128 + n)));
        }
    }
    float bb0[2], bb1[2], w30[2], w31[2];
#pragma unroll
    for (int ncl = 0; ncl < 2; ncl++) {
        int c0 = nBase + ncl * 8 + qc * 2;
        bb0[ncl] = __ldg(b2 + c0); bb1[ncl] = __ldg(b2 + c0 + 1);
        w30[ncl] = __ldg(W3 + c0); w31[ncl] = __ldg(W3 + c0 + 1);
    }
    float b3v = __ldg(b3);
    if (tid < 128) b1s[tid] = __ldg(b1 + tid);
    __syncthreads();

    for (int tile = blockIdx.x; tile < numTiles; tile += gridDim.x) {
        int eBase = tile * 128;
        __syncthreads();

        {
            int eloc = tid >> 1;
            int half_ = tid & 1;
            int e = eBase + eloc;
            unsigned* trow = tS + eloc * TS_HW + half_ * 32;
            if (e < E) {
                int s = ei[e], d = ei[E + e];
                const uint4* ap = (const uint4*)(Ad + (size_t)s * 128) + half_ * 8;
                const uint4* bp = (const uint4*)(Bd + (size_t)d * 128) + half_ * 8;
#pragma unroll
                for (int j = 0; j < 8; j++) {
                    uint4 av = __ldg(ap + j);
                    uint4 bv = __ldg(bp + j);
                    const float* bb = b1s + half_ * 64 + j * 8;
                    unsigned aw[4] = {av.x, av.y, av.z, av.w};
                    unsigned bw[4] = {bv.x, bv.y, bv.z, bv.w};
#pragma unroll
                    for (int w = 0; w < 4; w++) {
                        float2 af = __half22float2(bits_h2(aw[w]));
                        float2 bf2 = __half22float2(bits_h2(bw[w]));
                        float v0 = fmaxf(af.x + bf2.x + bb[2 * w], 0.f);
                        float v1 = fmaxf(af.y + bf2.y + bb[2 * w + 1], 0.f);
                        trow[j * 4 + w] = h2_bits(__floats2half2_rn(v0, v1));
                    }
                }
            } else {
#pragma unroll
                for (int j = 0; j < 32; j++) trow[j] = 0u;
            }
            if (tid < 128) esum[tid] = 0.f;
        }
        __syncthreads();

#pragma unroll 1
        for (int m = 0; m < 8; m++) {
            int r0 = m * 16;
            uint32_t rowAddr = lmBase + (uint32_t)r0 * 272;
            float acc[2][4];
            acc[0][0] = acc[0][1] = acc[0][2] = acc[0][3] = 0.f;
            acc[1][0] = acc[1][1] = acc[1][2] = acc[1][3] = 0.f;
#pragma unroll
            for (int c = 0; c < 8; c++) {
                unsigned a0, a1, a2, a3;
                asm volatile(
                    "ldmatrix.sync.aligned.m8n8.x4.shared.b16 {%0,%1,%2,%3}, [%4];"
                    : "=r"(a0), "=r"(a1), "=r"(a2), "=r"(a3)
                    : "r"(rowAddr + (uint32_t)c * 32));
                asm volatile(
                    "mma.sync.aligned.m16n8k16.row.col.f32.f16.f16.f32 "
                    "{%0,%1,%2,%3}, {%4,%5,%6,%7}, {%8,%9}, {%0,%1,%2,%3};"
                    : "+f"(acc[0][0]), "+f"(acc[0][1]), "+f"(acc[0][2]), "+f"(acc[0][3])
                    : "r"(a0), "r"(a1), "r"(a2), "r"(a3), "r"(bf[c][0][0]), "r"(bf[c][0][1]));
                asm volatile(
                    "mma.sync.aligned.m16n8k16.row.col.f32.f16.f16.f32 "
                    "{%0,%1,%2,%3}, {%4,%5,%6,%7}, {%8,%9}, {%0,%1,%2,%3};"
                    : "+f"(acc[1][0]), "+f"(acc[1][1]), "+f"(acc[1][2]), "+f"(acc[1][3])
                    : "r"(a0), "r"(a1), "r"(a2), "r"(a3), "r"(bf[c][1][0]), "r"(bf[c][1][1]));
            }
            float e0 = 0.f, e1 = 0.f;
#pragma unroll
            for (int ncl = 0; ncl < 2; ncl++) {
                e0 += fmaxf(acc[ncl][0] + bb0[ncl], 0.f) * w30[ncl]
                    + fmaxf(acc[ncl][1] + bb1[ncl], 0.f) * w31[ncl];
                e1 += fmaxf(acc[ncl][2] + bb0[ncl], 0.f) * w30[ncl]
                    + fmaxf(acc[ncl][3] + bb1[ncl], 0.f) * w31[ncl];
            }
            e0 += __shfl_xor_sync(0xffffffffu, e0, 1);
            e0 += __shfl_xor_sync(0xffffffffu, e0, 2);
            e1 += __shfl_xor_sync(0xffffffffu, e1, 1);
            e1 += __shfl_xor_sync(0xffffffffu, e1, 2);
            if (qc == 0) {
                atomicAdd(&esum[r0 + qr], e0);
                atomicAdd(&esum[r0 + qr + 8], e1);
            }
        }
        __syncthreads();

        if (tid < 128) {
            int e = eBase + tid;
            if (e < E) out[e] = esum[tid] + b3v;
        }
    }
}

extern "C" void kernel_launch(void* const* d_in, const int* in_sizes, int n_in,
                              void* d_out, int out_size) {
    const int* node_ids = (const int*)d_in[0];
    const int* ei       = (const int*)d_in[1];
    const int* nei      = (const int*)d_in[2];
    const float* eattr  = (const float*)d_in[3];
    const float* emb    = (const float*)d_in[4];
    const float* W_in   = (const float*)d_in[5];
    const float* b_in   = (const float*)d_in[6];
    const float* W_out  = (const float*)d_in[7];
    const float* b_out  = (const float*)d_in[8];
    const float* W1     = (const float*)d_in[9];
    const float* b1     = (const float*)d_in[10];
    const float* W2     = (const float*)d_in[11];
    const float* b2     = (const float*)d_in[12];
    const float* W3     = (const float*)d_in[13];
    const float* b3     = (const float*)d_in[14];
    int N = in_sizes[0];
    int E = in_sizes[3];
    float* out = (float*)d_out;

    float *agg1, *x1, *x2;
    __half *embh, *h2h, *Ad, *Bd;
    int *off1, *off2;
    int2 *pair1, *pair2;
    cudaGetSymbolAddress((void**)&embh, g_embh);
    cudaGetSymbolAddress((void**)&agg1, g_agg1);
    cudaGetSymbolAddress((void**)&x1, g_x1);
    cudaGetSymbolAddress((void**)&h2h, g_h2h);
    cudaGetSymbolAddress((void**)&x2, g_x2);
    cudaGetSymbolAddress((void**)&Ad, g_Adec);
    cudaGetSymbolAddress((void**)&Bd, g_Bdec);
    cudaGetSymbolAddress((void**)&off1, g_off1);
    cudaGetSymbolAddress((void**)&off2, g_off2);
    cudaGetSymbolAddress((void**)&pair1, g_pair1);
    cudaGetSymbolAddress((void**)&pair2, g_pair2);

    const int T = 256;
    zero_init_kernel<<<(N + T - 1) / T, T>>>(N);
    deg_cnt_kernel<<<(E + T - 1) / T, T>>>(ei, eattr, nei, E);
    scan2_kernel<<<1, 1024>>>(N, E);
    fill_kernel<<<(E + T - 1) / T, T>>>(ei, nei, eattr, node_ids, E);
    f2h_kernel<<<(N * 32 + T - 1) / T, T>>>(emb, embh, N * 32);

    int mBlocks = (N + 127) / 128;
    int smem_split = (128 * A_STU * 2 + 128 * W_STU * 2) * 4;
    cudaFuncSetAttribute((const void*)gemm_fp16_kernel<1, 0, 0, 0>,
                         cudaFuncAttributeMaxDynamicSharedMemorySize, smem_split);
    cudaFuncSetAttribute((const void*)gemm_fp16_kernel<1, 0, 0, 1>,
                         cudaFuncAttributeMaxDynamicSharedMemorySize, smem_split);
    cudaFuncSetAttribute((const void*)gemm_fp16_kernel<1, 1, 1, 1>,
                         cudaFuncAttributeMaxDynamicSharedMemorySize, smem_split);

    int gatherBlocks = (N * 32 + T - 1) / T;

    // conv1: fp16 gather-aggregate emb, then fp16-split GEMM with fused bias+elu
    gather_f16_kernel<<<gatherBlocks, T>>>(embh, agg1, off1, pair1, N);
    gemm_fp16_kernel<1, 0, 0, 0><<<dim3(2, mBlocks), 256, smem_split>>>(
        agg1, W_in, x1, N, 128, 256, b_in, 1, nullptr, nullptr, nullptr);

    // conv2: fp16-split GEMM (fp16 out) then fp16 gather-aggregate
    gemm_fp16_kernel<1, 0, 0, 1><<<dim3(1, mBlocks), 256, smem_split>>>(
        x1, W_out, h2h, N, 256, 128, nullptr, 0, nullptr, nullptr, nullptr);
    gather_f16_kernel<<<gatherBlocks, T>>>(h2h, x2, off2, pair2, N);

    // merged dual pre-GEMMs (fp16 split; elu(x2+b_out) fused on A, fp16 outputs)
    gemm_fp16_kernel<1, 1, 1, 1><<<dim3(2, mBlocks), 256, smem_split>>>(
        x2, W1, Ad, N, 128, 128, nullptr, 0, b_out, W1 + 128 * 128, Bd);

    // persistent fp16 tensor-core edge decoder
    int numTiles = (E + 127) / 128;
    int smem_dec = (128 * TS_HW + 256) * 4;
    cudaFuncSetAttribute(decoder_fp16_kernel, cudaFuncAttributeMaxDynamicSharedMemorySize, smem_dec);
    int grid_dec = 3 * 148;
    if (grid_dec > numTiles) grid_dec = numTiles;
    decoder_fp16_kernel<<<grid_dec, 256, smem_dec>>>(Ad, Bd, ei, b1, W2, b2, W3, b3, out, E, numTiles);
}

// round 13
// speedup vs baseline: 2.6937x; 1.0216x over previous
#include <cuda_runtime.h>
#include <cuda_fp16.h>
#include <math.h>
#include <stdint.h>

#define MAXN 50000
#define MAXE 800000

// ---- scratch (device globals; no allocation allowed) ----
__device__ float g_deg1[MAXN];
__device__ int   g_cnt1[MAXN];
__device__ int   g_deg2[MAXN];
__device__ int   g_off1[MAXN + 1];
__device__ int   g_off2[MAXN + 1];
__device__ int   g_cur1[MAXN];
__device__ int   g_cur2[MAXN];
__device__ int2  g_pair1[MAXE];
__device__ int2  g_pair2[MAXE];
__device__ __half g_embh[(size_t)MAXN * 128];
__device__ float g_agg1[(size_t)MAXN * 128];
__device__ float g_x1[(size_t)MAXN * 256];
__device__ __half g_h2h[(size_t)MAXN * 128];
__device__ float g_x2[(size_t)MAXN * 128];
__device__ __half g_Adec[(size_t)MAXN * 128];
__device__ __half g_Bdec[(size_t)MAXN * 128];

__device__ __forceinline__ unsigned h2_bits(__half2 h) {
    unsigned u;
    *(__half2*)&u = h;
    return u;
}
__device__ __forceinline__ __half2 bits_h2(unsigned u) {
    return *(__half2*)&u;
}
__device__ __forceinline__ uint32_t smem_u32(const void* p) {
    uint32_t a;
    asm("{ .reg .u64 t; cvta.to.shared.u64 t, %1; cvt.u32.u64 %0, t; }" : "=r"(a) : "l"(p));
    return a;
}

// ================= fused zero-init + emb fp16 conversion =================
__global__ void init_f2h_kernel(const float* __restrict__ emb, __half* __restrict__ embh,
                                int N, int n4) {
    int i = blockIdx.x * blockDim.x + threadIdx.x;
    if (i < N) {
        g_deg1[i] = 0.f; g_cnt1[i] = 0; g_deg2[i] = 0;
        g_cur1[i] = 0; g_cur2[i] = 0;
    }
    for (int j = i; j < n4; j += gridDim.x * blockDim.x) {
        float4 v = ((const float4*)emb)[j];
        uint2 o;
        o.x = h2_bits(__floats2half2_rn(v.x, v.y));
        o.y = h2_bits(__floats2half2_rn(v.z, v.w));
        ((uint2*)embh)[j] = o;
    }
}

// ================= CSR build =================
__global__ void deg_cnt_kernel(const int* __restrict__ ei, const float* __restrict__ w,
                               const int* __restrict__ nei, int E) {
    int e = blockIdx.x * blockDim.x + threadIdx.x;
    if (e < E) {
        int c1 = ei[E + e];
        atomicAdd(&g_deg1[c1], w[e]);
        atomicAdd(&g_cnt1[c1], 1);
        atomicAdd(&g_deg2[nei[E + e]], 1);
    }
}

__global__ __launch_bounds__(1024, 1)
void scan2_kernel(int N, int E) {
    __shared__ int warpTot[32];
    int tid = threadIdx.x;
    int lane = tid & 31, w = tid >> 5;
    int chunk = (N + 1023) / 1024;
    int beg = tid * chunk;
    int end = beg + chunk; if (end > N) end = N;
#pragma unroll 1
    for (int a = 0; a < 2; a++) {
        const int* c = a ? g_deg2 : g_cnt1;
        int* o = a ? g_off2 : g_off1;
        __syncthreads();
        int t = 0;
        for (int i = beg; i < end; i++) t += c[i];
        int v = t;
#pragma unroll
        for (int d = 1; d < 32; d <<= 1) {
            int u = __shfl_up_sync(0xffffffffu, v, d);
            if (lane >= d) v += u;
        }
        if (lane == 31) warpTot[w] = v;
        __syncthreads();
        if (w == 0) {
            int x = warpTot[lane];
#pragma unroll
            for (int d = 1; d < 32; d <<= 1) {
                int u = __shfl_up_sync(0xffffffffu, x, d);
                if (lane >= d) x += u;
            }
            warpTot[lane] = x;
        }
        __syncthreads();
        int run = v - t + (w > 0 ? warpTot[w - 1] : 0);
        for (int i = beg; i < end; i++) { o[i] = run; run += c[i]; }
    }
    if (tid == 0) { g_off1[N] = E; g_off2[N] = E; }
}

__global__ void fill_kernel(const int* __restrict__ ei, const int* __restrict__ nei,
                            const float* __restrict__ w, const int* __restrict__ node_ids,
                            int E) {
    int e = blockIdx.x * blockDim.x + threadIdx.x;
    if (e >= E) return;
    {
        int r = ei[e], c = ei[E + e];
        float dr = g_deg1[r], dc = g_deg1[c];
        float nrm = (dr > 0.f ? rsqrtf(dr) : 0.f) * w[e] * (dc > 0.f ? rsqrtf(dc) : 0.f);
        int p = g_off1[c] + atomicAdd(&g_cur1[c], 1);
        g_pair1[p] = make_int2(node_ids[r], __float_as_int(nrm));
    }
    {
        int r = nei[e], c = nei[E + e];
        float dr = (float)g_deg2[r], dc = (float)g_deg2[c];
        float nrm = (dr > 0.f ? rsqrtf(dr) : 0.f) * (dc > 0.f ? rsqrtf(dc) : 0.f);
        int p = g_off2[c] + atomicAdd(&g_cur2[c], 1);
        g_pair2[p] = make_int2(r, __float_as_int(nrm));
    }
}

// ---- gather-reduce from fp16 rows, unroll-4 for MLP ----
__global__ void gather_f16_kernel(const __half* __restrict__ h, float* __restrict__ out,
                                  const int* __restrict__ off, const int2* __restrict__ pair,
                                  int N) {
    int gw = (blockIdx.x * blockDim.x + threadIdx.x) >> 5;
    if (gw >= N) return;
    int lane = threadIdx.x & 31;
    int s = off[gw], t = off[gw + 1];
    float4 acc0 = make_float4(0.f, 0.f, 0.f, 0.f);
    float4 acc1 = make_float4(0.f, 0.f, 0.f, 0.f);
    int i = s;
#define GF16_STEP(P, W, ACC)                                                   \
    {                                                                          \
        float nn = __int_as_float((P).y);                                      \
        float2 va = __half22float2(bits_h2((W).x));                            \
        float2 vb = __half22float2(bits_h2((W).y));                            \
        ACC.x = fmaf(va.x, nn, ACC.x); ACC.y = fmaf(va.y, nn, ACC.y);          \
        ACC.z = fmaf(vb.x, nn, ACC.z); ACC.w = fmaf(vb.y, nn, ACC.w);          \
    }
    for (; i + 4 <= t; i += 4) {
        int2 p0 = __ldg(pair + i), p1 = __ldg(pair + i + 1);
        int2 p2 = __ldg(pair + i + 2), p3 = __ldg(pair + i + 3);
        uint2 w0 = *(const uint2*)(h + (size_t)p0.x * 128 + lane * 4);
        uint2 w1 = *(const uint2*)(h + (size_t)p1.x * 128 + lane * 4);
        uint2 w2 = *(const uint2*)(h + (size_t)p2.x * 128 + lane * 4);
        uint2 w3 = *(const uint2*)(h + (size_t)p3.x * 128 + lane * 4);
        GF16_STEP(p0, w0, acc0) GF16_STEP(p1, w1, acc1)
        GF16_STEP(p2, w2, acc0) GF16_STEP(p3, w3, acc1)
    }
    for (; i + 2 <= t; i += 2) {
        int2 p0 = __ldg(pair + i), p1 = __ldg(pair + i + 1);
        uint2 w0 = *(const uint2*)(h + (size_t)p0.x * 128 + lane * 4);
        uint2 w1 = *(const uint2*)(h + (size_t)p1.x * 128 + lane * 4);
        GF16_STEP(p0, w0, acc0) GF16_STEP(p1, w1, acc1)
    }
    if (i < t) {
        int2 p0 = __ldg(pair + i);
        uint2 w0 = *(const uint2*)(h + (size_t)p0.x * 128 + lane * 4);
        GF16_STEP(p0, w0, acc0)
    }
#undef GF16_STEP
    acc0.x += acc1.x; acc0.y += acc1.y; acc0.z += acc1.z; acc0.w += acc1.w;
    *(float4*)(out + (size_t)gw * 128 + lane * 4) = acc0;
}

// ================= fp16 mma.sync node GEMM (m16n8k16, hi/lo split) =================
#define A_STU 20   // u32 per A row (40 halves, 80 bytes)
#define W_STU 21   // u32 per W^T row (42 halves, 84 bytes)

template <int SPLIT, int PREACT, int DUAL, int OUTH>
__global__ __launch_bounds__(256, 1)
void gemm_fp16_kernel(const float* __restrict__ A, const float* __restrict__ W,
                      void* __restrict__ C, int M, int K, int Nc,
                      const float* __restrict__ bias, int act,
                      const float* __restrict__ abias,
                      const float* __restrict__ Wb, void* __restrict__ Cb) {
    extern __shared__ unsigned smg[];
    unsigned* Ahu = smg;
    unsigned* Alu = Ahu + 128 * A_STU;
    unsigned* Whu = Alu + (SPLIT ? 128 * A_STU : 0);
    unsigned* Wlu = Whu + 128 * W_STU;

    int tid = threadIdx.x;
    int warp = tid >> 5, lane = tid & 31;
    int qr = lane >> 2, qc = lane & 3;
    int m0 = blockIdx.y * 128;
    const float* Wp = W;
    void* Cp = C;
    int n0 = blockIdx.x * 128;
    if (DUAL) {
        if (blockIdx.x) { Wp = Wb; Cp = Cb; }
        n0 = 0;
    }
    int r0 = warp * 16;

    uint32_t Ah_s = smem_u32(Ahu);
    uint32_t Al_s = smem_u32(Alu);
    int laneRow = (lane & 7) + (lane & 8);
    int laneColB = ((lane >> 4) & 1) * 16;
    uint32_t lmH = Ah_s + (uint32_t)(r0 + laneRow) * 80 + (uint32_t)laneColB;
    uint32_t lmL = Al_s + (uint32_t)(r0 + laneRow) * 80 + (uint32_t)laneColB;

    float acc[16][4];
#pragma unroll
    for (int n = 0; n < 16; n++)
#pragma unroll
        for (int j = 0; j < 4; j++) acc[n][j] = 0.f;

    for (int kt = 0; kt < K; kt += 32) {
#pragma unroll
        for (int i = 0; i < 4; i++) {
            int idx4 = tid + i * 256;
            int row = idx4 >> 3;
            int col = (idx4 & 7) << 2;
            float4 v = make_float4(0.f, 0.f, 0.f, 0.f);
            if (m0 + row < M) v = *(const float4*)(A + (size_t)(m0 + row) * K + kt + col);
            if (PREACT) {
                float4 ab = *(const float4*)(abias + kt + col);
                v.x += ab.x; v.y += ab.y; v.z += ab.z; v.w += ab.w;
                v.x = v.x > 0.f ? v.x : expm1f(v.x);
                v.y = v.y > 0.f ? v.y : expm1f(v.y);
                v.z = v.z > 0.f ? v.z : expm1f(v.z);
                v.w = v.w > 0.f ? v.w : expm1f(v.w);
            }
            __half h0 = __float2half_rn(v.x), h1 = __float2half_rn(v.y);
            __half h2_ = __float2half_rn(v.z), h3 = __float2half_rn(v.w);
            Ahu[row * A_STU + (col >> 1)] = h2_bits(__halves2half2(h0, h1));
            Ahu[row * A_STU + (col >> 1) + 1] = h2_bits(__halves2half2(h2_, h3));
            if (SPLIT) {
                __half l0 = __float2half_rn(v.x - __half2float(h0));
                __half l1 = __float2half_rn(v.y - __half2float(h1));
                __half l2 = __float2half_rn(v.z - __half2float(h2_));
                __half l3 = __float2half_rn(v.w - __half2float(h3));
                Alu[row * A_STU + (col >> 1)] = h2_bits(__halves2half2(l0, l1));
                Alu[row * A_STU + (col >> 1) + 1] = h2_bits(__halves2half2(l2, l3));
            }
        }
#pragma unroll
        for (int i = 0; i < 2; i++) {
            int idx4 = tid + i * 256;
            int k2 = idx4 >> 5;
            int ncol = (idx4 & 31) << 2;
            const float* wp0 = Wp + (size_t)(kt + 2 * k2) * Nc + n0 + ncol;
            const float* wp1 = wp0 + Nc;
            float4 va = *(const float4*)wp0;
            float4 vb = *(const float4*)wp1;
            float fa[4] = {va.x, va.y, va.z, va.w};
            float fb[4] = {vb.x, vb.y, vb.z, vb.w};
#pragma unroll
            for (int j = 0; j < 4; j++) {
                __half ha = __float2half_rn(fa[j]), hb = __float2half_rn(fb[j]);
                Whu[(ncol + j) * W_STU + k2] = h2_bits(__halves2half2(ha, hb));
                if (SPLIT) {
                    __half la = __float2half_rn(fa[j] - __half2float(ha));
                    __half lb = __float2half_rn(fb[j] - __half2float(hb));
                    Wlu[(ncol + j) * W_STU + k2] = h2_bits(__halves2half2(la, lb));
                }
            }
        }
        __syncthreads();

#pragma unroll
        for (int kk = 0; kk < 2; kk++) {
            unsigned ah0, ah1, ah2, ah3, al0, al1, al2, al3;
            asm volatile(
                "ldmatrix.sync.aligned.m8n8.x4.shared.b16 {%0,%1,%2,%3}, [%4];"
                : "=r"(ah0), "=r"(ah1), "=r"(ah2), "=r"(ah3)
                : "r"(lmH + (uint32_t)kk * 32));
            if (SPLIT) {
                asm volatile(
                    "ldmatrix.sync.aligned.m8n8.x4.shared.b16 {%0,%1,%2,%3}, [%4];"
                    : "=r"(al0), "=r"(al1), "=r"(al2), "=r"(al3)
                    : "r"(lmL + (uint32_t)kk * 32));
            }
#pragma unroll
            for (int nc = 0; nc < 16; nc++) {
                int widx = (nc * 8 + qr) * W_STU + kk * 8 + qc;
                unsigned bh0 = Whu[widx];
                unsigned bh1 = Whu[widx + 4];
                asm volatile(
                    "mma.sync.aligned.m16n8k16.row.col.f32.f16.f16.f32 "
                    "{%0,%1,%2,%3}, {%4,%5,%6,%7}, {%8,%9}, {%0,%1,%2,%3};"
                    : "+f"(acc[nc][0]), "+f"(acc[nc][1]), "+f"(acc[nc][2]), "+f"(acc[nc][3])
                    : "r"(ah0), "r"(ah1), "r"(ah2), "r"(ah3), "r"(bh0), "r"(bh1));
                if (SPLIT) {
                    unsigned bl0 = Wlu[widx];
                    unsigned bl1 = Wlu[widx + 4];
                    asm volatile(
                        "mma.sync.aligned.m16n8k16.row.col.f32.f16.f16.f32 "
                        "{%0,%1,%2,%3}, {%4,%5,%6,%7}, {%8,%9}, {%0,%1,%2,%3};"
                        : "+f"(acc[nc][0]), "+f"(acc[nc][1]), "+f"(acc[nc][2]), "+f"(acc[nc][3])
                        : "r"(ah0), "r"(ah1), "r"(ah2), "r"(ah3), "r"(bl0), "r"(bl1));
                    asm volatile(
                        "mma.sync.aligned.m16n8k16.row.col.f32.f16.f16.f32 "
                        "{%0,%1,%2,%3}, {%4,%5,%6,%7}, {%8,%9}, {%0,%1,%2,%3};"
                        : "+f"(acc[nc][0]), "+f"(acc[nc][1]), "+f"(acc[nc][2]), "+f"(acc[nc][3])
                        : "r"(al0), "r"(al1), "r"(al2), "r"(al3), "r"(bh0), "r"(bh1));
                }
            }
        }
        __syncthreads();
    }

    int row0 = m0 + r0 + qr;
    int row1 = row0 + 8;
#pragma unroll
    for (int nc = 0; nc < 16; nc++) {
        int c0 = n0 + nc * 8 + qc * 2;
        float bz0 = 0.f, bz1 = 0.f;
        if (bias) { bz0 = __ldg(bias + c0); bz1 = __ldg(bias + c0 + 1); }
        float u0 = acc[nc][0] + bz0, u1 = acc[nc][1] + bz1;
        float u2 = acc[nc][2] + bz0, u3 = acc[nc][3] + bz1;
        if (act) {
            u0 = u0 > 0.f ? u0 : expm1f(u0);
            u1 = u1 > 0.f ? u1 : expm1f(u1);
            u2 = u2 > 0.f ? u2 : expm1f(u2);
            u3 = u3 > 0.f ? u3 : expm1f(u3);
        }
        if (OUTH) {
            if (row0 < M) *(__half2*)((__half*)Cp + (size_t)row0 * Nc + c0) = __floats2half2_rn(u0, u1);
            if (row1 < M) *(__half2*)((__half*)Cp + (size_t)row1 * Nc + c0) = __floats2half2_rn(u2, u3);
        } else {
            if (row0 < M) *(float2*)((float*)Cp + (size_t)row0 * Nc + c0) = make_float2(u0, u1);
            if (row1 < M) *(float2*)((float*)Cp + (size_t)row1 * Nc + c0) = make_float2(u2, u3);
        }
    }
}

// ============================================================================
// Persistent fp16 edge decoder (mma.sync m16n8k16.f16, ldmatrix A-fragments,
// half2 phase-1 staging with vectorized STS.128)
// ============================================================================
#define TS_HW 68   // u32 words per t row (136 halves; row stride 272 bytes)

__global__ __launch_bounds__(256, 3)
void decoder_fp16_kernel(const __half* __restrict__ Ad, const __half* __restrict__ Bd,
                         const int* __restrict__ ei,
                         const float* __restrict__ b1, const float* __restrict__ W2,
                         const float* __restrict__ b2, const float* __restrict__ W3,
                         const float* __restrict__ b3, float* __restrict__ out,
                         int E, int numTiles) {
    extern __shared__ unsigned smemd[];
    unsigned* tS = smemd;                           // 128 x TS_HW u32
    unsigned* b1h = smemd + 128 * TS_HW;            // 64 u32 (half2-packed b1)
    float* esum = (float*)(b1h + 64);               // 128 floats
    int tid = threadIdx.x;
    int warp = tid >> 5, lane = tid & 31;
    int qr = lane >> 2, qc = lane & 3;
    int nBase = warp * 16;
    uint32_t tS_s = smem_u32(tS);
    int laneRow = (lane & 7) + (lane & 8);
    int laneColB = ((lane >> 4) & 1) * 16;
    uint32_t lmBase = tS_s + (uint32_t)laneRow * 272 + (uint32_t)laneColB;

    unsigned bf[8][2][2];
#pragma unroll
    for (int c = 0; c < 8; c++) {
        int kb = c * 16;
#pragma unroll
        for (int ncl = 0; ncl < 2; ncl++) {
            int n = nBase + ncl * 8 + qr;
            bf[c][ncl][0] = h2_bits(__floats2half2_rn(
                __ldg(W2 + (kb + 2 * qc) * 128 + n), __ldg(W2 + (kb + 2 * qc + 1) * 128 + n)));
            bf[c][ncl][1] = h2_bits(__floats2half2_rn(
                __ldg(W2 + (kb + 2 * qc + 8) * 128 + n), __ldg(W2 + (kb + 2 * qc + 9) * 128 + n)));
        }
    }
    float bb0[2], bb1[2], w30[2], w31[2];
#pragma unroll
    for (int ncl = 0; ncl < 2; ncl++) {
        int c0 = nBase + ncl * 8 + qc * 2;
        bb0[ncl] = __ldg(b2 + c0); bb1[ncl] = __ldg(b2 + c0 + 1);
        w30[ncl] = __ldg(W3 + c0); w31[ncl] = __ldg(W3 + c0 + 1);
    }
    float b3v = __ldg(b3);
    if (tid < 64) b1h[tid] = h2_bits(__floats2half2_rn(__ldg(b1 + 2 * tid), __ldg(b1 + 2 * tid + 1)));
    __syncthreads();

    const __half2 hz = __floats2half2_rn(0.f, 0.f);

    for (int tile = blockIdx.x; tile < numTiles; tile += gridDim.x) {
        int eBase = tile * 128;
        __syncthreads();

        // phase 1: t = relu(A[src]+B[dst]+b1) in half2 math; STS.128 stores.
        {
            int eloc = tid >> 1;
            int half_ = tid & 1;
            int e = eBase + eloc;
            uint4* trow4 = (uint4*)(tS + eloc * TS_HW + half_ * 32);
            if (e < E) {
                int s = ei[e], d = ei[E + e];
                const uint4* ap = (const uint4*)(Ad + (size_t)s * 128) + half_ * 8;
                const uint4* bp = (const uint4*)(Bd + (size_t)d * 128) + half_ * 8;
                const uint4* cb = (const uint4*)b1h + half_ * 8;
#pragma unroll
                for (int j = 0; j < 8; j++) {
                    uint4 av = __ldg(ap + j);
                    uint4 bv = __ldg(bp + j);
                    uint4 cv = cb[j];
                    uint4 r;
                    r.x = h2_bits(__hmax2(__hadd2(__hadd2(bits_h2(av.x), bits_h2(bv.x)), bits_h2(cv.x)), hz));
                    r.y = h2_bits(__hmax2(__hadd2(__hadd2(bits_h2(av.y), bits_h2(bv.y)), bits_h2(cv.y)), hz));
                    r.z = h2_bits(__hmax2(__hadd2(__hadd2(bits_h2(av.z), bits_h2(bv.z)), bits_h2(cv.z)), hz));
                    r.w = h2_bits(__hmax2(__hadd2(__hadd2(bits_h2(av.w), bits_h2(bv.w)), bits_h2(cv.w)), hz));
                    trow4[j] = r;
                }
            } else {
                uint4 z4 = make_uint4(0u, 0u, 0u, 0u);
#pragma unroll
                for (int j = 0; j < 8; j++) trow4[j] = z4;
            }
            if (tid < 128) esum[tid] = 0.f;
        }
        __syncthreads();

#pragma unroll 1
        for (int m = 0; m < 8; m++) {
            int r0 = m * 16;
            uint32_t rowAddr = lmBase + (uint32_t)r0 * 272;
            float acc[2][4];
            acc[0][0] = acc[0][1] = acc[0][2] = acc[0][3] = 0.f;
            acc[1][0] = acc[1][1] = acc[1][2] = acc[1][3] = 0.f;
#pragma unroll
            for (int c = 0; c < 8; c++) {
                unsigned a0, a1, a2, a3;
                asm volatile(
                    "ldmatrix.sync.aligned.m8n8.x4.shared.b16 {%0,%1,%2,%3}, [%4];"
                    : "=r"(a0), "=r"(a1), "=r"(a2), "=r"(a3)
                    : "r"(rowAddr + (uint32_t)c * 32));
                asm volatile(
                    "mma.sync.aligned.m16n8k16.row.col.f32.f16.f16.f32 "
                    "{%0,%1,%2,%3}, {%4,%5,%6,%7}, {%8,%9}, {%0,%1,%2,%3};"
                    : "+f"(acc[0][0]), "+f"(acc[0][1]), "+f"(acc[0][2]), "+f"(acc[0][3])
                    : "r"(a0), "r"(a1), "r"(a2), "r"(a3), "r"(bf[c][0][0]), "r"(bf[c][0][1]));
                asm volatile(
                    "mma.sync.aligned.m16n8k16.row.col.f32.f16.f16.f32 "
                    "{%0,%1,%2,%3}, {%4,%5,%6,%7}, {%8,%9}, {%0,%1,%2,%3};"
                    : "+f"(acc[1][0]), "+f"(acc[1][1]), "+f"(acc[1][2]), "+f"(acc[1][3])
                    : "r"(a0), "r"(a1), "r"(a2), "r"(a3), "r"(bf[c][1][0]), "r"(bf[c][1][1]));
            }
            float e0 = 0.f, e1 = 0.f;
#pragma unroll
            for (int ncl = 0; ncl < 2; ncl++) {
                e0 += fmaxf(acc[ncl][0] + bb0[ncl], 0.f) * w30[ncl]
                    + fmaxf(acc[ncl][1] + bb1[ncl], 0.f) * w31[ncl];
                e1 += fmaxf(acc[ncl][2] + bb0[ncl], 0.f) * w30[ncl]
                    + fmaxf(acc[ncl][3] + bb1[ncl], 0.f) * w31[ncl];
            }
            e0 += __shfl_xor_sync(0xffffffffu, e0, 1);
            e0 += __shfl_xor_sync(0xffffffffu, e0, 2);
            e1 += __shfl_xor_sync(0xffffffffu, e1, 1);
            e1 += __shfl_xor_sync(0xffffffffu, e1, 2);
            if (qc == 0) {
                atomicAdd(&esum[r0 + qr], e0);
                atomicAdd(&esum[r0 + qr + 8], e1);
            }
        }
        __syncthreads();

        if (tid < 128) {
            int e = eBase + tid;
            if (e < E) out[e] = esum[tid] + b3v;
        }
    }
}

extern "C" void kernel_launch(void* const* d_in, const int* in_sizes, int n_in,
                              void* d_out, int out_size) {
    const int* node_ids = (const int*)d_in[0];
    const int* ei       = (const int*)d_in[1];
    const int* nei      = (const int*)d_in[2];
    const float* eattr  = (const float*)d_in[3];
    const float* emb    = (const float*)d_in[4];
    const float* W_in   = (const float*)d_in[5];
    const float* b_in   = (const float*)d_in[6];
    const float* W_out  = (const float*)d_in[7];
    const float* b_out  = (const float*)d_in[8];
    const float* W1     = (const float*)d_in[9];
    const float* b1     = (const float*)d_in[10];
    const float* W2     = (const float*)d_in[11];
    const float* b2     = (const float*)d_in[12];
    const float* W3     = (const float*)d_in[13];
    const float* b3     = (const float*)d_in[14];
    int N = in_sizes[0];
    int E = in_sizes[3];
    float* out = (float*)d_out;

    float *agg1, *x1, *x2;
    __half *embh, *h2h, *Ad, *Bd;
    int *off1, *off2;
    int2 *pair1, *pair2;
    cudaGetSymbolAddress((void**)&embh, g_embh);
    cudaGetSymbolAddress((void**)&agg1, g_agg1);
    cudaGetSymbolAddress((void**)&x1, g_x1);
    cudaGetSymbolAddress((void**)&h2h, g_h2h);
    cudaGetSymbolAddress((void**)&x2, g_x2);
    cudaGetSymbolAddress((void**)&Ad, g_Adec);
    cudaGetSymbolAddress((void**)&Bd, g_Bdec);
    cudaGetSymbolAddress((void**)&off1, g_off1);
    cudaGetSymbolAddress((void**)&off2, g_off2);
    cudaGetSymbolAddress((void**)&pair1, g_pair1);
    cudaGetSymbolAddress((void**)&pair2, g_pair2);

    const int T = 256;
    // fused zero-init + emb fp16 conversion
    init_f2h_kernel<<<(N * 32 + T - 1) / T, T>>>(emb, embh, N, N * 32);
    deg_cnt_kernel<<<(E + T - 1) / T, T>>>(ei, eattr, nei, E);
    scan2_kernel<<<1, 1024>>>(N, E);
    fill_kernel<<<(E + T - 1) / T, T>>>(ei, nei, eattr, node_ids, E);

    int mBlocks = (N + 127) / 128;
    int smem_split = (128 * A_STU * 2 + 128 * W_STU * 2) * 4;
    cudaFuncSetAttribute((const void*)gemm_fp16_kernel<1, 0, 0, 0>,
                         cudaFuncAttributeMaxDynamicSharedMemorySize, smem_split);
    cudaFuncSetAttribute((const void*)gemm_fp16_kernel<1, 0, 0, 1>,
                         cudaFuncAttributeMaxDynamicSharedMemorySize, smem_split);
    cudaFuncSetAttribute((const void*)gemm_fp16_kernel<1, 1, 1, 1>,
                         cudaFuncAttributeMaxDynamicSharedMemorySize, smem_split);

    int gatherBlocks = (N * 32 + T - 1) / T;

    // conv1: fp16 gather-aggregate emb, then fp16-split GEMM with fused bias+elu
    gather_f16_kernel<<<gatherBlocks, T>>>(embh, agg1, off1, pair1, N);
    gemm_fp16_kernel<1, 0, 0, 0><<<dim3(2, mBlocks), 256, smem_split>>>(
        agg1, W_in, x1, N, 128, 256, b_in, 1, nullptr, nullptr, nullptr);

    // conv2: fp16-split GEMM (fp16 out) then fp16 gather-aggregate
    gemm_fp16_kernel<1, 0, 0, 1><<<dim3(1, mBlocks), 256, smem_split>>>(
        x1, W_out, h2h, N, 256, 128, nullptr, 0, nullptr, nullptr, nullptr);
    gather_f16_kernel<<<gatherBlocks, T>>>(h2h, x2, off2, pair2, N);

    // merged dual pre-GEMMs (fp16 split; elu(x2+b_out) fused on A, fp16 outputs)
    gemm_fp16_kernel<1, 1, 1, 1><<<dim3(2, mBlocks), 256, smem_split>>>(
        x2, W1, Ad, N, 128, 128, nullptr, 0, b_out, W1 + 128 * 128, Bd);

    // persistent fp16 tensor-core edge decoder
    int numTiles = (E + 127) / 128;
    int smem_dec = (128 * TS_HW + 64 + 128) * 4;
    cudaFuncSetAttribute(decoder_fp16_kernel, cudaFuncAttributeMaxDynamicSharedMemorySize, smem_dec);
    int grid_dec = 3 * 148;
    if (grid_dec > numTiles) grid_dec = numTiles;
    decoder_fp16_kernel<<<grid_dec, 256, smem_dec>>>(Ad, Bd, ei, b1, W2, b2, W3, b3, out, E, numTiles);
}

// round 14
// speedup vs baseline: 3.0647x; 1.1377x over previous
#include <cuda_runtime.h>
#include <cuda_fp16.h>
#include <math.h>
#include <stdint.h>

#define MAXN 50000
#define MAXE 800000

// ---- scratch (device globals; no allocation allowed) ----
__device__ float g_deg1[MAXN];
__device__ int   g_cnt1[MAXN];
__device__ int   g_deg2[MAXN];
__device__ int   g_off1[MAXN + 1];
__device__ int   g_off2[MAXN + 1];
__device__ int   g_cur1[MAXN];
__device__ int   g_cur2[MAXN];
__device__ int2  g_pair1[MAXE];
__device__ int2  g_pair2[MAXE];
__device__ __half g_embh[(size_t)MAXN * 128];
__device__ float g_agg1[(size_t)MAXN * 128];
__device__ float g_x1[(size_t)MAXN * 256];
__device__ __half g_h2h[(size_t)MAXN * 128];
__device__ float g_x2[(size_t)MAXN * 128];
__device__ __half g_Adec[(size_t)MAXN * 128];
__device__ __half g_Bdec[(size_t)MAXN * 128];

__device__ __forceinline__ unsigned h2_bits(__half2 h) {
    unsigned u;
    *(__half2*)&u = h;
    return u;
}
__device__ __forceinline__ __half2 bits_h2(unsigned u) {
    return *(__half2*)&u;
}
__device__ __forceinline__ uint32_t smem_u32(const void* p) {
    uint32_t a;
    asm("{ .reg .u64 t; cvta.to.shared.u64 t, %1; cvt.u32.u64 %0, t; }" : "=r"(a) : "l"(p));
    return a;
}

// ================= fused zero-init + emb fp16 conversion =================
__global__ void init_f2h_kernel(const float* __restrict__ emb, __half* __restrict__ embh,
                                int N, int n4) {
    int i = blockIdx.x * blockDim.x + threadIdx.x;
    if (i < N) {
        g_deg1[i] = 0.f; g_cnt1[i] = 0; g_deg2[i] = 0;
        g_cur1[i] = 0; g_cur2[i] = 0;
    }
    for (int j = i; j < n4; j += gridDim.x * blockDim.x) {
        float4 v = ((const float4*)emb)[j];
        uint2 o;
        o.x = h2_bits(__floats2half2_rn(v.x, v.y));
        o.y = h2_bits(__floats2half2_rn(v.z, v.w));
        ((uint2*)embh)[j] = o;
    }
}

// ================= CSR build =================
__global__ void deg_cnt_kernel(const int* __restrict__ ei, const float* __restrict__ w,
                               const int* __restrict__ nei, int E) {
    int e = blockIdx.x * blockDim.x + threadIdx.x;
    if (e < E) {
        int c1 = ei[E + e];
        atomicAdd(&g_deg1[c1], w[e]);
        atomicAdd(&g_cnt1[c1], 1);
        atomicAdd(&g_deg2[nei[E + e]], 1);
    }
}

__global__ __launch_bounds__(1024, 1)
void scan2_kernel(int N, int E) {
    __shared__ int warpTot[32];
    int tid = threadIdx.x;
    int lane = tid & 31, w = tid >> 5;
    int chunk = (N + 1023) / 1024;
    int beg = tid * chunk;
    int end = beg + chunk; if (end > N) end = N;
#pragma unroll 1
    for (int a = 0; a < 2; a++) {
        const int* c = a ? g_deg2 : g_cnt1;
        int* o = a ? g_off2 : g_off1;
        __syncthreads();
        int t = 0;
        for (int i = beg; i < end; i++) t += c[i];
        int v = t;
#pragma unroll
        for (int d = 1; d < 32; d <<= 1) {
            int u = __shfl_up_sync(0xffffffffu, v, d);
            if (lane >= d) v += u;
        }
        if (lane == 31) warpTot[w] = v;
        __syncthreads();
        if (w == 0) {
            int x = warpTot[lane];
#pragma unroll
            for (int d = 1; d < 32; d <<= 1) {
                int u = __shfl_up_sync(0xffffffffu, x, d);
                if (lane >= d) x += u;
            }
            warpTot[lane] = x;
        }
        __syncthreads();
        int run = v - t + (w > 0 ? warpTot[w - 1] : 0);
        for (int i = beg; i < end; i++) { o[i] = run; run += c[i]; }
    }
    if (tid == 0) { g_off1[N] = E; g_off2[N] = E; }
}

__global__ void fill_kernel(const int* __restrict__ ei, const int* __restrict__ nei,
                            const float* __restrict__ w, const int* __restrict__ node_ids,
                            int E) {
    int e = blockIdx.x * blockDim.x + threadIdx.x;
    if (e >= E) return;
    {
        int r = ei[e], c = ei[E + e];
        float dr = g_deg1[r], dc = g_deg1[c];
        float nrm = (dr > 0.f ? rsqrtf(dr) : 0.f) * w[e] * (dc > 0.f ? rsqrtf(dc) : 0.f);
        int p = g_off1[c] + atomicAdd(&g_cur1[c], 1);
        g_pair1[p] = make_int2(node_ids[r], __float_as_int(nrm));
    }
    {
        int r = nei[e], c = nei[E + e];
        float dr = (float)g_deg2[r], dc = (float)g_deg2[c];
        float nrm = (dr > 0.f ? rsqrtf(dr) : 0.f) * (dc > 0.f ? rsqrtf(dc) : 0.f);
        int p = g_off2[c] + atomicAdd(&g_cur2[c], 1);
        g_pair2[p] = make_int2(r, __float_as_int(nrm));
    }
}

// ---- gather-reduce from fp16 rows, unroll-4 for MLP ----
__global__ void gather_f16_kernel(const __half* __restrict__ h, float* __restrict__ out,
                                  const int* __restrict__ off, const int2* __restrict__ pair,
                                  int N) {
    int gw = (blockIdx.x * blockDim.x + threadIdx.x) >> 5;
    if (gw >= N) return;
    int lane = threadIdx.x & 31;
    int s = off[gw], t = off[gw + 1];
    float4 acc0 = make_float4(0.f, 0.f, 0.f, 0.f);
    float4 acc1 = make_float4(0.f, 0.f, 0.f, 0.f);
    int i = s;
#define GF16_STEP(P, W, ACC)                                                   \
    {                                                                          \
        float nn = __int_as_float((P).y);                                      \
        float2 va = __half22float2(bits_h2((W).x));                            \
        float2 vb = __half22float2(bits_h2((W).y));                            \
        ACC.x = fmaf(va.x, nn, ACC.x); ACC.y = fmaf(va.y, nn, ACC.y);          \
        ACC.z = fmaf(vb.x, nn, ACC.z); ACC.w = fmaf(vb.y, nn, ACC.w);          \
    }
    for (; i + 4 <= t; i += 4) {
        int2 p0 = __ldg(pair + i), p1 = __ldg(pair + i + 1);
        int2 p2 = __ldg(pair + i + 2), p3 = __ldg(pair + i + 3);
        uint2 w0 = *(const uint2*)(h + (size_t)p0.x * 128 + lane * 4);
        uint2 w1 = *(const uint2*)(h + (size_t)p1.x * 128 + lane * 4);
        uint2 w2 = *(const uint2*)(h + (size_t)p2.x * 128 + lane * 4);
        uint2 w3 = *(const uint2*)(h + (size_t)p3.x * 128 + lane * 4);
        GF16_STEP(p0, w0, acc0) GF16_STEP(p1, w1, acc1)
        GF16_STEP(p2, w2, acc0) GF16_STEP(p3, w3, acc1)
    }
    for (; i + 2 <= t; i += 2) {
        int2 p0 = __ldg(pair + i), p1 = __ldg(pair + i + 1);
        uint2 w0 = *(const uint2*)(h + (size_t)p0.x * 128 + lane * 4);
        uint2 w1 = *(const uint2*)(h + (size_t)p1.x * 128 + lane * 4);
        GF16_STEP(p0, w0, acc0) GF16_STEP(p1, w1, acc1)
    }
    if (i < t) {
        int2 p0 = __ldg(pair + i);
        uint2 w0 = *(const uint2*)(h + (size_t)p0.x * 128 + lane * 4);
        GF16_STEP(p0, w0, acc0)
    }
#undef GF16_STEP
    acc0.x += acc1.x; acc0.y += acc1.y; acc0.z += acc1.z; acc0.w += acc1.w;
    *(float4*)(out + (size_t)gw * 128 + lane * 4) = acc0;
}

// ================= fp16 mma.sync node GEMM (m16n8k16, hi/lo split) =================
#define A_STU 20   // u32 per A row (40 halves, 80 bytes)
#define W_STU 21   // u32 per W^T row (42 halves, 84 bytes)

template <int SPLIT, int PREACT, int DUAL, int OUTH>
__global__ __launch_bounds__(256, 2)
void gemm_fp16_kernel(const float* __restrict__ A, const float* __restrict__ W,
                      void* __restrict__ C, int M, int K, int Nc,
                      const float* __restrict__ bias, int act,
                      const float* __restrict__ abias,
                      const float* __restrict__ Wb, void* __restrict__ Cb) {
    extern __shared__ unsigned smg[];
    unsigned* Ahu = smg;
    unsigned* Alu = Ahu + 128 * A_STU;
    unsigned* Whu = Alu + (SPLIT ? 128 * A_STU : 0);
    unsigned* Wlu = Whu + 128 * W_STU;

    int tid = threadIdx.x;
    int warp = tid >> 5, lane = tid & 31;
    int qr = lane >> 2, qc = lane & 3;
    int m0 = blockIdx.y * 128;
    const float* Wp = W;
    void* Cp = C;
    int n0 = blockIdx.x * 128;
    if (DUAL) {
        if (blockIdx.x) { Wp = Wb; Cp = Cb; }
        n0 = 0;
    }
    int r0 = warp * 16;

    uint32_t Ah_s = smem_u32(Ahu);
    uint32_t Al_s = smem_u32(Alu);
    int laneRow = (lane & 7) + (lane & 8);
    int laneColB = ((lane >> 4) & 1) * 16;
    uint32_t lmH = Ah_s + (uint32_t)(r0 + laneRow) * 80 + (uint32_t)laneColB;
    uint32_t lmL = Al_s + (uint32_t)(r0 + laneRow) * 80 + (uint32_t)laneColB;

    float acc[16][4];
#pragma unroll
    for (int n = 0; n < 16; n++)
#pragma unroll
        for (int j = 0; j < 4; j++) acc[n][j] = 0.f;

    for (int kt = 0; kt < K; kt += 32) {
#pragma unroll
        for (int i = 0; i < 4; i++) {
            int idx4 = tid + i * 256;
            int row = idx4 >> 3;
            int col = (idx4 & 7) << 2;
            float4 v = make_float4(0.f, 0.f, 0.f, 0.f);
            if (m0 + row < M) v = *(const float4*)(A + (size_t)(m0 + row) * K + kt + col);
            if (PREACT) {
                float4 ab = *(const float4*)(abias + kt + col);
                v.x += ab.x; v.y += ab.y; v.z += ab.z; v.w += ab.w;
                v.x = v.x > 0.f ? v.x : expm1f(v.x);
                v.y = v.y > 0.f ? v.y : expm1f(v.y);
                v.z = v.z > 0.f ? v.z : expm1f(v.z);
                v.w = v.w > 0.f ? v.w : expm1f(v.w);
            }
            __half h0 = __float2half_rn(v.x), h1 = __float2half_rn(v.y);
            __half h2_ = __float2half_rn(v.z), h3 = __float2half_rn(v.w);
            Ahu[row * A_STU + (col >> 1)] = h2_bits(__halves2half2(h0, h1));
            Ahu[row * A_STU + (col >> 1) + 1] = h2_bits(__halves2half2(h2_, h3));
            if (SPLIT) {
                __half l0 = __float2half_rn(v.x - __half2float(h0));
                __half l1 = __float2half_rn(v.y - __half2float(h1));
                __half l2 = __float2half_rn(v.z - __half2float(h2_));
                __half l3 = __float2half_rn(v.w - __half2float(h3));
                Alu[row * A_STU + (col >> 1)] = h2_bits(__halves2half2(l0, l1));
                Alu[row * A_STU + (col >> 1) + 1] = h2_bits(__halves2half2(l2, l3));
            }
        }
#pragma unroll
        for (int i = 0; i < 2; i++) {
            int idx4 = tid + i * 256;
            int k2 = idx4 >> 5;
            int ncol = (idx4 & 31) << 2;
            const float* wp0 = Wp + (size_t)(kt + 2 * k2) * Nc + n0 + ncol;
            const float* wp1 = wp0 + Nc;
            float4 va = *(const float4*)wp0;
            float4 vb = *(const float4*)wp1;
            float fa[4] = {va.x, va.y, va.z, va.w};
            float fb[4] = {vb.x, vb.y, vb.z, vb.w};
#pragma unroll
            for (int j = 0; j < 4; j++) {
                __half ha = __float2half_rn(fa[j]), hb = __float2half_rn(fb[j]);
                Whu[(ncol + j) * W_STU + k2] = h2_bits(__halves2half2(ha, hb));
                if (SPLIT) {
                    __half la = __float2half_rn(fa[j] - __half2float(ha));
                    __half lb = __float2half_rn(fb[j] - __half2float(hb));
                    Wlu[(ncol + j) * W_STU + k2] = h2_bits(__halves2half2(la, lb));
                }
            }
        }
        __syncthreads();

#pragma unroll
        for (int kk = 0; kk < 2; kk++) {
            unsigned ah0, ah1, ah2, ah3, al0, al1, al2, al3;
            asm volatile(
                "ldmatrix.sync.aligned.m8n8.x4.shared.b16 {%0,%1,%2,%3}, [%4];"
                : "=r"(ah0), "=r"(ah1), "=r"(ah2), "=r"(ah3)
                : "r"(lmH + (uint32_t)kk * 32));
            if (SPLIT) {
                asm volatile(
                    "ldmatrix.sync.aligned.m8n8.x4.shared.b16 {%0,%1,%2,%3}, [%4];"
                    : "=r"(al0), "=r"(al1), "=r"(al2), "=r"(al3)
                    : "r"(lmL + (uint32_t)kk * 32));
            }
#pragma unroll
            for (int nc = 0; nc < 16; nc++) {
                int widx = (nc * 8 + qr) * W_STU + kk * 8 + qc;
                unsigned bh0 = Whu[widx];
                unsigned bh1 = Whu[widx + 4];
                asm volatile(
                    "mma.sync.aligned.m16n8k16.row.col.f32.f16.f16.f32 "
                    "{%0,%1,%2,%3}, {%4,%5,%6,%7}, {%8,%9}, {%0,%1,%2,%3};"
                    : "+f"(acc[nc][0]), "+f"(acc[nc][1]), "+f"(acc[nc][2]), "+f"(acc[nc][3])
                    : "r"(ah0), "r"(ah1), "r"(ah2), "r"(ah3), "r"(bh0), "r"(bh1));
                if (SPLIT) {
                    unsigned bl0 = Wlu[widx];
                    unsigned bl1 = Wlu[widx + 4];
                    asm volatile(
                        "mma.sync.aligned.m16n8k16.row.col.f32.f16.f16.f32 "
                        "{%0,%1,%2,%3}, {%4,%5,%6,%7}, {%8,%9}, {%0,%1,%2,%3};"
                        : "+f"(acc[nc][0]), "+f"(acc[nc][1]), "+f"(acc[nc][2]), "+f"(acc[nc][3])
                        : "r"(ah0), "r"(ah1), "r"(ah2), "r"(ah3), "r"(bl0), "r"(bl1));
                    asm volatile(
                        "mma.sync.aligned.m16n8k16.row.col.f32.f16.f16.f32 "
                        "{%0,%1,%2,%3}, {%4,%5,%6,%7}, {%8,%9}, {%0,%1,%2,%3};"
                        : "+f"(acc[nc][0]), "+f"(acc[nc][1]), "+f"(acc[nc][2]), "+f"(acc[nc][3])
                        : "r"(al0), "r"(al1), "r"(al2), "r"(al3), "r"(bh0), "r"(bh1));
                }
            }
        }
        __syncthreads();
    }

    int row0 = m0 + r0 + qr;
    int row1 = row0 + 8;
#pragma unroll
    for (int nc = 0; nc < 16; nc++) {
        int c0 = n0 + nc * 8 + qc * 2;
        float bz0 = 0.f, bz1 = 0.f;
        if (bias) { bz0 = __ldg(bias + c0); bz1 = __ldg(bias + c0 + 1); }
        float u0 = acc[nc][0] + bz0, u1 = acc[nc][1] + bz1;
        float u2 = acc[nc][2] + bz0, u3 = acc[nc][3] + bz1;
        if (act) {
            u0 = u0 > 0.f ? u0 : expm1f(u0);
            u1 = u1 > 0.f ? u1 : expm1f(u1);
            u2 = u2 > 0.f ? u2 : expm1f(u2);
            u3 = u3 > 0.f ? u3 : expm1f(u3);
        }
        if (OUTH) {
            if (row0 < M) *(__half2*)((__half*)Cp + (size_t)row0 * Nc + c0) = __floats2half2_rn(u0, u1);
            if (row1 < M) *(__half2*)((__half*)Cp + (size_t)row1 * Nc + c0) = __floats2half2_rn(u2, u3);
        } else {
            if (row0 < M) *(float2*)((float*)Cp + (size_t)row0 * Nc + c0) = make_float2(u0, u1);
            if (row1 < M) *(float2*)((float*)Cp + (size_t)row1 * Nc + c0) = make_float2(u2, u3);
        }
    }
}

// ============================================================================
// Persistent fp16 edge decoder (mma.sync m16n8k16.f16, ldmatrix A-fragments,
// half2 phase-1 staging, atomic-free per-warp epilogue slices)
// ============================================================================
#define TS_HW 68   // u32 words per t row (136 halves; row stride 272 bytes)

__global__ __launch_bounds__(256, 3)
void decoder_fp16_kernel(const __half* __restrict__ Ad, const __half* __restrict__ Bd,
                         const int* __restrict__ ei,
                         const float* __restrict__ b1, const float* __restrict__ W2,
                         const float* __restrict__ b2, const float* __restrict__ W3,
                         const float* __restrict__ b3, float* __restrict__ out,
                         int E, int numTiles) {
    extern __shared__ unsigned smemd[];
    unsigned* tS = smemd;                           // 128 x TS_HW u32
    unsigned* b1h = smemd + 128 * TS_HW;            // 64 u32 (half2-packed b1)
    float* esum = (float*)(b1h + 64);               // 8 x 128 floats (per-warp slices)
    int tid = threadIdx.x;
    int warp = tid >> 5, lane = tid & 31;
    int qr = lane >> 2, qc = lane & 3;
    int nBase = warp * 16;
    uint32_t tS_s = smem_u32(tS);
    int laneRow = (lane & 7) + (lane & 8);
    int laneColB = ((lane >> 4) & 1) * 16;
    uint32_t lmBase = tS_s + (uint32_t)laneRow * 272 + (uint32_t)laneColB;
    float* esumW = esum + warp * 128;

    unsigned bf[8][2][2];
#pragma unroll
    for (int c = 0; c < 8; c++) {
        int kb = c * 16;
#pragma unroll
        for (int ncl = 0; ncl < 2; ncl++) {
            int n = nBase + ncl * 8 + qr;
            bf[c][ncl][0] = h2_bits(__floats2half2_rn(
                __ldg(W2 + (kb + 2 * qc) * 128 + n), __ldg(W2 + (kb + 2 * qc + 1) * 128 + n)));
            bf[c][ncl][1] = h2_bits(__floats2half2_rn(
                __ldg(W2 + (kb + 2 * qc + 8) * 128 + n), __ldg(W2 + (kb + 2 * qc + 9) * 128 + n)));
        }
    }
    float bb0[2], bb1[2], w30[2], w31[2];
#pragma unroll
    for (int ncl = 0; ncl < 2; ncl++) {
        int c0 = nBase + ncl * 8 + qc * 2;
        bb0[ncl] = __ldg(b2 + c0); bb1[ncl] = __ldg(b2 + c0 + 1);
        w30[ncl] = __ldg(W3 + c0); w31[ncl] = __ldg(W3 + c0 + 1);
    }
    float b3v = __ldg(b3);
    if (tid < 64) b1h[tid] = h2_bits(__floats2half2_rn(__ldg(b1 + 2 * tid), __ldg(b1 + 2 * tid + 1)));
    __syncthreads();

    const __half2 hz = __floats2half2_rn(0.f, 0.f);

    for (int tile = blockIdx.x; tile < numTiles; tile += gridDim.x) {
        int eBase = tile * 128;
        __syncthreads();

        // phase 1: t = relu(A[src]+B[dst]+b1) in half2 math; STS.128 stores.
        {
            int eloc = tid >> 1;
            int half_ = tid & 1;
            int e = eBase + eloc;
            uint4* trow4 = (uint4*)(tS + eloc * TS_HW + half_ * 32);
            if (e < E) {
                int s = ei[e], d = ei[E + e];
                const uint4* ap = (const uint4*)(Ad + (size_t)s * 128) + half_ * 8;
                const uint4* bp = (const uint4*)(Bd + (size_t)d * 128) + half_ * 8;
                const uint4* cb = (const uint4*)b1h + half_ * 8;
#pragma unroll
                for (int j = 0; j < 8; j++) {
                    uint4 av = __ldg(ap + j);
                    uint4 bv = __ldg(bp + j);
                    uint4 cv = cb[j];
                    uint4 r;
                    r.x = h2_bits(__hmax2(__hadd2(__hadd2(bits_h2(av.x), bits_h2(bv.x)), bits_h2(cv.x)), hz));
                    r.y = h2_bits(__hmax2(__hadd2(__hadd2(bits_h2(av.y), bits_h2(bv.y)), bits_h2(cv.y)), hz));
                    r.z = h2_bits(__hmax2(__hadd2(__hadd2(bits_h2(av.z), bits_h2(bv.z)), bits_h2(cv.z)), hz));
                    r.w = h2_bits(__hmax2(__hadd2(__hadd2(bits_h2(av.w), bits_h2(bv.w)), bits_h2(cv.w)), hz));
                    trow4[j] = r;
                }
            } else {
                uint4 z4 = make_uint4(0u, 0u, 0u, 0u);
#pragma unroll
                for (int j = 0; j < 8; j++) trow4[j] = z4;
            }
        }
        __syncthreads();

#pragma unroll 1
        for (int m = 0; m < 8; m++) {
            int r0 = m * 16;
            uint32_t rowAddr = lmBase + (uint32_t)r0 * 272;
            float acc[2][4];
            acc[0][0] = acc[0][1] = acc[0][2] = acc[0][3] = 0.f;
            acc[1][0] = acc[1][1] = acc[1][2] = acc[1][3] = 0.f;
#pragma unroll
            for (int c = 0; c < 8; c++) {
                unsigned a0, a1, a2, a3;
                asm volatile(
                    "ldmatrix.sync.aligned.m8n8.x4.shared.b16 {%0,%1,%2,%3}, [%4];"
                    : "=r"(a0), "=r"(a1), "=r"(a2), "=r"(a3)
                    : "r"(rowAddr + (uint32_t)c * 32));
                asm volatile(
                    "mma.sync.aligned.m16n8k16.row.col.f32.f16.f16.f32 "
                    "{%0,%1,%2,%3}, {%4,%5,%6,%7}, {%8,%9}, {%0,%1,%2,%3};"
                    : "+f"(acc[0][0]), "+f"(acc[0][1]), "+f"(acc[0][2]), "+f"(acc[0][3])
                    : "r"(a0), "r"(a1), "r"(a2), "r"(a3), "r"(bf[c][0][0]), "r"(bf[c][0][1]));
                asm volatile(
                    "mma.sync.aligned.m16n8k16.row.col.f32.f16.f16.f32 "
                    "{%0,%1,%2,%3}, {%4,%5,%6,%7}, {%8,%9}, {%0,%1,%2,%3};"
                    : "+f"(acc[1][0]), "+f"(acc[1][1]), "+f"(acc[1][2]), "+f"(acc[1][3])
                    : "r"(a0), "r"(a1), "r"(a2), "r"(a3), "r"(bf[c][1][0]), "r"(bf[c][1][1]));
            }
            float e0 = 0.f, e1 = 0.f;
#pragma unroll
            for (int ncl = 0; ncl < 2; ncl++) {
                e0 += fmaxf(acc[ncl][0] + bb0[ncl], 0.f) * w30[ncl]
                    + fmaxf(acc[ncl][1] + bb1[ncl], 0.f) * w31[ncl];
                e1 += fmaxf(acc[ncl][2] + bb0[ncl], 0.f) * w30[ncl]
                    + fmaxf(acc[ncl][3] + bb1[ncl], 0.f) * w31[ncl];
            }
            e0 += __shfl_xor_sync(0xffffffffu, e0, 1);
            e0 += __shfl_xor_sync(0xffffffffu, e0, 2);
            e1 += __shfl_xor_sync(0xffffffffu, e1, 1);
            e1 += __shfl_xor_sync(0xffffffffu, e1, 2);
            if (qc == 0) {
                esumW[r0 + qr] = e0;       // per-warp slice: no atomics
                esumW[r0 + qr + 8] = e1;
            }
        }
        __syncthreads();

        if (tid < 128) {
            int e = eBase + tid;
            if (e < E) {
                float s = esum[tid];
#pragma unroll
                for (int w = 1; w < 8; w++) s += esum[w * 128 + tid];
                out[e] = s + b3v;
            }
        }
    }
}

extern "C" void kernel_launch(void* const* d_in, const int* in_sizes, int n_in,
                              void* d_out, int out_size) {
    const int* node_ids = (const int*)d_in[0];
    const int* ei       = (const int*)d_in[1];
    const int* nei      = (const int*)d_in[2];
    const float* eattr  = (const float*)d_in[3];
    const float* emb    = (const float*)d_in[4];
    const float* W_in   = (const float*)d_in[5];
    const float* b_in   = (const float*)d_in[6];
    const float* W_out  = (const float*)d_in[7];
    const float* b_out  = (const float*)d_in[8];
    const float* W1     = (const float*)d_in[9];
    const float* b1     = (const float*)d_in[10];
    const float* W2     = (const float*)d_in[11];
    const float* b2     = (const float*)d_in[12];
    const float* W3     = (const float*)d_in[13];
    const float* b3     = (const float*)d_in[14];
    int N = in_sizes[0];
    int E = in_sizes[3];
    float* out = (float*)d_out;

    float *agg1, *x1, *x2;
    __half *embh, *h2h, *Ad, *Bd;
    int *off1, *off2;
    int2 *pair1, *pair2;
    cudaGetSymbolAddress((void**)&embh, g_embh);
    cudaGetSymbolAddress((void**)&agg1, g_agg1);
    cudaGetSymbolAddress((void**)&x1, g_x1);
    cudaGetSymbolAddress((void**)&h2h, g_h2h);
    cudaGetSymbolAddress((void**)&x2, g_x2);
    cudaGetSymbolAddress((void**)&Ad, g_Adec);
    cudaGetSymbolAddress((void**)&Bd, g_Bdec);
    cudaGetSymbolAddress((void**)&off1, g_off1);
    cudaGetSymbolAddress((void**)&off2, g_off2);
    cudaGetSymbolAddress((void**)&pair1, g_pair1);
    cudaGetSymbolAddress((void**)&pair2, g_pair2);

    const int T = 256;
    init_f2h_kernel<<<(N * 32 + T - 1) / T, T>>>(emb, embh, N, N * 32);
    deg_cnt_kernel<<<(E + T - 1) / T, T>>>(ei, eattr, nei, E);
    scan2_kernel<<<1, 1024>>>(N, E);
    fill_kernel<<<(E + T - 1) / T, T>>>(ei, nei, eattr, node_ids, E);

    int mBlocks = (N + 127) / 128;
    int smem_split = (128 * A_STU * 2 + 128 * W_STU * 2) * 4;
    cudaFuncSetAttribute((const void*)gemm_fp16_kernel<1, 0, 0, 0>,
                         cudaFuncAttributeMaxDynamicSharedMemorySize, smem_split);
    cudaFuncSetAttribute((const void*)gemm_fp16_kernel<1, 0, 0, 1>,
                         cudaFuncAttributeMaxDynamicSharedMemorySize, smem_split);
    cudaFuncSetAttribute((const void*)gemm_fp16_kernel<1, 1, 1, 1>,
                         cudaFuncAttributeMaxDynamicSharedMemorySize, smem_split);

    int gatherBlocks = (N * 32 + T - 1) / T;

    // conv1: fp16 gather-aggregate emb, then fp16-split GEMM with fused bias+elu
    gather_f16_kernel<<<gatherBlocks, T>>>(embh, agg1, off1, pair1, N);
    gemm_fp16_kernel<1, 0, 0, 0><<<dim3(2, mBlocks), 256, smem_split>>>(
        agg1, W_in, x1, N, 128, 256, b_in, 1, nullptr, nullptr, nullptr);

    // conv2: fp16-split GEMM (fp16 out) then fp16 gather-aggregate
    gemm_fp16_kernel<1, 0, 0, 1><<<dim3(1, mBlocks), 256, smem_split>>>(
        x1, W_out, h2h, N, 256, 128, nullptr, 0, nullptr, nullptr, nullptr);
    gather_f16_kernel<<<gatherBlocks, T>>>(h2h, x2, off2, pair2, N);

    // merged dual pre-GEMMs (fp16 split; elu(x2+b_out) fused on A, fp16 outputs)
    gemm_fp16_kernel<1, 1, 1, 1><<<dim3(2, mBlocks), 256, smem_split>>>(
        x2, W1, Ad, N, 128, 128, nullptr, 0, b_out, W1 + 128 * 128, Bd);

    // persistent fp16 tensor-core edge decoder
    int numTiles = (E + 127) / 128;
    int smem_dec = (128 * TS_HW + 64 + 8 * 128) * 4;
    cudaFuncSetAttribute(decoder_fp16_kernel, cudaFuncAttributeMaxDynamicSharedMemorySize, smem_dec);
    int grid_dec = 3 * 148;
    if (grid_dec > numTiles) grid_dec = numTiles;
    decoder_fp16_kernel<<<grid_dec, 256, smem_dec>>>(Ad, Bd, ei, b1, W2, b2, W3, b3, out, E, numTiles);
}